// round 5
// baseline (speedup 1.0000x reference)
#include <cuda_runtime.h>
#include <cuda_bf16.h>
#include <cstdint>

#define EMB 128
#define NR 6
#define SA 272          // A/B smem row stride in bytes (136 bf16)
#define SS 132          // Sum4 row stride in floats
#define THREADS 512

// Precomputed table @ W_block projections: rows 0-95 Tsrc, 96-191 Tdst,
// 192-211 Tstep, 212-213 Teq (+bias folded into Teq rows).
__device__ float g_T[214 * EMB];

__device__ __forceinline__ uint32_t smem_u32(const void* p) {
    uint32_t a;
    asm("{ .reg .u64 t; cvta.to.shared.u64 t, %1; cvt.u32.u64 %0, t; }" : "=r"(a) : "l"(p));
    return a;
}
__device__ __forceinline__ float silu_f(float x) {
    return __fdividef(x, 1.0f + __expf(-x));
}
__device__ __forceinline__ void ldsm4(uint32_t* r, uint32_t addr) {
    asm volatile("ldmatrix.sync.aligned.m8n8.x4.shared.b16 {%0,%1,%2,%3}, [%4];"
                 : "=r"(r[0]), "=r"(r[1]), "=r"(r[2]), "=r"(r[3]) : "r"(addr));
}
__device__ __forceinline__ void ldsm4t(uint32_t* r, uint32_t addr) {
    asm volatile("ldmatrix.sync.aligned.m8n8.x4.trans.shared.b16 {%0,%1,%2,%3}, [%4];"
                 : "=r"(r[0]), "=r"(r[1]), "=r"(r[2]), "=r"(r[3]) : "r"(addr));
}
__device__ __forceinline__ void mma_bf16(float* d, const uint32_t* a, const uint32_t* b) {
    asm volatile("mma.sync.aligned.m16n8k16.row.col.f32.bf16.bf16.f32 "
                 "{%0,%1,%2,%3}, {%4,%5,%6,%7}, {%8,%9}, {%0,%1,%2,%3};"
                 : "+f"(d[0]), "+f"(d[1]), "+f"(d[2]), "+f"(d[3])
                 : "r"(a[0]), "r"(a[1]), "r"(a[2]), "r"(a[3]), "r"(b[0]), "r"(b[1]));
}

// ---------------------------------------------------------------------------
// Kernel 1: g_T = tables @ W_blocks (bias folded into Teq rows)
// ---------------------------------------------------------------------------
__global__ void precompute_kernel(const float* __restrict__ emb_table,
                                  const float* __restrict__ step_table,
                                  const float* __restrict__ equiv_table,
                                  const float* __restrict__ W,
                                  const float* __restrict__ b)
{
    __shared__ float in[EMB];
    int r = blockIdx.x, c = threadIdx.x;
    const float* srow; const float* Wb; bool addb = false;
    if (r < 96)       { srow = emb_table + r * EMB;           Wb = W; }
    else if (r < 192) { srow = emb_table + (r - 96) * EMB;    Wb = W + EMB * EMB; }
    else if (r < 212) { srow = step_table + (r - 192) * EMB;  Wb = W + 3 * EMB * EMB; }
    else              { srow = equiv_table + (r - 212) * EMB; Wb = W + 4 * EMB * EMB; addb = true; }
    in[c] = srow[c];
    __syncthreads();
    float a0 = 0, a1 = 0, a2 = 0, a3 = 0;
    #pragma unroll
    for (int k = 0; k < EMB; k += 4) {
        a0 = fmaf(in[k + 0], Wb[(k + 0) * EMB + c], a0);
        a1 = fmaf(in[k + 1], Wb[(k + 1) * EMB + c], a1);
        a2 = fmaf(in[k + 2], Wb[(k + 2) * EMB + c], a2);
        a3 = fmaf(in[k + 3], Wb[(k + 3) * EMB + c], a3);
    }
    g_T[r * EMB + c] = (a0 + a1) + (a2 + a3) + (addb ? b[c] : 0.0f);
}

// ---------------------------------------------------------------------------
// Kernel 2: persistent fused edge kernel (mma.sync bf16 hi/lo 3-pass GEMM)
// 512 threads, 16 warps in a 4x4 grid, 32x32 output tile per warp.
// smem layout (bytes):
//   0      Ahi   34816   (bf16 [128 e][136 k])
//   34816  Alo   34816
//   69632  Bhi   34816   (bf16 [128 k][136 n])
//   104448 Blo   34816
//   139264 Sum4  67584   (f32 [128 e][132 c])
//   206848 Wr     4096   (f32 [128 k][8])
//   210944 sidx   2048   (int [4][128])
//   total 212992
// ---------------------------------------------------------------------------
__global__ __launch_bounds__(THREADS, 1)
void edge_kernel(const int* __restrict__ Z, const int* __restrict__ stepA,
                 const int* __restrict__ src, const int* __restrict__ dst,
                 const int* __restrict__ equiv,
                 const float* __restrict__ rbf, const float* __restrict__ dvec,
                 const float* __restrict__ W_rbf, const float* __restrict__ b_rbf,
                 const float* __restrict__ W2,
                 float* __restrict__ out, int E, int tiles)
{
    extern __shared__ char sm[];
    char*  const Ahi  = sm;
    char*  const Alo  = sm + 34816;
    char*  const Bhi  = sm + 69632;
    char*  const Blo  = sm + 104448;
    float* const Sum4 = (float*)(sm + 139264);
    float* const Wr   = (float*)(sm + 206848);
    int*   const sidx = (int*)(sm + 210944);

    const int tid  = threadIdx.x;
    const int wid  = tid >> 5;
    const int lane = tid & 31;

    // ---- one-time setup ----
    for (int idx = tid; idx < EMB * EMB; idx += THREADS) {
        int k = idx >> 7, n = idx & 127;
        float w = W2[idx];                        // W2[k][n]
        __nv_bfloat16 h = __float2bfloat16(w);
        float l = w - __bfloat162float(h);
        *(__nv_bfloat16*)(Bhi + k * SA + n * 2) = h;
        *(__nv_bfloat16*)(Blo + k * SA + n * 2) = __float2bfloat16(l);
    }
    for (int i = tid; i < EMB * 8; i += THREADS) {
        int k = i >> 3, j = i & 7;
        Wr[i] = (j < 6) ? W_rbf[j * EMB + k] : (j == 6 ? b_rbf[k] : 0.0f);
    }
    const float4 te0 = *(const float4*)&g_T[212 * EMB + lane * 4];
    const float4 te1 = *(const float4*)&g_T[213 * EMB + lane * 4];
    __syncthreads();

    const int m0 = (wid & 3) * 32;
    const int n0 = (wid >> 2) * 32;
    const uint32_t lmoff = (uint32_t)((lane & 15) * SA + (lane >> 4) * 16);
    const uint32_t Ahi_u = smem_u32(Ahi), Alo_u = smem_u32(Alo);
    const uint32_t Bhi_u = smem_u32(Bhi), Blo_u = smem_u32(Blo);
    float* const envo = out + (size_t)E * EMB;

    for (int t = blockIdx.x; t < tiles; t += gridDim.x) {
        const int ebase = t * 128;

        // ---- P1: indices (tid<128) + rbf_env (tid in [128,384), 2 threads/edge) ----
        if (tid < 128) {
            const int ge = ebase + tid;
            int zs = 0, zd = 0, st = 0, eq = 0;
            if (ge < E) {
                int s = src[ge], dd = dst[ge];
                zs = Z[s]; zd = Z[dd]; st = stepA[s]; eq = equiv[ge];
            }
            sidx[tid] = zs; sidx[128 + tid] = zd;
            sidx[256 + tid] = st; sidx[384 + tid] = eq;
        } else if (tid < 384) {
            const int q = tid - 128;
            const int e = q >> 1;                 // 0..127
            const int half = q & 1;               // 3 freqs each
            const int ge = ebase + e;
            if (ge < E) {
                float x = dvec[ge] * 0.2f;
                float inv = 1.0f / x;
                float x2 = x * x;
                float x5 = x2 * x2 * x;
                float env = inv + x5 * (-28.0f + x * (48.0f + x * (-21.0f)));
                float coef = env * inv;
                const float PI = 3.14159265358979323846f;
                float* o = envo + (size_t)ge * NR + half * 3;
                const float fb = PI * (float)(half * 3);
                #pragma unroll
                for (int j = 0; j < 3; j++) o[j] = coef * sinf(x * (fb + PI * (float)(j + 1)));
            }
        }
        __syncthreads();

        // ---- P2a: cooperative table-row sums into Sum4 (8 rows per warp) ----
        #pragma unroll
        for (int i = 0; i < 8; i++) {
            const int e = wid * 8 + i;
            const int zs = sidx[e], zd = sidx[128 + e], st = sidx[256 + e], eq = sidx[384 + e];
            float4 rs = *(const float4*)&g_T[zs * EMB + lane * 4];
            float4 rd = *(const float4*)&g_T[(96 + zd) * EMB + lane * 4];
            float4 rt = *(const float4*)&g_T[(192 + st) * EMB + lane * 4];
            float4 te = eq ? te1 : te0;
            float4 s;
            s.x = (rs.x + rd.x) + (rt.x + te.x);
            s.y = (rs.y + rd.y) + (rt.y + te.y);
            s.z = (rs.z + rd.z) + (rt.z + te.z);
            s.w = (rs.w + rd.w) + (rt.w + te.w);
            *(float4*)&Sum4[e * SS + lane * 4] = s;
        }

        // ---- P2b: A = silu(rbf @ W_rbf + b), bf16 hi/lo; 32 k-values/thread ----
        {
            const int e = tid >> 2;
            const int kq = (tid & 3) * 32;
            const int ge = ebase + e;
            float r0 = 0, r1 = 0, r2 = 0, r3 = 0, r4 = 0, r5 = 0;
            if (ge < E) {
                const float* rp = rbf + (size_t)ge * NR;
                r0 = rp[0]; r1 = rp[1]; r2 = rp[2]; r3 = rp[3]; r4 = rp[4]; r5 = rp[5];
            }
            char* ah = Ahi + e * SA + kq * 2;
            char* al = Alo + e * SA + kq * 2;
            #pragma unroll
            for (int kk = 0; kk < 16; kk++) {
                const float* w0 = Wr + (kq + 2 * kk) * 8;
                float4 wa = *(const float4*)(w0);
                float4 wb = *(const float4*)(w0 + 4);
                float4 wc = *(const float4*)(w0 + 8);
                float4 wd = *(const float4*)(w0 + 12);
                float z0 = wb.z + r0 * wa.x + r1 * wa.y + r2 * wa.z + r3 * wa.w + r4 * wb.x + r5 * wb.y;
                float z1 = wd.z + r0 * wc.x + r1 * wc.y + r2 * wc.z + r3 * wc.w + r4 * wd.x + r5 * wd.y;
                float a0 = silu_f(z0);
                float a1 = silu_f(z1);
                __nv_bfloat16 h0 = __float2bfloat16(a0);
                __nv_bfloat16 h1 = __float2bfloat16(a1);
                float l0 = a0 - __bfloat162float(h0);
                float l1 = a1 - __bfloat162float(h1);
                uint32_t hp = ((uint32_t)__bfloat16_as_ushort(h1) << 16) | (uint32_t)__bfloat16_as_ushort(h0);
                uint32_t lp;
                asm("cvt.rn.bf16x2.f32 %0, %1, %2;" : "=r"(lp) : "f"(l1), "f"(l0));
                *(uint32_t*)(ah + kk * 4) = hp;
                *(uint32_t*)(al + kk * 4) = lp;
            }
        }
        __syncthreads();

        // ---- P3: GEMM  D(32x32 per warp) = Ahi*Bhi + Ahi*Blo + Alo*Bhi ----
        float d[2][2][2][4];
        #pragma unroll
        for (int mt = 0; mt < 2; mt++)
            #pragma unroll
            for (int j = 0; j < 2; j++)
                #pragma unroll
                for (int s2 = 0; s2 < 2; s2++)
                    d[mt][j][s2][0] = d[mt][j][s2][1] = d[mt][j][s2][2] = d[mt][j][s2][3] = 0.0f;

        #pragma unroll
        for (int p = 0; p < 3; p++) {
            const uint32_t Au = ((p == 2) ? Alo_u : Ahi_u) + m0 * SA + lmoff;
            const uint32_t Bu = ((p == 1) ? Blo_u : Bhi_u) + n0 * 2 + lmoff;
            #pragma unroll
            for (int ks = 0; ks < 8; ks++) {
                uint32_t a[8];
                ldsm4(a + 0, Au + ks * 32);
                ldsm4(a + 4, Au + 16 * SA + ks * 32);
                uint32_t b[8];
                ldsm4t(b + 0, Bu + ks * 16 * SA);
                ldsm4t(b + 4, Bu + ks * 16 * SA + 32);
                #pragma unroll
                for (int mt = 0; mt < 2; mt++)
                    #pragma unroll
                    for (int j = 0; j < 2; j++)
                        #pragma unroll
                        for (int s2 = 0; s2 < 2; s2++)
                            mma_bf16(d[mt][j][s2], a + mt * 4, b + 4 * j + 2 * s2);
            }
        }

        // ---- P4: epilogue: + Sum4, silu, direct float2 stores ----
        #pragma unroll
        for (int mt = 0; mt < 2; mt++) {
            const int r = m0 + mt * 16 + (lane >> 2);
            const int ge1 = ebase + r;
            const int ge2 = ge1 + 8;
            const float* S1 = &Sum4[r * SS];
            const float* S2 = &Sum4[(r + 8) * SS];
            #pragma unroll
            for (int j = 0; j < 2; j++)
                #pragma unroll
                for (int s2 = 0; s2 < 2; s2++) {
                    const int c = n0 + j * 16 + s2 * 8 + (lane & 3) * 2;
                    const float* dd = d[mt][j][s2];
                    if (ge1 < E) {
                        float2 s = *(const float2*)&S1[c];
                        float2 v;
                        v.x = silu_f(dd[0] + s.x);
                        v.y = silu_f(dd[1] + s.y);
                        *(float2*)&out[(size_t)ge1 * EMB + c] = v;
                    }
                    if (ge2 < E) {
                        float2 s = *(const float2*)&S2[c];
                        float2 v;
                        v.x = silu_f(dd[2] + s.x);
                        v.y = silu_f(dd[3] + s.y);
                        *(float2*)&out[(size_t)ge2 * EMB + c] = v;
                    }
                }
        }
        __syncthreads();
    }
}

// ---------------------------------------------------------------------------
extern "C" void kernel_launch(void* const* d_in, const int* in_sizes, int n_in,
                              void* d_out, int out_size)
{
    const int*   Z          = (const int*)d_in[0];
    const int*   stepA      = (const int*)d_in[1];
    const int*   src        = (const int*)d_in[2];
    const int*   dst        = (const int*)d_in[3];
    const int*   equiv      = (const int*)d_in[4];
    const float* rbf        = (const float*)d_in[5];
    const float* dvec       = (const float*)d_in[6];
    const float* emb_table  = (const float*)d_in[7];
    const float* step_table = (const float*)d_in[8];
    const float* equiv_tab  = (const float*)d_in[9];
    const float* W_rbf      = (const float*)d_in[10];
    const float* b_rbf      = (const float*)d_in[11];
    const float* W          = (const float*)d_in[12];
    const float* b          = (const float*)d_in[13];
    float* out = (float*)d_out;

    const int E = in_sizes[2];
    const int tiles = (E + 127) / 128;

    static int sms = 0;
    if (sms == 0) {
        if (cudaDeviceGetAttribute(&sms, cudaDevAttrMultiProcessorCount, 0) != cudaSuccess || sms <= 0)
            sms = 148;
    }
    const int grid = sms < tiles ? sms : tiles;

    const int smem_bytes = 212992;
    cudaFuncSetAttribute(edge_kernel, cudaFuncAttributeMaxDynamicSharedMemorySize, smem_bytes);

    precompute_kernel<<<214, 128>>>(emb_table, step_table, equiv_tab, W, b);
    edge_kernel<<<grid, THREADS, smem_bytes>>>(Z, stepA, src, dst, equiv,
                                               rbf, dvec, W_rbf, b_rbf,
                                               W + 2 * EMB * EMB, out, E, tiles);
}

// round 6
// speedup vs baseline: 1.4679x; 1.4679x over previous
#include <cuda_runtime.h>
#include <cuda_bf16.h>
#include <cstdint>

#define EMB 128
#define NR 6
#define SA 272          // A/B smem row stride in bytes (136 bf16)
#define SS 132          // Sum4 row stride in floats
#define THREADS 384     // 8 consumer warps + 4 producer warps

// Precomputed table @ W_block projections: rows 0-95 Tsrc, 96-191 Tdst,
// 192-211 Tstep, 212-213 Teq (+bias folded into Teq rows).
__device__ float g_T[214 * EMB];

__device__ __forceinline__ uint32_t smem_u32(const void* p) {
    uint32_t a;
    asm("{ .reg .u64 t; cvta.to.shared.u64 t, %1; cvt.u32.u64 %0, t; }" : "=r"(a) : "l"(p));
    return a;
}
// silu(x) = 0.5x * (1 + tanh(x/2)) ; tanh.approx = 1 MUFU
__device__ __forceinline__ float silu_f(float x) {
    float h = 0.5f * x, t;
    asm("tanh.approx.f32 %0, %1;" : "=f"(t) : "f"(h));
    return fmaf(h, t, h);
}
__device__ __forceinline__ void ldsm4(uint32_t* r, uint32_t addr) {
    asm volatile("ldmatrix.sync.aligned.m8n8.x4.shared.b16 {%0,%1,%2,%3}, [%4];"
                 : "=r"(r[0]), "=r"(r[1]), "=r"(r[2]), "=r"(r[3]) : "r"(addr));
}
__device__ __forceinline__ void ldsm4t(uint32_t* r, uint32_t addr) {
    asm volatile("ldmatrix.sync.aligned.m8n8.x4.trans.shared.b16 {%0,%1,%2,%3}, [%4];"
                 : "=r"(r[0]), "=r"(r[1]), "=r"(r[2]), "=r"(r[3]) : "r"(addr));
}
__device__ __forceinline__ void mma_bf16(float* d, const uint32_t* a, const uint32_t* b) {
    asm volatile("mma.sync.aligned.m16n8k16.row.col.f32.bf16.bf16.f32 "
                 "{%0,%1,%2,%3}, {%4,%5,%6,%7}, {%8,%9}, {%0,%1,%2,%3};"
                 : "+f"(d[0]), "+f"(d[1]), "+f"(d[2]), "+f"(d[3])
                 : "r"(a[0]), "r"(a[1]), "r"(a[2]), "r"(a[3]), "r"(b[0]), "r"(b[1]));
}
#define BAR_SYNC(id, cnt)   asm volatile("bar.sync %0, %1;"   :: "r"(id), "r"(cnt) : "memory")
#define BAR_ARRIVE(id, cnt) asm volatile("bar.arrive %0, %1;" :: "r"(id), "r"(cnt) : "memory")

// ---------------------------------------------------------------------------
// Kernel 1: g_T = tables @ W_blocks (bias folded into Teq rows)
// ---------------------------------------------------------------------------
__global__ void precompute_kernel(const float* __restrict__ emb_table,
                                  const float* __restrict__ step_table,
                                  const float* __restrict__ equiv_table,
                                  const float* __restrict__ W,
                                  const float* __restrict__ b)
{
    __shared__ float in[EMB];
    int r = blockIdx.x, c = threadIdx.x;
    const float* srow; const float* Wb; bool addb = false;
    if (r < 96)       { srow = emb_table + r * EMB;           Wb = W; }
    else if (r < 192) { srow = emb_table + (r - 96) * EMB;    Wb = W + EMB * EMB; }
    else if (r < 212) { srow = step_table + (r - 192) * EMB;  Wb = W + 3 * EMB * EMB; }
    else              { srow = equiv_table + (r - 212) * EMB; Wb = W + 4 * EMB * EMB; addb = true; }
    in[c] = srow[c];
    __syncthreads();
    float a0 = 0, a1 = 0, a2 = 0, a3 = 0;
    #pragma unroll
    for (int k = 0; k < EMB; k += 4) {
        a0 = fmaf(in[k + 0], Wb[(k + 0) * EMB + c], a0);
        a1 = fmaf(in[k + 1], Wb[(k + 1) * EMB + c], a1);
        a2 = fmaf(in[k + 2], Wb[(k + 2) * EMB + c], a2);
        a3 = fmaf(in[k + 3], Wb[(k + 3) * EMB + c], a3);
    }
    g_T[r * EMB + c] = (a0 + a1) + (a2 + a3) + (addb ? b[c] : 0.0f);
}

// ---------------------------------------------------------------------------
// Kernel 2: persistent warp-specialized edge kernel.
// Consumers (warps 0-7): 32x64 tile, 3-pass bf16 hi/lo mma.sync GEMM + epilogue.
// Producers (warps 8-11): indices + rbf_env + A-tile (bf16 hi/lo) + Sum4.
// Named barriers: 1=A_full, 2=A_empty, 3=Sum_full, 4=Sum_empty (count 384),
//                 5=producer-only (count 128).
// smem (bytes): Ahi 34816 | Alo 34816 | Bhi 34816 | Blo 34816 |
//               Sum4 67584 | Wr 4096 | sidx 2x2048  => 215040
// ---------------------------------------------------------------------------
__global__ __launch_bounds__(THREADS, 1)
void edge_kernel(const int* __restrict__ Z, const int* __restrict__ stepA,
                 const int* __restrict__ src, const int* __restrict__ dst,
                 const int* __restrict__ equiv,
                 const float* __restrict__ rbf, const float* __restrict__ dvec,
                 const float* __restrict__ W_rbf, const float* __restrict__ b_rbf,
                 const float* __restrict__ W2,
                 float* __restrict__ out, int E, int tiles)
{
    extern __shared__ char sm[];
    char*  const Ahi  = sm;
    char*  const Alo  = sm + 34816;
    char*  const Bhi  = sm + 69632;
    char*  const Blo  = sm + 104448;
    float* const Sum4 = (float*)(sm + 139264);
    float* const Wr   = (float*)(sm + 206848);
    int*   const sidx = (int*)(sm + 210944);     // [2][512]

    const int tid  = threadIdx.x;
    const int wid  = tid >> 5;
    const int lane = tid & 31;

    // ---- one-time setup: split W2^T into bf16 hi/lo, pack W_rbf rows ----
    for (int idx = tid; idx < EMB * EMB; idx += THREADS) {
        int k = idx >> 7, n = idx & 127;
        float w = W2[idx];                        // W2[k][n]
        __nv_bfloat16 h = __float2bfloat16(w);
        float l = w - __bfloat162float(h);
        *(__nv_bfloat16*)(Bhi + k * SA + n * 2) = h;
        *(__nv_bfloat16*)(Blo + k * SA + n * 2) = __float2bfloat16(l);
    }
    for (int i = tid; i < EMB * 8; i += THREADS) {
        int k = i >> 3, j = i & 7;
        Wr[i] = (j < 6) ? W_rbf[j * EMB + k] : (j == 6 ? b_rbf[k] : 0.0f);
    }
    __syncthreads();

    float* const envo = out + (size_t)E * EMB;

    if (wid < 8) {
        // =================== CONSUMERS ===================
        const int m0 = (wid & 3) * 32;
        const int nb = (wid >> 2) * 64;
        const uint32_t lmoff = (uint32_t)((lane & 15) * SA + (lane >> 4) * 16);
        const uint32_t Ahi_u = smem_u32(Ahi), Alo_u = smem_u32(Alo);
        const uint32_t Bhi_u = smem_u32(Bhi), Blo_u = smem_u32(Blo);

        for (int t = blockIdx.x; t < tiles; t += gridDim.x) {
            const int ebase = t * 128;
            BAR_SYNC(1, THREADS);                 // wait A_full

            float d[2][4][2][4];
            #pragma unroll
            for (int mt = 0; mt < 2; mt++)
                #pragma unroll
                for (int j = 0; j < 4; j++)
                    #pragma unroll
                    for (int s2 = 0; s2 < 2; s2++)
                        d[mt][j][s2][0] = d[mt][j][s2][1] = d[mt][j][s2][2] = d[mt][j][s2][3] = 0.0f;

            #pragma unroll
            for (int p = 0; p < 3; p++) {
                const uint32_t Au = ((p == 2) ? Alo_u : Ahi_u) + m0 * SA + lmoff;
                const uint32_t Bu = ((p == 1) ? Blo_u : Bhi_u) + nb * 2 + lmoff;
                #pragma unroll
                for (int ks = 0; ks < 8; ks++) {
                    uint32_t a[8];
                    ldsm4(a + 0, Au + ks * 32);
                    ldsm4(a + 4, Au + 16 * SA + ks * 32);
                    uint32_t b[16];
                    #pragma unroll
                    for (int j = 0; j < 4; j++) ldsm4t(b + 4 * j, Bu + ks * 16 * SA + j * 32);
                    #pragma unroll
                    for (int mt = 0; mt < 2; mt++)
                        #pragma unroll
                        for (int j = 0; j < 4; j++)
                            #pragma unroll
                            for (int s2 = 0; s2 < 2; s2++)
                                mma_bf16(d[mt][j][s2], a + mt * 4, b + 4 * j + 2 * s2);
                }
            }
            BAR_ARRIVE(2, THREADS);               // A_empty
            BAR_SYNC(3, THREADS);                 // wait Sum_full

            #pragma unroll
            for (int mt = 0; mt < 2; mt++) {
                const int r = m0 + mt * 16 + (lane >> 2);
                const int ge1 = ebase + r;
                const int ge2 = ge1 + 8;
                const float* S1 = &Sum4[r * SS];
                const float* S2 = &Sum4[(r + 8) * SS];
                #pragma unroll
                for (int j = 0; j < 4; j++)
                    #pragma unroll
                    for (int s2 = 0; s2 < 2; s2++) {
                        const int c = nb + j * 16 + s2 * 8 + (lane & 3) * 2;
                        const float* dd = d[mt][j][s2];
                        if (ge1 < E) {
                            float2 s = *(const float2*)&S1[c];
                            float2 v;
                            v.x = silu_f(dd[0] + s.x);
                            v.y = silu_f(dd[1] + s.y);
                            *(float2*)&out[(size_t)ge1 * EMB + c] = v;
                        }
                        if (ge2 < E) {
                            float2 s = *(const float2*)&S2[c];
                            float2 v;
                            v.x = silu_f(dd[2] + s.x);
                            v.y = silu_f(dd[3] + s.y);
                            *(float2*)&out[(size_t)ge2 * EMB + c] = v;
                        }
                    }
            }
            BAR_ARRIVE(4, THREADS);               // Sum_empty
        }
    } else {
        // =================== PRODUCERS ===================
        const int pid = tid - 256;                // 0..127
        const int pw  = pid >> 5, pl = pid & 31;
        const float4 te0 = *(const float4*)&g_T[212 * EMB + pl * 4];
        const float4 te1 = *(const float4*)&g_T[213 * EMB + pl * 4];
        char* const ah0 = Ahi + pid * SA;
        char* const al0 = Alo + pid * SA;
        bool first = true;

        for (int t = blockIdx.x; t < tiles; t += gridDim.x) {
            const int ebase = t * 128;
            const int ge = ebase + pid;
            const bool valid = (ge < E);

            int zs = 0, zd = 0, st = 0, eq = 0;
            float r0 = 0, r1 = 0, r2 = 0, r3 = 0, r4 = 0, r5 = 0;
            float dv = 1.0f;
            if (valid) {
                int s = src[ge], dd = dst[ge];
                zs = Z[s]; zd = Z[dd]; st = stepA[s]; eq = equiv[ge];
                const float* rp = rbf + (size_t)ge * NR;
                r0 = rp[0]; r1 = rp[1]; r2 = rp[2]; r3 = rp[3]; r4 = rp[4]; r5 = rp[5];
                dv = dvec[ge];
            }
            // rbf_env (independent of pipeline)
            if (valid) {
                float x = dv * 0.2f;
                float inv = 1.0f / x;
                float x2 = x * x;
                float x5 = x2 * x2 * x;
                float env = inv + x5 * (-28.0f + x * (48.0f + x * (-21.0f)));
                float coef = env * inv;
                const float PI = 3.14159265358979323846f;
                float* o = envo + (size_t)ge * NR;
                #pragma unroll
                for (int j = 0; j < NR; j++) o[j] = coef * __sinf(x * (PI * (float)(j + 1)));
            }

            if (!first) BAR_SYNC(2, THREADS);     // wait A_empty (GEMM t-1 ldsm done)

            int* sx = sidx + (t & 1) * 512;
            sx[pid] = zs; sx[128 + pid] = zd; sx[256 + pid] = st; sx[384 + pid] = eq;

            // A row pid: z_k = b_k + sum_j r_j W_rbf[j][k]; silu; bf16 hi/lo split.
            #pragma unroll 2
            for (int k8 = 0; k8 < 128; k8 += 8) {
                uint32_t hb[4], lb[4];
                #pragma unroll
                for (int kk = 0; kk < 4; kk++) {
                    const int k = k8 + 2 * kk;
                    float4 wa = *(const float4*)&Wr[k * 8];
                    float4 wb = *(const float4*)&Wr[k * 8 + 4];
                    float4 wc = *(const float4*)&Wr[(k + 1) * 8];
                    float4 wd = *(const float4*)&Wr[(k + 1) * 8 + 4];
                    float z0 = wb.z + r0 * wa.x + r1 * wa.y + r2 * wa.z + r3 * wa.w + r4 * wb.x + r5 * wb.y;
                    float z1 = wd.z + r0 * wc.x + r1 * wc.y + r2 * wc.z + r3 * wc.w + r4 * wd.x + r5 * wd.y;
                    float a0 = silu_f(z0);
                    float a1 = silu_f(z1);
                    __nv_bfloat16 h0 = __float2bfloat16(a0);
                    __nv_bfloat16 h1 = __float2bfloat16(a1);
                    float l0 = a0 - __bfloat162float(h0);
                    float l1 = a1 - __bfloat162float(h1);
                    hb[kk] = ((uint32_t)__bfloat16_as_ushort(h1) << 16) | (uint32_t)__bfloat16_as_ushort(h0);
                    uint32_t lp;
                    asm("cvt.rn.bf16x2.f32 %0, %1, %2;" : "=r"(lp) : "f"(l1), "f"(l0));
                    lb[kk] = lp;
                }
                *(uint4*)(ah0 + k8 * 2) = make_uint4(hb[0], hb[1], hb[2], hb[3]);
                *(uint4*)(al0 + k8 * 2) = make_uint4(lb[0], lb[1], lb[2], lb[3]);
            }
            __threadfence_block();
            BAR_ARRIVE(1, THREADS);               // A_full

            if (!first) BAR_SYNC(4, THREADS);     // wait Sum_empty (epilogue t-1 done)
            first = false;
            BAR_SYNC(5, 128);                     // producer-only: sidx visible

            // Sum4 rows [pw*32, pw*32+32): cooperative 512B-row gathers
            #pragma unroll 4
            for (int i = 0; i < 32; i++) {
                const int r = pw * 32 + i;
                const int rzs = sx[r], rzd = sx[128 + r], rst = sx[256 + r], req = sx[384 + r];
                float4 rs = *(const float4*)&g_T[rzs * EMB + pl * 4];
                float4 rd = *(const float4*)&g_T[(96 + rzd) * EMB + pl * 4];
                float4 rt = *(const float4*)&g_T[(192 + rst) * EMB + pl * 4];
                float4 te = req ? te1 : te0;
                float4 s;
                s.x = (rs.x + rd.x) + (rt.x + te.x);
                s.y = (rs.y + rd.y) + (rt.y + te.y);
                s.z = (rs.z + rd.z) + (rt.z + te.z);
                s.w = (rs.w + rd.w) + (rt.w + te.w);
                *(float4*)&Sum4[r * SS + pl * 4] = s;
            }
            __threadfence_block();
            BAR_ARRIVE(3, THREADS);               // Sum_full
        }
    }
}

// ---------------------------------------------------------------------------
extern "C" void kernel_launch(void* const* d_in, const int* in_sizes, int n_in,
                              void* d_out, int out_size)
{
    const int*   Z          = (const int*)d_in[0];
    const int*   stepA      = (const int*)d_in[1];
    const int*   src        = (const int*)d_in[2];
    const int*   dst        = (const int*)d_in[3];
    const int*   equiv      = (const int*)d_in[4];
    const float* rbf        = (const float*)d_in[5];
    const float* dvec       = (const float*)d_in[6];
    const float* emb_table  = (const float*)d_in[7];
    const float* step_table = (const float*)d_in[8];
    const float* equiv_tab  = (const float*)d_in[9];
    const float* W_rbf      = (const float*)d_in[10];
    const float* b_rbf      = (const float*)d_in[11];
    const float* W          = (const float*)d_in[12];
    const float* b          = (const float*)d_in[13];
    float* out = (float*)d_out;

    const int E = in_sizes[2];
    const int tiles = (E + 127) / 128;

    static int sms = 0;
    if (sms == 0) {
        if (cudaDeviceGetAttribute(&sms, cudaDevAttrMultiProcessorCount, 0) != cudaSuccess || sms <= 0)
            sms = 148;
    }
    const int grid = sms < tiles ? sms : tiles;

    const int smem_bytes = 215040;
    cudaFuncSetAttribute(edge_kernel, cudaFuncAttributeMaxDynamicSharedMemorySize, smem_bytes);

    precompute_kernel<<<214, 128>>>(emb_table, step_table, equiv_tab, W, b);
    edge_kernel<<<grid, THREADS, smem_bytes>>>(Z, stepA, src, dst, equiv,
                                               rbf, dvec, W_rbf, b_rbf,
                                               W + 2 * EMB * EMB, out, E, tiles);
}

// round 7
// speedup vs baseline: 1.5789x; 1.0757x over previous
#include <cuda_runtime.h>
#include <cuda_fp16.h>
#include <cstdint>

#define EMB 128
#define NR 6
#define SA 272          // A/B smem row stride in bytes (136 fp16)
#define SS 132          // Sum4 row stride in floats
#define THREADS 384     // 8 consumer warps + 4 producer warps

// smem offsets (bytes)
#define OFF_A0   0
#define OFF_A1   34816
#define OFF_B    69632
#define OFF_SUM  104448
#define OFF_RBFS 172032   // 2 x 128 x 8 floats
#define OFF_SIDX 180224   // 2 x 512 ints
#define SMEM_TOT 184320

// Precomputed table @ W_block projections: rows 0-95 Tsrc, 96-191 Tdst,
// 192-211 Tstep, 212-213 Teq (+bias folded into Teq rows).
__device__ float g_T[214 * EMB];

__device__ __forceinline__ uint32_t smem_u32(const void* p) {
    uint32_t a;
    asm("{ .reg .u64 t; cvta.to.shared.u64 t, %1; cvt.u32.u64 %0, t; }" : "=r"(a) : "l"(p));
    return a;
}
// silu(x) = 0.5x * (1 + tanh(x/2))
__device__ __forceinline__ float silu_f(float x) {
    float h = 0.5f * x, t;
    asm("tanh.approx.f32 %0, %1;" : "=f"(t) : "f"(h));
    return fmaf(h, t, h);
}
__device__ __forceinline__ void ldsm4(uint32_t* r, uint32_t addr) {
    asm volatile("ldmatrix.sync.aligned.m8n8.x4.shared.b16 {%0,%1,%2,%3}, [%4];"
                 : "=r"(r[0]), "=r"(r[1]), "=r"(r[2]), "=r"(r[3]) : "r"(addr));
}
__device__ __forceinline__ void ldsm4t(uint32_t* r, uint32_t addr) {
    asm volatile("ldmatrix.sync.aligned.m8n8.x4.trans.shared.b16 {%0,%1,%2,%3}, [%4];"
                 : "=r"(r[0]), "=r"(r[1]), "=r"(r[2]), "=r"(r[3]) : "r"(addr));
}
__device__ __forceinline__ void mma_f16(float* d, const uint32_t* a, const uint32_t* b) {
    asm volatile("mma.sync.aligned.m16n8k16.row.col.f32.f16.f16.f32 "
                 "{%0,%1,%2,%3}, {%4,%5,%6,%7}, {%8,%9}, {%0,%1,%2,%3};"
                 : "+f"(d[0]), "+f"(d[1]), "+f"(d[2]), "+f"(d[3])
                 : "r"(a[0]), "r"(a[1]), "r"(a[2]), "r"(a[3]), "r"(b[0]), "r"(b[1]));
}
#define BAR_SYNC(id, cnt)   asm volatile("bar.sync %0, %1;"   :: "r"(id), "r"(cnt) : "memory")
#define BAR_ARRIVE(id, cnt) asm volatile("bar.arrive %0, %1;" :: "r"(id), "r"(cnt) : "memory")

// ---------------------------------------------------------------------------
// Kernel 1: g_T = tables @ W_blocks (bias folded into Teq rows). 2 rows/block.
// ---------------------------------------------------------------------------
__global__ void precompute_kernel(const float* __restrict__ emb_table,
                                  const float* __restrict__ step_table,
                                  const float* __restrict__ equiv_table,
                                  const float* __restrict__ W,
                                  const float* __restrict__ b)
{
    __shared__ float in[2][EMB];
    int r = blockIdx.x * 2 + (threadIdx.x >> 7);
    int c = threadIdx.x & 127;
    if (r >= 214) return;
    const float* srow; const float* Wb; bool addb = false;
    if (r < 96)       { srow = emb_table + r * EMB;           Wb = W; }
    else if (r < 192) { srow = emb_table + (r - 96) * EMB;    Wb = W + EMB * EMB; }
    else if (r < 212) { srow = step_table + (r - 192) * EMB;  Wb = W + 3 * EMB * EMB; }
    else              { srow = equiv_table + (r - 212) * EMB; Wb = W + 4 * EMB * EMB; addb = true; }
    in[threadIdx.x >> 7][c] = srow[c];
    __syncthreads();
    const float* inr = in[threadIdx.x >> 7];
    float a0 = 0, a1 = 0, a2 = 0, a3 = 0;
    #pragma unroll
    for (int k = 0; k < EMB; k += 4) {
        a0 = fmaf(inr[k + 0], Wb[(k + 0) * EMB + c], a0);
        a1 = fmaf(inr[k + 1], Wb[(k + 1) * EMB + c], a1);
        a2 = fmaf(inr[k + 2], Wb[(k + 2) * EMB + c], a2);
        a3 = fmaf(inr[k + 3], Wb[(k + 3) * EMB + c], a3);
    }
    g_T[r * EMB + c] = (a0 + a1) + (a2 + a3) + (addb ? b[c] : 0.0f);
}

// ---------------------------------------------------------------------------
// Kernel 2: rbf_env (separate, memory-bound). 2 edges/thread, float4 stores.
// ---------------------------------------------------------------------------
__global__ void rbf_env_kernel(const float* __restrict__ dvec, float* __restrict__ envo, int E)
{
    int i = blockIdx.x * blockDim.x + threadIdx.x;
    int e0 = i * 2;
    if (e0 >= E) return;
    float v[12];
    #pragma unroll
    for (int q = 0; q < 2; q++) {
        int e = e0 + q;
        float x = (e < E) ? dvec[e] * 0.2f : 1.0f;
        float inv = 1.0f / x;
        float x2 = x * x;
        float x5 = x2 * x2 * x;
        float env = inv + x5 * (-28.0f + x * (48.0f + x * (-21.0f)));
        float coef = env * inv;
        const float PI = 3.14159265358979323846f;
        #pragma unroll
        for (int j = 0; j < NR; j++) v[q * 6 + j] = coef * __sinf(x * (PI * (float)(j + 1)));
    }
    float* o = envo + (size_t)e0 * NR;
    if (e0 + 1 < E) {
        *(float4*)(o + 0) = make_float4(v[0], v[1], v[2], v[3]);
        *(float4*)(o + 4) = make_float4(v[4], v[5], v[6], v[7]);
        *(float4*)(o + 8) = make_float4(v[8], v[9], v[10], v[11]);
    } else {
        #pragma unroll
        for (int j = 0; j < 6; j++) o[j] = v[j];
    }
}

// ---------------------------------------------------------------------------
// Kernel 3: persistent warp-specialized edge kernel.
// Consumers (warps 0-7): 32x64 tile single-pass fp16 mma.sync GEMM + epilogue.
// Producers (warps 8-11): indices + rbf stage + A fp16 + Sum4.
// A double-buffered. Barriers: 1/2=A_full[b], 3/4=A_empty[b], 5=Sum_full,
// 6=Sum_empty (384), 7=consumer-only (256), 8=producer-only (128).
// ---------------------------------------------------------------------------
__global__ __launch_bounds__(THREADS, 1)
void edge_kernel(const int* __restrict__ Z, const int* __restrict__ stepA,
                 const int* __restrict__ src, const int* __restrict__ dst,
                 const int* __restrict__ equiv,
                 const float* __restrict__ rbf,
                 const float* __restrict__ W_rbf, const float* __restrict__ b_rbf,
                 const float* __restrict__ W2,
                 float* __restrict__ out, int E, int tiles)
{
    extern __shared__ char sm[];
    char*  const Bsm  = sm + OFF_B;
    float* const Sum4 = (float*)(sm + OFF_SUM);
    float* const rbfs = (float*)(sm + OFF_RBFS);   // [2][128][8]
    int*   const sidx = (int*)(sm + OFF_SIDX);     // [2][4][128]

    const int tid  = threadIdx.x;
    const int wid  = tid >> 5;
    const int lane = tid & 31;

    // ---- one-time: W2^T -> fp16 smem ----
    for (int idx = tid; idx < EMB * EMB; idx += THREADS) {
        int k = idx >> 7, n = idx & 127;
        *(__half*)(Bsm + k * SA + n * 2) = __float2half(W2[idx]);
    }
    __syncthreads();

    if (wid < 8) {
        // =================== CONSUMERS ===================
        const int m0 = (wid & 3) * 32;
        const int nb = (wid >> 2) * 64;
        const uint32_t lmoff = (uint32_t)((lane & 15) * SA + (lane >> 4) * 16);
        const uint32_t A_u[2] = { smem_u32(sm + OFF_A0), smem_u32(sm + OFF_A1) };
        const uint32_t B_u = smem_u32(Bsm);
        int it = 0;

        for (int t = blockIdx.x; t < tiles; t += gridDim.x, it++) {
            const int ebase = t * 128;
            const int buf = it & 1;
            BAR_SYNC(1 + buf, THREADS);           // A_full[buf]

            float d[2][4][2][4];
            #pragma unroll
            for (int mt = 0; mt < 2; mt++)
                #pragma unroll
                for (int j = 0; j < 4; j++)
                    #pragma unroll
                    for (int s2 = 0; s2 < 2; s2++)
                        d[mt][j][s2][0] = d[mt][j][s2][1] = d[mt][j][s2][2] = d[mt][j][s2][3] = 0.0f;

            const uint32_t Au = A_u[buf] + m0 * SA + lmoff;
            const uint32_t Bu = B_u + nb * 2 + lmoff;
            #pragma unroll
            for (int ks = 0; ks < 8; ks++) {
                uint32_t a[8];
                ldsm4(a + 0, Au + ks * 32);
                ldsm4(a + 4, Au + 16 * SA + ks * 32);
                uint32_t b[16];
                #pragma unroll
                for (int j = 0; j < 4; j++) ldsm4t(b + 4 * j, Bu + ks * 16 * SA + j * 32);
                #pragma unroll
                for (int mt = 0; mt < 2; mt++)
                    #pragma unroll
                    for (int j = 0; j < 4; j++)
                        #pragma unroll
                        for (int s2 = 0; s2 < 2; s2++)
                            mma_f16(d[mt][j][s2], a + mt * 4, b + 4 * j + 2 * s2);
            }
            BAR_ARRIVE(3 + buf, THREADS);         // A_empty[buf]
            BAR_SYNC(5, THREADS);                 // Sum_full

            // epilogue in-place into Sum4
            #pragma unroll
            for (int mt = 0; mt < 2; mt++) {
                const int r = m0 + mt * 16 + (lane >> 2);
                float* S1 = &Sum4[r * SS];
                float* S2 = &Sum4[(r + 8) * SS];
                #pragma unroll
                for (int j = 0; j < 4; j++)
                    #pragma unroll
                    for (int s2 = 0; s2 < 2; s2++) {
                        const int c = nb + j * 16 + s2 * 8 + (lane & 3) * 2;
                        const float* dd = d[mt][j][s2];
                        float2 s1 = *(float2*)&S1[c];
                        s1.x = silu_f(dd[0] + s1.x);
                        s1.y = silu_f(dd[1] + s1.y);
                        *(float2*)&S1[c] = s1;
                        float2 s2v = *(float2*)&S2[c];
                        s2v.x = silu_f(dd[2] + s2v.x);
                        s2v.y = silu_f(dd[3] + s2v.y);
                        *(float2*)&S2[c] = s2v;
                    }
            }
            BAR_SYNC(7, 256);                     // consumer-only

            // coalesced copy-out: 16 rows per warp, 512B rows
            #pragma unroll 4
            for (int i = 0; i < 16; i++) {
                const int rr = wid * 16 + i;
                const int ge = ebase + rr;
                if (ge < E) {
                    float4 v = *(float4*)&Sum4[rr * SS + lane * 4];
                    *(float4*)&out[(size_t)ge * EMB + lane * 4] = v;
                }
            }
            BAR_ARRIVE(6, THREADS);               // Sum_empty
        }
    } else {
        // =================== PRODUCERS ===================
        const int pid = tid - 256;                // 0..127
        const int pw  = pid >> 5, pl = pid & 31;
        const int kp  = pid & 63;                 // k-pair: k0=2kp, k1=2kp+1
        const int eh  = pid >> 6;                 // edge half: 64*eh..64*eh+63

        // per-thread W_rbf weights in registers
        float w0[NR], w1[NR];
        #pragma unroll
        for (int j = 0; j < NR; j++) {
            w0[j] = W_rbf[j * EMB + 2 * kp];
            w1[j] = W_rbf[j * EMB + 2 * kp + 1];
        }
        const float b0 = b_rbf[2 * kp], b1 = b_rbf[2 * kp + 1];
        const float4 te0 = *(const float4*)&g_T[212 * EMB + pl * 4];
        const float4 te1 = *(const float4*)&g_T[213 * EMB + pl * 4];
        char* const A_c[2] = { sm + OFF_A0, sm + OFF_A1 };
        int it = 0;

        for (int t = blockIdx.x; t < tiles; t += gridDim.x, it++) {
            const int ebase = t * 128;
            const int buf = it & 1;
            const int ge = ebase + pid;
            const bool valid = (ge < E);

            // edge loads (latency overlapped with the barrier wait below)
            int zs = 0, zd = 0, st = 0, eq = 0;
            float2 ra = make_float2(0, 0), rb = make_float2(0, 0), rc = make_float2(0, 0);
            if (valid) {
                int s = src[ge], dd = dst[ge];
                zs = Z[s]; zd = Z[dd]; st = stepA[s]; eq = equiv[ge];
                const float* rp = rbf + (size_t)ge * NR;
                ra = *(const float2*)(rp);
                rb = *(const float2*)(rp + 2);
                rc = *(const float2*)(rp + 4);
            }

            if (it >= 2) BAR_SYNC(3 + buf, THREADS);   // A_empty[buf]

            // stage rbf + indices
            float* rrow = rbfs + buf * 1024 + pid * 8;
            *(float2*)(rrow + 0) = ra;
            *(float2*)(rrow + 2) = rb;
            *(float2*)(rrow + 4) = rc;
            int* sx = sidx + buf * 512;
            sx[pid] = zs; sx[128 + pid] = zd; sx[256 + pid] = st; sx[384 + pid] = eq;
            BAR_SYNC(8, 128);                     // producers: rbfs/sidx visible

            // A production: 64 edges x 2 k-values, fp16
            char* const abase = A_c[buf] + kp * 4;
            const float* rb0 = rbfs + buf * 1024 + (64 * eh) * 8;
            #pragma unroll 4
            for (int e0 = 0; e0 < 64; e0++) {
                float4 q1 = *(const float4*)(rb0 + e0 * 8);
                float2 q2 = *(const float2*)(rb0 + e0 * 8 + 4);
                float z0 = b0 + q1.x * w0[0] + q1.y * w0[1] + q1.z * w0[2]
                              + q1.w * w0[3] + q2.x * w0[4] + q2.y * w0[5];
                float z1 = b1 + q1.x * w1[0] + q1.y * w1[1] + q1.z * w1[2]
                              + q1.w * w1[3] + q2.x * w1[4] + q2.y * w1[5];
                float a0 = silu_f(z0);
                float a1 = silu_f(z1);
                uint32_t p;
                asm("cvt.rn.f16x2.f32 %0, %1, %2;" : "=r"(p) : "f"(a1), "f"(a0));
                *(uint32_t*)(abase + (64 * eh + e0) * SA) = p;
            }
            __threadfence_block();
            BAR_ARRIVE(1 + buf, THREADS);         // A_full[buf]

            if (it >= 1) BAR_SYNC(6, THREADS);    // Sum_empty

            // Sum4: 32 rows per producer warp, cooperative 512B-row gathers
            #pragma unroll 4
            for (int i = 0; i < 32; i++) {
                const int r = pw * 32 + i;
                const int rzs = sx[r], rzd = sx[128 + r], rst = sx[256 + r], req = sx[384 + r];
                float4 rs = *(const float4*)&g_T[rzs * EMB + pl * 4];
                float4 rd = *(const float4*)&g_T[(96 + rzd) * EMB + pl * 4];
                float4 rt = *(const float4*)&g_T[(192 + rst) * EMB + pl * 4];
                float4 te = req ? te1 : te0;
                float4 s;
                s.x = (rs.x + rd.x) + (rt.x + te.x);
                s.y = (rs.y + rd.y) + (rt.y + te.y);
                s.z = (rs.z + rd.z) + (rt.z + te.z);
                s.w = (rs.w + rd.w) + (rt.w + te.w);
                *(float4*)&Sum4[r * SS + pl * 4] = s;
            }
            __threadfence_block();
            BAR_ARRIVE(5, THREADS);               // Sum_full
        }
    }
}

// ---------------------------------------------------------------------------
extern "C" void kernel_launch(void* const* d_in, const int* in_sizes, int n_in,
                              void* d_out, int out_size)
{
    const int*   Z          = (const int*)d_in[0];
    const int*   stepA      = (const int*)d_in[1];
    const int*   src        = (const int*)d_in[2];
    const int*   dst        = (const int*)d_in[3];
    const int*   equiv      = (const int*)d_in[4];
    const float* rbf        = (const float*)d_in[5];
    const float* dvec       = (const float*)d_in[6];
    const float* emb_table  = (const float*)d_in[7];
    const float* step_table = (const float*)d_in[8];
    const float* equiv_tab  = (const float*)d_in[9];
    const float* W_rbf      = (const float*)d_in[10];
    const float* b_rbf      = (const float*)d_in[11];
    const float* W          = (const float*)d_in[12];
    const float* b          = (const float*)d_in[13];
    float* out = (float*)d_out;

    const int E = in_sizes[2];
    const int tiles = (E + 127) / 128;

    static int sms = 0;
    if (sms == 0) {
        if (cudaDeviceGetAttribute(&sms, cudaDevAttrMultiProcessorCount, 0) != cudaSuccess || sms <= 0)
            sms = 148;
    }
    const int grid = sms < tiles ? sms : tiles;

    cudaFuncSetAttribute(edge_kernel, cudaFuncAttributeMaxDynamicSharedMemorySize, SMEM_TOT);

    precompute_kernel<<<107, 256>>>(emb_table, step_table, equiv_tab, W, b);
    rbf_env_kernel<<<(E / 2 + 255) / 256, 256>>>(dvec, out + (size_t)E * EMB, E);
    edge_kernel<<<grid, THREADS, SMEM_TOT>>>(Z, stepA, src, dst, equiv,
                                             rbf, W_rbf, b_rbf,
                                             W + 2 * EMB * EMB, out, E, tiles);
}

// round 8
// speedup vs baseline: 1.5935x; 1.0093x over previous
#include <cuda_runtime.h>
#include <cuda_fp16.h>
#include <cstdint>

#define EMB 128
#define NR 6
#define SA 272          // A/B smem row stride in bytes (136 fp16)
#define SS 132          // Sum4 row stride in floats
#define TILE 64         // edges per tile
#define THREADS 192     // 4 consumer warps + 2 producer warps

// smem offsets (bytes)
#define OFF_A0   0
#define OFF_A1   17408
#define OFF_B    34816
#define OFF_SUM  69632    // 64 x 132 floats
#define OFF_RBFS 103424   // 2 x 64 x 8 floats
#define OFF_SIDX 107520   // 2 x 256 ints
#define SMEM_TOT 109568

// Precomputed table @ W_block projections: rows 0-95 Tsrc, 96-191 Tdst,
// 192-211 Tstep, 212-213 Teq (+bias folded into Teq rows).
__device__ float g_T[214 * EMB];

__device__ __forceinline__ uint32_t smem_u32(const void* p) {
    uint32_t a;
    asm("{ .reg .u64 t; cvta.to.shared.u64 t, %1; cvt.u32.u64 %0, t; }" : "=r"(a) : "l"(p));
    return a;
}
// silu(x) = 0.5x * (1 + tanh(x/2))
__device__ __forceinline__ float silu_f(float x) {
    float h = 0.5f * x, t;
    asm("tanh.approx.f32 %0, %1;" : "=f"(t) : "f"(h));
    return fmaf(h, t, h);
}
__device__ __forceinline__ void ldsm4(uint32_t* r, uint32_t addr) {
    asm volatile("ldmatrix.sync.aligned.m8n8.x4.shared.b16 {%0,%1,%2,%3}, [%4];"
                 : "=r"(r[0]), "=r"(r[1]), "=r"(r[2]), "=r"(r[3]) : "r"(addr));
}
__device__ __forceinline__ void ldsm4t(uint32_t* r, uint32_t addr) {
    asm volatile("ldmatrix.sync.aligned.m8n8.x4.trans.shared.b16 {%0,%1,%2,%3}, [%4];"
                 : "=r"(r[0]), "=r"(r[1]), "=r"(r[2]), "=r"(r[3]) : "r"(addr));
}
__device__ __forceinline__ void mma_f16(float* d, const uint32_t* a, const uint32_t* b) {
    asm volatile("mma.sync.aligned.m16n8k16.row.col.f32.f16.f16.f32 "
                 "{%0,%1,%2,%3}, {%4,%5,%6,%7}, {%8,%9}, {%0,%1,%2,%3};"
                 : "+f"(d[0]), "+f"(d[1]), "+f"(d[2]), "+f"(d[3])
                 : "r"(a[0]), "r"(a[1]), "r"(a[2]), "r"(a[3]), "r"(b[0]), "r"(b[1]));
}
#define BAR_SYNC(id, cnt)   asm volatile("bar.sync %0, %1;"   :: "r"(id), "r"(cnt) : "memory")
#define BAR_ARRIVE(id, cnt) asm volatile("bar.arrive %0, %1;" :: "r"(id), "r"(cnt) : "memory")

// ---------------------------------------------------------------------------
// Kernel 1: g_T = tables @ W_blocks (bias folded into Teq rows). 2 rows/block.
// ---------------------------------------------------------------------------
__global__ void precompute_kernel(const float* __restrict__ emb_table,
                                  const float* __restrict__ step_table,
                                  const float* __restrict__ equiv_table,
                                  const float* __restrict__ W,
                                  const float* __restrict__ b)
{
    __shared__ float in[2][EMB];
    int r = blockIdx.x * 2 + (threadIdx.x >> 7);
    int c = threadIdx.x & 127;
    if (r >= 214) return;
    const float* srow; const float* Wb; bool addb = false;
    if (r < 96)       { srow = emb_table + r * EMB;           Wb = W; }
    else if (r < 192) { srow = emb_table + (r - 96) * EMB;    Wb = W + EMB * EMB; }
    else if (r < 212) { srow = step_table + (r - 192) * EMB;  Wb = W + 3 * EMB * EMB; }
    else              { srow = equiv_table + (r - 212) * EMB; Wb = W + 4 * EMB * EMB; addb = true; }
    in[threadIdx.x >> 7][c] = srow[c];
    __syncthreads();
    const float* inr = in[threadIdx.x >> 7];
    float a0 = 0, a1 = 0, a2 = 0, a3 = 0;
    #pragma unroll
    for (int k = 0; k < EMB; k += 4) {
        a0 = fmaf(inr[k + 0], Wb[(k + 0) * EMB + c], a0);
        a1 = fmaf(inr[k + 1], Wb[(k + 1) * EMB + c], a1);
        a2 = fmaf(inr[k + 2], Wb[(k + 2) * EMB + c], a2);
        a3 = fmaf(inr[k + 3], Wb[(k + 3) * EMB + c], a3);
    }
    g_T[r * EMB + c] = (a0 + a1) + (a2 + a3) + (addb ? b[c] : 0.0f);
}

// ---------------------------------------------------------------------------
// Kernel 2: rbf_env (separate, memory-bound). 2 edges/thread, float4 stores.
// ---------------------------------------------------------------------------
__global__ void rbf_env_kernel(const float* __restrict__ dvec, float* __restrict__ envo, int E)
{
    int i = blockIdx.x * blockDim.x + threadIdx.x;
    int e0 = i * 2;
    if (e0 >= E) return;
    float v[12];
    #pragma unroll
    for (int q = 0; q < 2; q++) {
        int e = e0 + q;
        float x = (e < E) ? dvec[e] * 0.2f : 1.0f;
        float inv = 1.0f / x;
        float x2 = x * x;
        float x5 = x2 * x2 * x;
        float env = inv + x5 * (-28.0f + x * (48.0f + x * (-21.0f)));
        float coef = env * inv;
        const float PI = 3.14159265358979323846f;
        #pragma unroll
        for (int j = 0; j < NR; j++) v[q * 6 + j] = coef * __sinf(x * (PI * (float)(j + 1)));
    }
    float* o = envo + (size_t)e0 * NR;
    if (e0 + 1 < E) {
        *(float4*)(o + 0) = make_float4(v[0], v[1], v[2], v[3]);
        *(float4*)(o + 4) = make_float4(v[4], v[5], v[6], v[7]);
        *(float4*)(o + 8) = make_float4(v[8], v[9], v[10], v[11]);
    } else {
        #pragma unroll
        for (int j = 0; j < 6; j++) o[j] = v[j];
    }
}

// ---------------------------------------------------------------------------
// Kernel 3: persistent warp-specialized edge kernel, 2 CTAs per SM.
// Consumers (warps 0-3): 32x64 tile single-pass fp16 mma.sync GEMM + epilogue.
// Producers (warps 4-5): indices + rbf stage + A fp16 + Sum4.
// A double-buffered. Barriers: 1/2=A_full[b], 3/4=A_empty[b], 5=Sum_full,
// 6=Sum_empty (192), 7=consumer-only (128), 8=producer-only (64).
// ---------------------------------------------------------------------------
__global__ __launch_bounds__(THREADS, 2)
void edge_kernel(const int* __restrict__ Z, const int* __restrict__ stepA,
                 const int* __restrict__ src, const int* __restrict__ dst,
                 const int* __restrict__ equiv,
                 const float* __restrict__ rbf,
                 const float* __restrict__ W_rbf, const float* __restrict__ b_rbf,
                 const float* __restrict__ W2,
                 float* __restrict__ out, int E, int tiles)
{
    extern __shared__ char sm[];
    char*  const Bsm  = sm + OFF_B;
    float* const Sum4 = (float*)(sm + OFF_SUM);
    float* const rbfs = (float*)(sm + OFF_RBFS);   // [2][64][8]
    int*   const sidx = (int*)(sm + OFF_SIDX);     // [2][4][64]

    const int tid  = threadIdx.x;
    const int wid  = tid >> 5;
    const int lane = tid & 31;

    // ---- one-time: W2^T -> fp16 smem ----
    for (int idx = tid; idx < EMB * EMB; idx += THREADS) {
        int k = idx >> 7, n = idx & 127;
        *(__half*)(Bsm + k * SA + n * 2) = __float2half(W2[idx]);
    }
    __syncthreads();

    if (wid < 4) {
        // =================== CONSUMERS ===================
        const int m0 = (wid & 1) * 32;
        const int nb = (wid >> 1) * 64;
        const uint32_t lmoff = (uint32_t)((lane & 15) * SA + (lane >> 4) * 16);
        const uint32_t A_u[2] = { smem_u32(sm + OFF_A0), smem_u32(sm + OFF_A1) };
        const uint32_t B_u = smem_u32(Bsm);
        int it = 0;

        for (int t = blockIdx.x; t < tiles; t += gridDim.x, it++) {
            const int ebase = t * TILE;
            const int buf = it & 1;
            BAR_SYNC(1 + buf, THREADS);           // A_full[buf]

            float d[2][4][2][4];
            #pragma unroll
            for (int mt = 0; mt < 2; mt++)
                #pragma unroll
                for (int j = 0; j < 4; j++)
                    #pragma unroll
                    for (int s2 = 0; s2 < 2; s2++)
                        d[mt][j][s2][0] = d[mt][j][s2][1] = d[mt][j][s2][2] = d[mt][j][s2][3] = 0.0f;

            const uint32_t Au = A_u[buf] + m0 * SA + lmoff;
            const uint32_t Bu = B_u + nb * 2 + lmoff;
            #pragma unroll
            for (int ks = 0; ks < 8; ks++) {
                uint32_t a[8];
                ldsm4(a + 0, Au + ks * 32);
                ldsm4(a + 4, Au + 16 * SA + ks * 32);
                uint32_t b[16];
                #pragma unroll
                for (int j = 0; j < 4; j++) ldsm4t(b + 4 * j, Bu + ks * 16 * SA + j * 32);
                #pragma unroll
                for (int mt = 0; mt < 2; mt++)
                    #pragma unroll
                    for (int j = 0; j < 4; j++)
                        #pragma unroll
                        for (int s2 = 0; s2 < 2; s2++)
                            mma_f16(d[mt][j][s2], a + mt * 4, b + 4 * j + 2 * s2);
            }
            BAR_ARRIVE(3 + buf, THREADS);         // A_empty[buf]
            BAR_SYNC(5, THREADS);                 // Sum_full

            // epilogue in-place into Sum4
            #pragma unroll
            for (int mt = 0; mt < 2; mt++) {
                const int r = m0 + mt * 16 + (lane >> 2);
                float* S1 = &Sum4[r * SS];
                float* S2 = &Sum4[(r + 8) * SS];
                #pragma unroll
                for (int j = 0; j < 4; j++)
                    #pragma unroll
                    for (int s2 = 0; s2 < 2; s2++) {
                        const int c = nb + j * 16 + s2 * 8 + (lane & 3) * 2;
                        const float* dd = d[mt][j][s2];
                        float2 s1 = *(float2*)&S1[c];
                        s1.x = silu_f(dd[0] + s1.x);
                        s1.y = silu_f(dd[1] + s1.y);
                        *(float2*)&S1[c] = s1;
                        float2 s2v = *(float2*)&S2[c];
                        s2v.x = silu_f(dd[2] + s2v.x);
                        s2v.y = silu_f(dd[3] + s2v.y);
                        *(float2*)&S2[c] = s2v;
                    }
            }
            BAR_SYNC(7, 128);                     // consumer-only

            // coalesced copy-out: 16 rows per warp, 512B rows
            #pragma unroll 4
            for (int i = 0; i < 16; i++) {
                const int rr = wid * 16 + i;
                const int ge = ebase + rr;
                if (ge < E) {
                    float4 v = *(float4*)&Sum4[rr * SS + lane * 4];
                    *(float4*)&out[(size_t)ge * EMB + lane * 4] = v;
                }
            }
            BAR_ARRIVE(6, THREADS);               // Sum_empty
        }
    } else {
        // =================== PRODUCERS ===================
        const int pid = tid - 128;                // 0..63
        const int pw  = pid >> 5, pl = pid & 31;

        // per-thread W_rbf weights in registers (k-pair 2*pid, 2*pid+1)
        float w0[NR], w1[NR];
        #pragma unroll
        for (int j = 0; j < NR; j++) {
            w0[j] = W_rbf[j * EMB + 2 * pid];
            w1[j] = W_rbf[j * EMB + 2 * pid + 1];
        }
        const float b0 = b_rbf[2 * pid], b1 = b_rbf[2 * pid + 1];
        const float4 te0 = *(const float4*)&g_T[212 * EMB + pl * 4];
        const float4 te1 = *(const float4*)&g_T[213 * EMB + pl * 4];
        char* const A_c[2] = { sm + OFF_A0, sm + OFF_A1 };
        int it = 0;

        for (int t = blockIdx.x; t < tiles; t += gridDim.x, it++) {
            const int ebase = t * TILE;
            const int buf = it & 1;
            const int ge = ebase + pid;
            const bool valid = (ge < E);

            // edge loads (latency overlapped with the barrier wait below)
            int zs = 0, zd = 0, st = 0, eq = 0;
            float2 ra = make_float2(0, 0), rb = make_float2(0, 0), rc = make_float2(0, 0);
            if (valid) {
                int s = src[ge], dd = dst[ge];
                zs = Z[s]; zd = Z[dd]; st = stepA[s]; eq = equiv[ge];
                const float* rp = rbf + (size_t)ge * NR;
                ra = *(const float2*)(rp);
                rb = *(const float2*)(rp + 2);
                rc = *(const float2*)(rp + 4);
            }

            if (it >= 2) BAR_SYNC(3 + buf, THREADS);   // A_empty[buf]

            // stage rbf + indices
            float* rrow = rbfs + buf * 512 + pid * 8;
            *(float2*)(rrow + 0) = ra;
            *(float2*)(rrow + 2) = rb;
            *(float2*)(rrow + 4) = rc;
            int* sx = sidx + buf * 256;
            sx[pid] = zs; sx[64 + pid] = zd; sx[128 + pid] = st; sx[192 + pid] = eq;
            BAR_SYNC(8, 64);                      // producers: rbfs/sidx visible

            // A production: 64 edges x 2 k-values, fp16
            char* const abase = A_c[buf] + pid * 4;
            const float* rb0 = rbfs + buf * 512;
            #pragma unroll 4
            for (int e0 = 0; e0 < TILE; e0++) {
                float4 q1 = *(const float4*)(rb0 + e0 * 8);
                float2 q2 = *(const float2*)(rb0 + e0 * 8 + 4);
                float z0 = b0 + q1.x * w0[0] + q1.y * w0[1] + q1.z * w0[2]
                              + q1.w * w0[3] + q2.x * w0[4] + q2.y * w0[5];
                float z1 = b1 + q1.x * w1[0] + q1.y * w1[1] + q1.z * w1[2]
                              + q1.w * w1[3] + q2.x * w1[4] + q2.y * w1[5];
                float a0 = silu_f(z0);
                float a1 = silu_f(z1);
                uint32_t p;
                asm("cvt.rn.f16x2.f32 %0, %1, %2;" : "=r"(p) : "f"(a1), "f"(a0));
                *(uint32_t*)(abase + e0 * SA) = p;
            }
            __threadfence_block();
            BAR_ARRIVE(1 + buf, THREADS);         // A_full[buf]

            if (it >= 1) BAR_SYNC(6, THREADS);    // Sum_empty

            // Sum4: 32 rows per producer warp, cooperative 512B-row gathers
            #pragma unroll 4
            for (int i = 0; i < 32; i++) {
                const int r = pw * 32 + i;
                const int rzs = sx[r], rzd = sx[64 + r], rst = sx[128 + r], req = sx[192 + r];
                float4 rs = *(const float4*)&g_T[rzs * EMB + pl * 4];
                float4 rd = *(const float4*)&g_T[(96 + rzd) * EMB + pl * 4];
                float4 rt = *(const float4*)&g_T[(192 + rst) * EMB + pl * 4];
                float4 te = req ? te1 : te0;
                float4 s;
                s.x = (rs.x + rd.x) + (rt.x + te.x);
                s.y = (rs.y + rd.y) + (rt.y + te.y);
                s.z = (rs.z + rd.z) + (rt.z + te.z);
                s.w = (rs.w + rd.w) + (rt.w + te.w);
                *(float4*)&Sum4[r * SS + pl * 4] = s;
            }
            __threadfence_block();
            BAR_ARRIVE(5, THREADS);               // Sum_full
        }
    }
}

// ---------------------------------------------------------------------------
extern "C" void kernel_launch(void* const* d_in, const int* in_sizes, int n_in,
                              void* d_out, int out_size)
{
    const int*   Z          = (const int*)d_in[0];
    const int*   stepA      = (const int*)d_in[1];
    const int*   src        = (const int*)d_in[2];
    const int*   dst        = (const int*)d_in[3];
    const int*   equiv      = (const int*)d_in[4];
    const float* rbf        = (const float*)d_in[5];
    const float* dvec       = (const float*)d_in[6];
    const float* emb_table  = (const float*)d_in[7];
    const float* step_table = (const float*)d_in[8];
    const float* equiv_tab  = (const float*)d_in[9];
    const float* W_rbf      = (const float*)d_in[10];
    const float* b_rbf      = (const float*)d_in[11];
    const float* W          = (const float*)d_in[12];
    const float* b          = (const float*)d_in[13];
    float* out = (float*)d_out;

    const int E = in_sizes[2];
    const int tiles = (E + TILE - 1) / TILE;

    static int sms = 0;
    if (sms == 0) {
        if (cudaDeviceGetAttribute(&sms, cudaDevAttrMultiProcessorCount, 0) != cudaSuccess || sms <= 0)
            sms = 148;
    }
    int grid = 2 * sms;
    if (grid > tiles) grid = tiles;

    cudaFuncSetAttribute(edge_kernel, cudaFuncAttributeMaxDynamicSharedMemorySize, SMEM_TOT);

    precompute_kernel<<<107, 256>>>(emb_table, step_table, equiv_tab, W, b);
    rbf_env_kernel<<<(E / 2 + 255) / 256, 256>>>(dvec, out + (size_t)E * EMB, E);
    edge_kernel<<<grid, THREADS, SMEM_TOT>>>(Z, stepA, src, dst, equiv,
                                             rbf, W_rbf, b_rbf,
                                             W + 2 * EMB * EMB, out, E, tiles);
}

// round 10
// speedup vs baseline: 2.2396x; 1.4054x over previous
#include <cuda_runtime.h>
#include <cuda_fp16.h>
#include <cstdint>

#define EMB 128
#define NR 6
#define SA 272          // A/B smem row stride in bytes (136 fp16)
#define SS 132          // Sum row stride in floats (528B = 33*16, float4-aligned)
#define RS 9            // rbf stage row stride in floats
#define TILE 96         // edges per tile
#define THREADS 384     // 12 warps, monolithic phases, 2 CTAs/SM

// smem offsets (bytes)
#define OFF_A    0        // 96*272           = 26112
#define OFF_B    26112    // 128*272          = 34816 -> 60928
#define OFF_SUM  60928    // 96*132*4         = 50688 -> 111616
#define OFF_RBFS OFF_SUM  // overlay: 96*9*4  = 3456 (dead before Sum written)
#define OFF_WR   111616   // 4*264*4          = 4224  -> 115840
#define OFF_IDX  115840   // 96*4             = 384   -> 116224
#define SMEM_TOT 116224   // x2 CTAs = 232448 <= 233472 (228KB)

// Precomputed table @ W_block projections: rows 0-95 Tsrc, 96-191 Tdst,
// 192-211 Tstep, 212-213 Teq (+bias folded into Teq rows).
__device__ float g_T[214 * EMB];

__device__ __forceinline__ uint32_t smem_u32(const void* p) {
    uint32_t a;
    asm("{ .reg .u64 t; cvta.to.shared.u64 t, %1; cvt.u32.u64 %0, t; }" : "=r"(a) : "l"(p));
    return a;
}
// silu(x) = 0.5x * (1 + tanh(x/2))
__device__ __forceinline__ float silu_f(float x) {
    float h = 0.5f * x, t;
    asm("tanh.approx.f32 %0, %1;" : "=f"(t) : "f"(h));
    return fmaf(h, t, h);
}
__device__ __forceinline__ void ldsm4(uint32_t* r, uint32_t addr) {
    asm volatile("ldmatrix.sync.aligned.m8n8.x4.shared.b16 {%0,%1,%2,%3}, [%4];"
                 : "=r"(r[0]), "=r"(r[1]), "=r"(r[2]), "=r"(r[3]) : "r"(addr));
}
__device__ __forceinline__ void ldsm4t(uint32_t* r, uint32_t addr) {
    asm volatile("ldmatrix.sync.aligned.m8n8.x4.trans.shared.b16 {%0,%1,%2,%3}, [%4];"
                 : "=r"(r[0]), "=r"(r[1]), "=r"(r[2]), "=r"(r[3]) : "r"(addr));
}
__device__ __forceinline__ void mma_f16(float* d, const uint32_t* a, const uint32_t* b) {
    asm volatile("mma.sync.aligned.m16n8k16.row.col.f32.f16.f16.f32 "
                 "{%0,%1,%2,%3}, {%4,%5,%6,%7}, {%8,%9}, {%0,%1,%2,%3};"
                 : "+f"(d[0]), "+f"(d[1]), "+f"(d[2]), "+f"(d[3])
                 : "r"(a[0]), "r"(a[1]), "r"(a[2]), "r"(a[3]), "r"(b[0]), "r"(b[1]));
}

// ---------------------------------------------------------------------------
// Kernel 1: g_T = tables @ W_blocks (bias folded into Teq rows). 2 rows/block.
// ---------------------------------------------------------------------------
__global__ void precompute_kernel(const float* __restrict__ emb_table,
                                  const float* __restrict__ step_table,
                                  const float* __restrict__ equiv_table,
                                  const float* __restrict__ W,
                                  const float* __restrict__ b)
{
    __shared__ float in[2][EMB];
    int r = blockIdx.x * 2 + (threadIdx.x >> 7);
    int c = threadIdx.x & 127;
    if (r >= 214) return;
    const float* srow; const float* Wb; bool addb = false;
    if (r < 96)       { srow = emb_table + r * EMB;           Wb = W; }
    else if (r < 192) { srow = emb_table + (r - 96) * EMB;    Wb = W + EMB * EMB; }
    else if (r < 212) { srow = step_table + (r - 192) * EMB;  Wb = W + 3 * EMB * EMB; }
    else              { srow = equiv_table + (r - 212) * EMB; Wb = W + 4 * EMB * EMB; addb = true; }
    in[threadIdx.x >> 7][c] = srow[c];
    __syncthreads();
    const float* inr = in[threadIdx.x >> 7];
    float a0 = 0, a1 = 0, a2 = 0, a3 = 0;
    #pragma unroll
    for (int k = 0; k < EMB; k += 4) {
        a0 = fmaf(inr[k + 0], Wb[(k + 0) * EMB + c], a0);
        a1 = fmaf(inr[k + 1], Wb[(k + 1) * EMB + c], a1);
        a2 = fmaf(inr[k + 2], Wb[(k + 2) * EMB + c], a2);
        a3 = fmaf(inr[k + 3], Wb[(k + 3) * EMB + c], a3);
    }
    g_T[r * EMB + c] = (a0 + a1) + (a2 + a3) + (addb ? b[c] : 0.0f);
}

// ---------------------------------------------------------------------------
// Kernel 2: rbf_env (separate, memory-bound). 2 edges/thread, float4 stores.
// ---------------------------------------------------------------------------
__global__ void rbf_env_kernel(const float* __restrict__ dvec, float* __restrict__ envo, int E)
{
    int i = blockIdx.x * blockDim.x + threadIdx.x;
    int e0 = i * 2;
    if (e0 >= E) return;
    float v[12];
    #pragma unroll
    for (int q = 0; q < 2; q++) {
        int e = e0 + q;
        float x = (e < E) ? dvec[e] * 0.2f : 1.0f;
        float inv = 1.0f / x;
        float x2 = x * x;
        float x5 = x2 * x2 * x;
        float env = inv + x5 * (-28.0f + x * (48.0f + x * (-21.0f)));
        float coef = env * inv;
        const float PI = 3.14159265358979323846f;
        #pragma unroll
        for (int j = 0; j < NR; j++) v[q * 6 + j] = coef * __sinf(x * (PI * (float)(j + 1)));
    }
    float* o = envo + (size_t)e0 * NR;
    if (e0 + 1 < E) {
        *(float4*)(o + 0) = make_float4(v[0], v[1], v[2], v[3]);
        *(float4*)(o + 4) = make_float4(v[4], v[5], v[6], v[7]);
        *(float4*)(o + 8) = make_float4(v[8], v[9], v[10], v[11]);
    } else {
        #pragma unroll
        for (int j = 0; j < 6; j++) o[j] = v[j];
    }
}

// ---------------------------------------------------------------------------
// Kernel 3: persistent monolithic edge kernel, 2 CTAs/SM x 384 threads.
// 12 warps in a 3(m) x 4(n) grid, 32x32 output tile per warp, fp16 mma.sync.
// ---------------------------------------------------------------------------
__global__ __launch_bounds__(THREADS, 2)
void edge_kernel(const int* __restrict__ Z, const int* __restrict__ stepA,
                 const int* __restrict__ src, const int* __restrict__ dst,
                 const int* __restrict__ equiv,
                 const float* __restrict__ rbf,
                 const float* __restrict__ W_rbf, const float* __restrict__ b_rbf,
                 const float* __restrict__ W2,
                 float* __restrict__ out, int E, int tiles)
{
    extern __shared__ char sm[];
    char*  const Asm  = sm + OFF_A;
    char*  const Bsm  = sm + OFF_B;
    float* const Sum  = (float*)(sm + OFF_SUM);
    float* const rbfs = (float*)(sm + OFF_RBFS);   // overlay, dead before Sum written
    float* const Wr   = (float*)(sm + OFF_WR);     // [4][264] (32k x 8 + pad per q)
    int*   const sidx = (int*)(sm + OFF_IDX);      // [96] packed

    const int tid  = threadIdx.x;
    const int wid  = tid >> 5;
    const int lane = tid & 31;

    // ---- one-time: W2^T -> fp16 smem; W_rbf -> banked smem blocks ----
    for (int idx = tid; idx < EMB * EMB; idx += THREADS) {
        int k = idx >> 7, n = idx & 127;
        *(__half*)(Bsm + k * SA + n * 2) = __float2half(W2[idx]);
    }
    for (int i = tid; i < 4 * 32 * 8; i += THREADS) {
        int q = i >> 8, kk = (i >> 3) & 31, j = i & 7;
        int k = 32 * q + kk;
        Wr[q * 264 + kk * 8 + j] = (j < 6) ? W_rbf[j * EMB + k] : (j == 6 ? b_rbf[k] : 0.0f);
    }
    __syncthreads();

    const int wm = wid >> 2;      // 0..2  (m-group of 32 edges)
    const int wn = wid & 3;       // 0..3  (n-group of 32 cols)
    const int m0 = wm * 32;
    const uint32_t lmoff = (uint32_t)((lane & 15) * SA + (lane >> 4) * 16);
    const uint32_t A_u = smem_u32(Asm);
    const uint32_t B_u = smem_u32(Bsm);
    // A-production mapping: e = tid % 96 (lanes contiguous), q = tid / 96
    const int pe = tid % TILE;
    const int pq = tid / TILE;    // 0..3, k-range [32q, 32q+32)

    for (int t = blockIdx.x; t < tiles; t += gridDim.x) {
        const int ebase = t * TILE;

        // ---- P1: indices (tid<96, bit-packed) + rbf stage (96<=tid<192) ----
        if (tid < TILE) {
            const int ge = ebase + tid;
            int pk = 0;
            if (ge < E) {
                int s = src[ge], dd = dst[ge];
                pk = Z[s] | (Z[dd] << 7) | (stepA[s] << 14) | (equiv[ge] << 19);
            }
            sidx[tid] = pk;
        } else if (tid < 2 * TILE) {
            const int e = tid - TILE;
            const int ge = ebase + e;
            if (ge < E) {
                const float* rp = rbf + (size_t)ge * NR;
                float2 a = *(const float2*)(rp);
                float2 b = *(const float2*)(rp + 2);
                float2 c = *(const float2*)(rp + 4);
                float* rr = rbfs + e * RS;
                rr[0] = a.x; rr[1] = a.y; rr[2] = b.x;
                rr[3] = b.y; rr[4] = c.x; rr[5] = c.y;
            }
        }
        __syncthreads();

        // ---- P2a: A = silu(rbf @ W_rbf + b) fp16; thread = (edge pe, k-quarter pq) ----
        {
            const float* rr = rbfs + pe * RS;
            float r0 = rr[0], r1 = rr[1], r2 = rr[2], r3 = rr[3], r4 = rr[4], r5 = rr[5];
            const float* wq = Wr + pq * 264;
            char* ah = Asm + pe * SA + pq * 64;
            #pragma unroll
            for (int g = 0; g < 4; g++) {
                uint32_t hb[4];
                #pragma unroll
                for (int pp = 0; pp < 4; pp++) {
                    const int kk = g * 8 + pp * 2;
                    float4 wa = *(const float4*)&wq[kk * 8];
                    float4 wb = *(const float4*)&wq[kk * 8 + 4];
                    float4 wc = *(const float4*)&wq[kk * 8 + 8];
                    float4 wd = *(const float4*)&wq[kk * 8 + 12];
                    float z0 = wb.z + r0 * wa.x + r1 * wa.y + r2 * wa.z + r3 * wa.w + r4 * wb.x + r5 * wb.y;
                    float z1 = wd.z + r0 * wc.x + r1 * wc.y + r2 * wc.z + r3 * wc.w + r4 * wd.x + r5 * wd.y;
                    float a0 = silu_f(z0);
                    float a1 = silu_f(z1);
                    asm("cvt.rn.f16x2.f32 %0, %1, %2;" : "=r"(hb[pp]) : "f"(a1), "f"(a0));
                }
                *(uint4*)(ah + g * 16) = make_uint4(hb[0], hb[1], hb[2], hb[3]);
            }
        }
        __syncthreads();

        // ---- P2b: Sum gathers (8 rows/warp; LDG latency overlaps other warps' GEMM) ----
        #pragma unroll
        for (int i = 0; i < 8; i++) {
            const int r = wid * 8 + i;
            const uint32_t pk = (uint32_t)sidx[r];
            const int zs = pk & 127, zd = (pk >> 7) & 127;
            const int st = (pk >> 14) & 31, eq = (pk >> 19) & 1;
            float4 rs = *(const float4*)&g_T[zs * EMB + lane * 4];
            float4 rd = *(const float4*)&g_T[(96 + zd) * EMB + lane * 4];
            float4 rt = *(const float4*)&g_T[(192 + st) * EMB + lane * 4];
            float4 te = *(const float4*)&g_T[(212 + eq) * EMB + lane * 4];
            float4 s;
            s.x = (rs.x + rd.x) + (rt.x + te.x);
            s.y = (rs.y + rd.y) + (rt.y + te.y);
            s.z = (rs.z + rd.z) + (rt.z + te.z);
            s.w = (rs.w + rd.w) + (rt.w + te.w);
            *(float4*)&Sum[r * SS + lane * 4] = s;
        }

        // ---- P3: GEMM 32x32 per warp, single-pass fp16 ----
        float d[2][4][4];
        #pragma unroll
        for (int mt = 0; mt < 2; mt++)
            #pragma unroll
            for (int jj = 0; jj < 4; jj++)
                d[mt][jj][0] = d[mt][jj][1] = d[mt][jj][2] = d[mt][jj][3] = 0.0f;

        {
            const uint32_t Au = A_u + m0 * SA + lmoff;
            const uint32_t Bu = B_u + wn * 64 + lmoff;
            #pragma unroll
            for (int ks = 0; ks < 8; ks++) {
                uint32_t a[8];
                ldsm4(a + 0, Au + ks * 32);
                ldsm4(a + 4, Au + 16 * SA + ks * 32);
                uint32_t b[8];
                ldsm4t(b + 0, Bu + ks * 16 * SA);
                ldsm4t(b + 4, Bu + ks * 16 * SA + 32);
                #pragma unroll
                for (int mt = 0; mt < 2; mt++)
                    #pragma unroll
                    for (int jj = 0; jj < 4; jj++)
                        mma_f16(d[mt][jj], a + mt * 4, b + 2 * jj);
            }
        }
        __syncthreads();

        // ---- P4: epilogue in-place into Sum ----
        #pragma unroll
        for (int mt = 0; mt < 2; mt++) {
            const int r1 = m0 + mt * 16 + (lane >> 2);
            float* S1 = &Sum[r1 * SS];
            float* S2 = &Sum[(r1 + 8) * SS];
            #pragma unroll
            for (int jj = 0; jj < 4; jj++) {
                const int c = wn * 32 + jj * 8 + (lane & 3) * 2;
                const float* dd = d[mt][jj];
                float2 s1 = *(float2*)&S1[c];
                s1.x = silu_f(dd[0] + s1.x);
                s1.y = silu_f(dd[1] + s1.y);
                *(float2*)&S1[c] = s1;
                float2 s2 = *(float2*)&S2[c];
                s2.x = silu_f(dd[2] + s2.x);
                s2.y = silu_f(dd[3] + s2.y);
                *(float2*)&S2[c] = s2;
            }
        }
        __syncthreads();

        // ---- P5: coalesced copy-out (8 rows/warp, 512B rows) ----
        #pragma unroll
        for (int i = 0; i < 8; i++) {
            const int r = wid * 8 + i;
            const int ge = ebase + r;
            if (ge < E) {
                float4 v = *(float4*)&Sum[r * SS + lane * 4];
                *(float4*)&out[(size_t)ge * EMB + lane * 4] = v;
            }
        }
        __syncthreads();
    }
}

// ---------------------------------------------------------------------------
extern "C" void kernel_launch(void* const* d_in, const int* in_sizes, int n_in,
                              void* d_out, int out_size)
{
    const int*   Z          = (const int*)d_in[0];
    const int*   stepA      = (const int*)d_in[1];
    const int*   src        = (const int*)d_in[2];
    const int*   dst        = (const int*)d_in[3];
    const int*   equiv      = (const int*)d_in[4];
    const float* rbf        = (const float*)d_in[5];
    const float* dvec       = (const float*)d_in[6];
    const float* emb_table  = (const float*)d_in[7];
    const float* step_table = (const float*)d_in[8];
    const float* equiv_tab  = (const float*)d_in[9];
    const float* W_rbf      = (const float*)d_in[10];
    const float* b_rbf      = (const float*)d_in[11];
    const float* W          = (const float*)d_in[12];
    const float* b          = (const float*)d_in[13];
    float* out = (float*)d_out;

    const int E = in_sizes[2];
    const int tiles = (E + TILE - 1) / TILE;

    static int sms = 0;
    if (sms == 0) {
        if (cudaDeviceGetAttribute(&sms, cudaDevAttrMultiProcessorCount, 0) != cudaSuccess || sms <= 0)
            sms = 148;
    }
    int grid = 2 * sms;
    if (grid > tiles) grid = tiles;

    cudaFuncSetAttribute(edge_kernel, cudaFuncAttributeMaxDynamicSharedMemorySize, SMEM_TOT);

    precompute_kernel<<<107, 256>>>(emb_table, step_table, equiv_tab, W, b);
    rbf_env_kernel<<<(E / 2 + 255) / 256, 256>>>(dvec, out + (size_t)E * EMB, E);
    edge_kernel<<<grid, THREADS, SMEM_TOT>>>(Z, stepA, src, dst, equiv,
                                             rbf, W_rbf, b_rbf,
                                             W + 2 * EMB * EMB, out, E, tiles);
}

// round 11
// speedup vs baseline: 2.2849x; 1.0202x over previous
#include <cuda_runtime.h>
#include <cuda_fp16.h>
#include <cstdint>

#define EMB 128
#define NR 6
#define SA 272          // A/B smem row stride in bytes (136 fp16)
#define SS 132          // Sum row stride in floats (528B = 33*16, float4-aligned)
#define RS 9            // rbf stage row stride in floats
#define TILE 96         // edges per tile
#define THREADS 384     // 12 warps, monolithic phases, 2 CTAs/SM

// smem offsets (bytes)
#define OFF_A    0        // 96*272           = 26112
#define OFF_B    26112    // 128*272          = 34816 -> 60928
#define OFF_SUM  60928    // 96*132*4         = 50688 -> 111616
#define OFF_RBFS OFF_SUM  // overlay: 96*9*4  = 3456 (dead before Sum written)
#define OFF_WR   111616   // 4*264*4          = 4224  -> 115840
#define OFF_IDX  115840   // 96*4             = 384   -> 116224
#define SMEM_TOT 116224   // x2 CTAs = 232448 <= 233472 (228KB)

// Precomputed table @ W_block projections in fp16: rows 0-95 Tsrc, 96-191 Tdst,
// 192-211 Tstep, 212-213 Teq (+bias folded into Teq rows). uint2 for 8B loads.
__device__ uint2 g_Th[214 * 32];

__device__ __forceinline__ uint32_t smem_u32(const void* p) {
    uint32_t a;
    asm("{ .reg .u64 t; cvta.to.shared.u64 t, %1; cvt.u32.u64 %0, t; }" : "=r"(a) : "l"(p));
    return a;
}
// silu(x) = 0.5x * (1 + tanh(x/2))
__device__ __forceinline__ float silu_f(float x) {
    float h = 0.5f * x, t;
    asm("tanh.approx.f32 %0, %1;" : "=f"(t) : "f"(h));
    return fmaf(h, t, h);
}
__device__ __forceinline__ void ldsm4(uint32_t* r, uint32_t addr) {
    asm volatile("ldmatrix.sync.aligned.m8n8.x4.shared.b16 {%0,%1,%2,%3}, [%4];"
                 : "=r"(r[0]), "=r"(r[1]), "=r"(r[2]), "=r"(r[3]) : "r"(addr));
}
__device__ __forceinline__ void ldsm4t(uint32_t* r, uint32_t addr) {
    asm volatile("ldmatrix.sync.aligned.m8n8.x4.trans.shared.b16 {%0,%1,%2,%3}, [%4];"
                 : "=r"(r[0]), "=r"(r[1]), "=r"(r[2]), "=r"(r[3]) : "r"(addr));
}
__device__ __forceinline__ void mma_f16(float* d, const uint32_t* a, const uint32_t* b) {
    asm volatile("mma.sync.aligned.m16n8k16.row.col.f32.f16.f16.f32 "
                 "{%0,%1,%2,%3}, {%4,%5,%6,%7}, {%8,%9}, {%0,%1,%2,%3};"
                 : "+f"(d[0]), "+f"(d[1]), "+f"(d[2]), "+f"(d[3])
                 : "r"(a[0]), "r"(a[1]), "r"(a[2]), "r"(a[3]), "r"(b[0]), "r"(b[1]));
}
// sum 4 fp16 table fragments (uint2 each = 4 halves) into float4
__device__ __forceinline__ float4 tsum4(uint2 u0, uint2 u1, uint2 u2, uint2 u3) {
    float2 a0 = __half22float2(*(__half2*)&u0.x), a1 = __half22float2(*(__half2*)&u0.y);
    float2 b0 = __half22float2(*(__half2*)&u1.x), b1 = __half22float2(*(__half2*)&u1.y);
    float2 c0 = __half22float2(*(__half2*)&u2.x), c1 = __half22float2(*(__half2*)&u2.y);
    float2 d0 = __half22float2(*(__half2*)&u3.x), d1 = __half22float2(*(__half2*)&u3.y);
    float4 s;
    s.x = (a0.x + b0.x) + (c0.x + d0.x);
    s.y = (a0.y + b0.y) + (c0.y + d0.y);
    s.z = (a1.x + b1.x) + (c1.x + d1.x);
    s.w = (a1.y + b1.y) + (c1.y + d1.y);
    return s;
}

// ---------------------------------------------------------------------------
// Kernel 1: g_Th = fp16(tables @ W_blocks) (bias folded into Teq rows).
// ---------------------------------------------------------------------------
__global__ void precompute_kernel(const float* __restrict__ emb_table,
                                  const float* __restrict__ step_table,
                                  const float* __restrict__ equiv_table,
                                  const float* __restrict__ W,
                                  const float* __restrict__ b)
{
    __shared__ float in[2][EMB];
    int r = blockIdx.x * 2 + (threadIdx.x >> 7);
    int c = threadIdx.x & 127;
    if (r >= 214) return;
    const float* srow; const float* Wb; bool addb = false;
    if (r < 96)       { srow = emb_table + r * EMB;           Wb = W; }
    else if (r < 192) { srow = emb_table + (r - 96) * EMB;    Wb = W + EMB * EMB; }
    else if (r < 212) { srow = step_table + (r - 192) * EMB;  Wb = W + 3 * EMB * EMB; }
    else              { srow = equiv_table + (r - 212) * EMB; Wb = W + 4 * EMB * EMB; addb = true; }
    in[threadIdx.x >> 7][c] = srow[c];
    __syncthreads();
    const float* inr = in[threadIdx.x >> 7];
    float a0 = 0, a1 = 0, a2 = 0, a3 = 0;
    #pragma unroll
    for (int k = 0; k < EMB; k += 4) {
        a0 = fmaf(inr[k + 0], Wb[(k + 0) * EMB + c], a0);
        a1 = fmaf(inr[k + 1], Wb[(k + 1) * EMB + c], a1);
        a2 = fmaf(inr[k + 2], Wb[(k + 2) * EMB + c], a2);
        a3 = fmaf(inr[k + 3], Wb[(k + 3) * EMB + c], a3);
    }
    float v = (a0 + a1) + (a2 + a3) + (addb ? b[c] : 0.0f);
    ((__half*)g_Th)[r * EMB + c] = __float2half(v);
}

// ---------------------------------------------------------------------------
// Kernel 2: persistent monolithic edge kernel, 2 CTAs/SM x 384 threads.
// 12 warps in a 3(m) x 4(n) grid, 32x32 output tile per warp, fp16 mma.sync.
// rbf_env folded into P1 (threads 192-287); fp16 table gathers.
// ---------------------------------------------------------------------------
__global__ __launch_bounds__(THREADS, 2)
void edge_kernel(const int* __restrict__ Z, const int* __restrict__ stepA,
                 const int* __restrict__ src, const int* __restrict__ dst,
                 const int* __restrict__ equiv,
                 const float* __restrict__ rbf, const float* __restrict__ dvec,
                 const float* __restrict__ W_rbf, const float* __restrict__ b_rbf,
                 const float* __restrict__ W2,
                 float* __restrict__ out, int E, int tiles)
{
    extern __shared__ char sm[];
    char*  const Asm  = sm + OFF_A;
    char*  const Bsm  = sm + OFF_B;
    float* const Sum  = (float*)(sm + OFF_SUM);
    float* const rbfs = (float*)(sm + OFF_RBFS);   // overlay, dead before Sum written
    float* const Wr   = (float*)(sm + OFF_WR);     // [4][264] (32k x 8 + pad per q)
    int*   const sidx = (int*)(sm + OFF_IDX);      // [96] packed

    const int tid  = threadIdx.x;
    const int wid  = tid >> 5;
    const int lane = tid & 31;

    // ---- one-time: W2^T -> fp16 smem; W_rbf -> banked smem blocks ----
    for (int idx = tid; idx < EMB * EMB; idx += THREADS) {
        int k = idx >> 7, n = idx & 127;
        *(__half*)(Bsm + k * SA + n * 2) = __float2half(W2[idx]);
    }
    for (int i = tid; i < 4 * 32 * 8; i += THREADS) {
        int q = i >> 8, kk = (i >> 3) & 31, j = i & 7;
        int k = 32 * q + kk;
        Wr[q * 264 + kk * 8 + j] = (j < 6) ? W_rbf[j * EMB + k] : (j == 6 ? b_rbf[k] : 0.0f);
    }
    __syncthreads();

    const int wm = wid >> 2;      // 0..2  (m-group of 32 edges)
    const int wn = wid & 3;       // 0..3  (n-group of 32 cols)
    const int m0 = wm * 32;
    const uint32_t lmoff = (uint32_t)((lane & 15) * SA + (lane >> 4) * 16);
    const uint32_t A_u = smem_u32(Asm);
    const uint32_t B_u = smem_u32(Bsm);
    // A-production mapping: e = tid % 96 (lanes contiguous), q = tid / 96
    const int pe = tid % TILE;
    const int pq = tid / TILE;    // 0..3, k-range [32q, 32q+32)
    // preload Teq rows (fp16)
    const uint2 te0u = g_Th[212 * 32 + lane];
    const uint2 te1u = g_Th[213 * 32 + lane];
    float* const envo = out + (size_t)E * EMB;

    for (int t = blockIdx.x; t < tiles; t += gridDim.x) {
        const int ebase = t * TILE;

        // ---- P1: indices (tid<96) + rbf stage (96..191) + rbf_env (192..287) ----
        if (tid < TILE) {
            const int ge = ebase + tid;
            int pk = 0;
            if (ge < E) {
                int s = src[ge], dd = dst[ge];
                pk = Z[s] | (Z[dd] << 7) | (stepA[s] << 14) | (equiv[ge] << 19);
            }
            sidx[tid] = pk;
        } else if (tid < 2 * TILE) {
            const int e = tid - TILE;
            const int ge = ebase + e;
            if (ge < E) {
                const float* rp = rbf + (size_t)ge * NR;
                float2 a = *(const float2*)(rp);
                float2 b = *(const float2*)(rp + 2);
                float2 c = *(const float2*)(rp + 4);
                float* rr = rbfs + e * RS;
                rr[0] = a.x; rr[1] = a.y; rr[2] = b.x;
                rr[3] = b.y; rr[4] = c.x; rr[5] = c.y;
            }
        } else if (tid < 3 * TILE) {
            const int e = tid - 2 * TILE;
            const int ge = ebase + e;
            if (ge < E) {
                float x = dvec[ge] * 0.2f;
                float inv = 1.0f / x;
                float x2 = x * x;
                float x5 = x2 * x2 * x;
                float env = inv + x5 * (-28.0f + x * (48.0f + x * (-21.0f)));
                float coef = env * inv;
                const float PI = 3.14159265358979323846f;
                float th = PI * x;
                float s1 = __sinf(th), c1 = __cosf(th);
                float twoc = 2.0f * c1;
                float sp = 0.0f, s = s1;
                float o[NR];
                #pragma unroll
                for (int j = 0; j < NR; j++) {
                    o[j] = coef * s;
                    float sn = twoc * s - sp;
                    sp = s; s = sn;
                }
                float* op = envo + (size_t)ge * NR;
                *(float2*)(op + 0) = make_float2(o[0], o[1]);
                *(float2*)(op + 2) = make_float2(o[2], o[3]);
                *(float2*)(op + 4) = make_float2(o[4], o[5]);
            }
        }
        __syncthreads();

        // ---- P2a: A = silu(rbf @ W_rbf + b) fp16; thread = (edge pe, k-quarter pq) ----
        {
            const float* rr = rbfs + pe * RS;
            float r0 = rr[0], r1 = rr[1], r2 = rr[2], r3 = rr[3], r4 = rr[4], r5 = rr[5];
            const float* wq = Wr + pq * 264;
            char* ah = Asm + pe * SA + pq * 64;
            #pragma unroll
            for (int g = 0; g < 4; g++) {
                uint32_t hb[4];
                #pragma unroll
                for (int pp = 0; pp < 4; pp++) {
                    const int kk = g * 8 + pp * 2;
                    float4 wa = *(const float4*)&wq[kk * 8];
                    float4 wb = *(const float4*)&wq[kk * 8 + 4];
                    float4 wc = *(const float4*)&wq[kk * 8 + 8];
                    float4 wd = *(const float4*)&wq[kk * 8 + 12];
                    float z0 = wb.z + r0 * wa.x + r1 * wa.y + r2 * wa.z + r3 * wa.w + r4 * wb.x + r5 * wb.y;
                    float z1 = wd.z + r0 * wc.x + r1 * wc.y + r2 * wc.z + r3 * wc.w + r4 * wd.x + r5 * wd.y;
                    float a0 = silu_f(z0);
                    float a1 = silu_f(z1);
                    asm("cvt.rn.f16x2.f32 %0, %1, %2;" : "=r"(hb[pp]) : "f"(a1), "f"(a0));
                }
                *(uint4*)(ah + g * 16) = make_uint4(hb[0], hb[1], hb[2], hb[3]);
            }
        }
        __syncthreads();

        // ---- P2b: fp16 table gathers (8 rows/warp; overlaps other warps' GEMM) ----
        #pragma unroll
        for (int i = 0; i < 8; i++) {
            const int r = wid * 8 + i;
            const uint32_t pk = (uint32_t)sidx[r];
            const int zs = pk & 127, zd = (pk >> 7) & 127;
            const int st = (pk >> 14) & 31, eq = (pk >> 19) & 1;
            uint2 u0 = g_Th[zs * 32 + lane];
            uint2 u1 = g_Th[(96 + zd) * 32 + lane];
            uint2 u2 = g_Th[(192 + st) * 32 + lane];
            uint2 u3 = eq ? te1u : te0u;
            *(float4*)&Sum[r * SS + lane * 4] = tsum4(u0, u1, u2, u3);
        }

        // ---- P3: GEMM 32x32 per warp, single-pass fp16 ----
        float d[2][4][4];
        #pragma unroll
        for (int mt = 0; mt < 2; mt++)
            #pragma unroll
            for (int jj = 0; jj < 4; jj++)
                d[mt][jj][0] = d[mt][jj][1] = d[mt][jj][2] = d[mt][jj][3] = 0.0f;

        {
            const uint32_t Au = A_u + m0 * SA + lmoff;
            const uint32_t Bu = B_u + wn * 64 + lmoff;
            #pragma unroll
            for (int ks = 0; ks < 8; ks++) {
                uint32_t a[8];
                ldsm4(a + 0, Au + ks * 32);
                ldsm4(a + 4, Au + 16 * SA + ks * 32);
                uint32_t b[8];
                ldsm4t(b + 0, Bu + ks * 16 * SA);
                ldsm4t(b + 4, Bu + ks * 16 * SA + 32);
                #pragma unroll
                for (int mt = 0; mt < 2; mt++)
                    #pragma unroll
                    for (int jj = 0; jj < 4; jj++)
                        mma_f16(d[mt][jj], a + mt * 4, b + 2 * jj);
            }
        }
        __syncthreads();

        // ---- P4: epilogue in-place into Sum ----
        #pragma unroll
        for (int mt = 0; mt < 2; mt++) {
            const int r1 = m0 + mt * 16 + (lane >> 2);
            float* S1 = &Sum[r1 * SS];
            float* S2 = &Sum[(r1 + 8) * SS];
            #pragma unroll
            for (int jj = 0; jj < 4; jj++) {
                const int c = wn * 32 + jj * 8 + (lane & 3) * 2;
                const float* dd = d[mt][jj];
                float2 s1 = *(float2*)&S1[c];
                s1.x = silu_f(dd[0] + s1.x);
                s1.y = silu_f(dd[1] + s1.y);
                *(float2*)&S1[c] = s1;
                float2 s2 = *(float2*)&S2[c];
                s2.x = silu_f(dd[2] + s2.x);
                s2.y = silu_f(dd[3] + s2.y);
                *(float2*)&S2[c] = s2;
            }
        }
        __syncthreads();

        // ---- P5: coalesced copy-out (8 rows/warp, 512B rows) ----
        #pragma unroll
        for (int i = 0; i < 8; i++) {
            const int r = wid * 8 + i;
            const int ge = ebase + r;
            if (ge < E) {
                float4 v = *(float4*)&Sum[r * SS + lane * 4];
                *(float4*)&out[(size_t)ge * EMB + lane * 4] = v;
            }
        }
        __syncthreads();
    }
}

// ---------------------------------------------------------------------------
extern "C" void kernel_launch(void* const* d_in, const int* in_sizes, int n_in,
                              void* d_out, int out_size)
{
    const int*   Z          = (const int*)d_in[0];
    const int*   stepA      = (const int*)d_in[1];
    const int*   src        = (const int*)d_in[2];
    const int*   dst        = (const int*)d_in[3];
    const int*   equiv      = (const int*)d_in[4];
    const float* rbf        = (const float*)d_in[5];
    const float* dvec       = (const float*)d_in[6];
    const float* emb_table  = (const float*)d_in[7];
    const float* step_table = (const float*)d_in[8];
    const float* equiv_tab  = (const float*)d_in[9];
    const float* W_rbf      = (const float*)d_in[10];
    const float* b_rbf      = (const float*)d_in[11];
    const float* W          = (const float*)d_in[12];
    const float* b          = (const float*)d_in[13];
    float* out = (float*)d_out;

    const int E = in_sizes[2];
    const int tiles = (E + TILE - 1) / TILE;

    static int sms = 0;
    if (sms == 0) {
        if (cudaDeviceGetAttribute(&sms, cudaDevAttrMultiProcessorCount, 0) != cudaSuccess || sms <= 0)
            sms = 148;
    }
    int grid = 2 * sms;
    if (grid > tiles) grid = tiles;

    cudaFuncSetAttribute(edge_kernel, cudaFuncAttributeMaxDynamicSharedMemorySize, SMEM_TOT);

    precompute_kernel<<<107, 256>>>(emb_table, step_table, equiv_tab, W, b);
    edge_kernel<<<grid, THREADS, SMEM_TOT>>>(Z, stepA, src, dst, equiv,
                                             rbf, dvec, W_rbf, b_rbf,
                                             W + 2 * EMB * EMB, out, E, tiles);
}

// round 12
// speedup vs baseline: 3.0812x; 1.3485x over previous
#include <cuda_runtime.h>
#include <cuda_fp16.h>
#include <cstdint>

#define EMB 128
#define NR 6
#define SA 272          // B smem row stride in bytes (136 fp16)
#define SS 132          // Sum row stride in floats (528B = 33*16, float4-aligned)
#define RS 9            // rbf stage row stride in floats
#define TILE 96         // edges per tile
#define THREADS 384     // 12 warps, monolithic phases, 2 CTAs/SM

// smem offsets (bytes)
#define OFF_A    0        // 96*256 swizzled   = 24576
#define OFF_B    24576    // 128*272           = 34816 -> 59392
#define OFF_SUM  59392    // 96*132*4          = 50688 -> 110080
#define OFF_RBFS OFF_SUM  // overlay: 96*9*4   = 3456 (dead before Sum written)
#define OFF_WR   110080   // 4*264*4           = 4224  -> 114304
#define OFF_IDX  114304   // 96*4              = 384   -> 114688
#define SMEM_TOT 114688   // (114688+1024r)*2 = 231424 <= 233472 (228KB)

// Precomputed table @ W_block projections in fp16: rows 0-95 Tsrc, 96-191 Tdst,
// 192-211 Tstep, 212-213 Teq (+bias folded into Teq rows). uint2 for 8B loads.
__device__ uint2 g_Th[214 * 32];

__device__ __forceinline__ uint32_t smem_u32(const void* p) {
    uint32_t a;
    asm("{ .reg .u64 t; cvta.to.shared.u64 t, %1; cvt.u32.u64 %0, t; }" : "=r"(a) : "l"(p));
    return a;
}
// silu(x) = 0.5x * (1 + tanh(x/2))
__device__ __forceinline__ float silu_f(float x) {
    float h = 0.5f * x, t;
    asm("tanh.approx.f32 %0, %1;" : "=f"(t) : "f"(h));
    return fmaf(h, t, h);
}
__device__ __forceinline__ void ldsm4(uint32_t* r, uint32_t addr) {
    asm volatile("ldmatrix.sync.aligned.m8n8.x4.shared.b16 {%0,%1,%2,%3}, [%4];"
                 : "=r"(r[0]), "=r"(r[1]), "=r"(r[2]), "=r"(r[3]) : "r"(addr));
}
__device__ __forceinline__ void ldsm4t(uint32_t* r, uint32_t addr) {
    asm volatile("ldmatrix.sync.aligned.m8n8.x4.trans.shared.b16 {%0,%1,%2,%3}, [%4];"
                 : "=r"(r[0]), "=r"(r[1]), "=r"(r[2]), "=r"(r[3]) : "r"(addr));
}
__device__ __forceinline__ void mma_f16(float* d, const uint32_t* a, const uint32_t* b) {
    asm volatile("mma.sync.aligned.m16n8k16.row.col.f32.f16.f16.f32 "
                 "{%0,%1,%2,%3}, {%4,%5,%6,%7}, {%8,%9}, {%0,%1,%2,%3};"
                 : "+f"(d[0]), "+f"(d[1]), "+f"(d[2]), "+f"(d[3])
                 : "r"(a[0]), "r"(a[1]), "r"(a[2]), "r"(a[3]), "r"(b[0]), "r"(b[1]));
}
// sum 4 fp16 table fragments (uint2 each = 4 halves) into float4
__device__ __forceinline__ float4 tsum4(uint2 u0, uint2 u1, uint2 u2, uint2 u3) {
    float2 a0 = __half22float2(*(__half2*)&u0.x), a1 = __half22float2(*(__half2*)&u0.y);
    float2 b0 = __half22float2(*(__half2*)&u1.x), b1 = __half22float2(*(__half2*)&u1.y);
    float2 c0 = __half22float2(*(__half2*)&u2.x), c1 = __half22float2(*(__half2*)&u2.y);
    float2 d0 = __half22float2(*(__half2*)&u3.x), d1 = __half22float2(*(__half2*)&u3.y);
    float4 s;
    s.x = (a0.x + b0.x) + (c0.x + d0.x);
    s.y = (a0.y + b0.y) + (c0.y + d0.y);
    s.z = (a1.x + b1.x) + (c1.x + d1.x);
    s.w = (a1.y + b1.y) + (c1.y + d1.y);
    return s;
}

// ---------------------------------------------------------------------------
// Kernel 1: g_Th = fp16(tables @ W_blocks) (bias folded into Teq rows).
// ---------------------------------------------------------------------------
__global__ void precompute_kernel(const float* __restrict__ emb_table,
                                  const float* __restrict__ step_table,
                                  const float* __restrict__ equiv_table,
                                  const float* __restrict__ W,
                                  const float* __restrict__ b)
{
    __shared__ float in[2][EMB];
    int r = blockIdx.x * 2 + (threadIdx.x >> 7);
    int c = threadIdx.x & 127;
    if (r >= 214) return;
    const float* srow; const float* Wb; bool addb = false;
    if (r < 96)       { srow = emb_table + r * EMB;           Wb = W; }
    else if (r < 192) { srow = emb_table + (r - 96) * EMB;    Wb = W + EMB * EMB; }
    else if (r < 212) { srow = step_table + (r - 192) * EMB;  Wb = W + 3 * EMB * EMB; }
    else              { srow = equiv_table + (r - 212) * EMB; Wb = W + 4 * EMB * EMB; addb = true; }
    in[threadIdx.x >> 7][c] = srow[c];
    __syncthreads();
    const float* inr = in[threadIdx.x >> 7];
    float a0 = 0, a1 = 0, a2 = 0, a3 = 0;
    #pragma unroll
    for (int k = 0; k < EMB; k += 4) {
        a0 = fmaf(inr[k + 0], Wb[(k + 0) * EMB + c], a0);
        a1 = fmaf(inr[k + 1], Wb[(k + 1) * EMB + c], a1);
        a2 = fmaf(inr[k + 2], Wb[(k + 2) * EMB + c], a2);
        a3 = fmaf(inr[k + 3], Wb[(k + 3) * EMB + c], a3);
    }
    float v = (a0 + a1) + (a2 + a3) + (addb ? b[c] : 0.0f);
    ((__half*)g_Th)[r * EMB + c] = __float2half(v);
}

// ---------------------------------------------------------------------------
// Kernel 2: persistent monolithic edge kernel, 2 CTAs/SM x 384 threads.
// 12 warps in a 3(m) x 4(n) grid, 32x32 output tile per warp, fp16 mma.sync.
// A tile: compact 256B stride, XOR-swizzled (chunk c of row r at (c^(r&7))*16).
// ---------------------------------------------------------------------------
__global__ __launch_bounds__(THREADS, 2)
void edge_kernel(const int* __restrict__ Z, const int* __restrict__ stepA,
                 const int* __restrict__ src, const int* __restrict__ dst,
                 const int* __restrict__ equiv,
                 const float* __restrict__ rbf, const float* __restrict__ dvec,
                 const float* __restrict__ W_rbf, const float* __restrict__ b_rbf,
                 const float* __restrict__ W2,
                 float* __restrict__ out, int E, int tiles)
{
    extern __shared__ char sm[];
    char*  const Asm  = sm + OFF_A;
    char*  const Bsm  = sm + OFF_B;
    float* const Sum  = (float*)(sm + OFF_SUM);
    float* const rbfs = (float*)(sm + OFF_RBFS);   // overlay, dead before Sum written
    float* const Wr   = (float*)(sm + OFF_WR);     // [4][264] (32k x 8 + pad per q)
    int*   const sidx = (int*)(sm + OFF_IDX);      // [96] packed

    const int tid  = threadIdx.x;
    const int wid  = tid >> 5;
    const int lane = tid & 31;

    // ---- one-time: W2^T -> fp16 smem; W_rbf -> banked smem blocks ----
    for (int idx = tid; idx < EMB * EMB; idx += THREADS) {
        int k = idx >> 7, n = idx & 127;
        *(__half*)(Bsm + k * SA + n * 2) = __float2half(W2[idx]);
    }
    for (int i = tid; i < 4 * 32 * 8; i += THREADS) {
        int q = i >> 8, kk = (i >> 3) & 31, j = i & 7;
        int k = 32 * q + kk;
        Wr[q * 264 + kk * 8 + j] = (j < 6) ? W_rbf[j * EMB + k] : (j == 6 ? b_rbf[k] : 0.0f);
    }
    __syncthreads();

    const int wm = wid >> 2;      // 0..2  (m-group of 32 edges)
    const int wn = wid & 3;       // 0..3  (n-group of 32 cols)
    const int m0 = wm * 32;
    const uint32_t lmoff = (uint32_t)((lane & 15) * SA + (lane >> 4) * 16);
    const uint32_t A_u = smem_u32(Asm);
    const uint32_t B_u = smem_u32(Bsm);
    // A swizzled read addressing: row = m0 + (lane&15); r3 = row&7 = lane&7
    const uint32_t r3   = (uint32_t)(lane & 7);
    const uint32_t hxa  = (uint32_t)(((lane >> 4) ^ (lane & 1)) * 16);
    const uint32_t r6x  = (r3 & 6) * 16;
    const uint32_t AuBase = A_u + (uint32_t)(m0 + (lane & 15)) * 256 + hxa;
    // A-production mapping: e = tid % 96 (lanes contiguous), q = tid / 96
    const int pe = tid % TILE;
    const int pq = tid / TILE;    // 0..3, k-range [32q, 32q+32)
    // preload Teq rows (fp16)
    const uint2 te0u = g_Th[212 * 32 + lane];
    const uint2 te1u = g_Th[213 * 32 + lane];
    float* const envo = out + (size_t)E * EMB;

    for (int t = blockIdx.x; t < tiles; t += gridDim.x) {
        const int ebase = t * TILE;

        // ---- P1: indices (tid<96) + rbf stage (96..191) + rbf_env (192..287) ----
        if (tid < TILE) {
            const int ge = ebase + tid;
            int pk = 0;
            if (ge < E) {
                int s = src[ge], dd = dst[ge];
                pk = Z[s] | (Z[dd] << 7) | (stepA[s] << 14) | (equiv[ge] << 19);
            }
            sidx[tid] = pk;
        } else if (tid < 2 * TILE) {
            const int e = tid - TILE;
            const int ge = ebase + e;
            if (ge < E) {
                const float* rp = rbf + (size_t)ge * NR;
                float2 a = *(const float2*)(rp);
                float2 b = *(const float2*)(rp + 2);
                float2 c = *(const float2*)(rp + 4);
                float* rr = rbfs + e * RS;
                rr[0] = a.x; rr[1] = a.y; rr[2] = b.x;
                rr[3] = b.y; rr[4] = c.x; rr[5] = c.y;
            }
        } else if (tid < 3 * TILE) {
            const int e = tid - 2 * TILE;
            const int ge = ebase + e;
            if (ge < E) {
                float x = dvec[ge] * 0.2f;
                float inv = 1.0f / x;
                float x2 = x * x;
                float x5 = x2 * x2 * x;
                float env = inv + x5 * (-28.0f + x * (48.0f + x * (-21.0f)));
                float coef = env * inv;
                const float PI = 3.14159265358979323846f;
                float th = PI * x;
                float s1 = __sinf(th), c1 = __cosf(th);
                float twoc = 2.0f * c1;
                float sp = 0.0f, s = s1;
                float o[NR];
                #pragma unroll
                for (int j = 0; j < NR; j++) {
                    o[j] = coef * s;
                    float sn = twoc * s - sp;
                    sp = s; s = sn;
                }
                float* op = envo + (size_t)ge * NR;
                *(float2*)(op + 0) = make_float2(o[0], o[1]);
                *(float2*)(op + 2) = make_float2(o[2], o[3]);
                *(float2*)(op + 4) = make_float2(o[4], o[5]);
            }
        }
        __syncthreads();

        // ---- P2a: A = silu(rbf @ W_rbf + b) fp16, swizzled store ----
        {
            const float* rr = rbfs + pe * RS;
            float r0 = rr[0], r1 = rr[1], r2 = rr[2], r3v = rr[3], r4 = rr[4], r5 = rr[5];
            const float* wq = Wr + pq * 264;
            char* ah = Asm + pe * 256;
            const int sw = pe & 7;
            #pragma unroll
            for (int g = 0; g < 4; g++) {
                uint32_t hb[4];
                #pragma unroll
                for (int pp = 0; pp < 4; pp++) {
                    const int kk = g * 8 + pp * 2;
                    float4 wa = *(const float4*)&wq[kk * 8];
                    float4 wb = *(const float4*)&wq[kk * 8 + 4];
                    float4 wc = *(const float4*)&wq[kk * 8 + 8];
                    float4 wd = *(const float4*)&wq[kk * 8 + 12];
                    float z0 = wb.z + r0 * wa.x + r1 * wa.y + r2 * wa.z + r3v * wa.w + r4 * wb.x + r5 * wb.y;
                    float z1 = wd.z + r0 * wc.x + r1 * wc.y + r2 * wc.z + r3v * wc.w + r4 * wd.x + r5 * wd.y;
                    float a0 = silu_f(z0);
                    float a1 = silu_f(z1);
                    asm("cvt.rn.f16x2.f32 %0, %1, %2;" : "=r"(hb[pp]) : "f"(a1), "f"(a0));
                }
                const uint32_t off = (uint32_t)(((pq * 4 + g) ^ sw) * 16);
                *(uint4*)(ah + off) = make_uint4(hb[0], hb[1], hb[2], hb[3]);
            }
        }
        __syncthreads();

        // ---- P2b: fp16 table gathers (8 rows/warp; overlaps other warps' GEMM) ----
        #pragma unroll
        for (int i = 0; i < 8; i++) {
            const int r = wid * 8 + i;
            const uint32_t pk = (uint32_t)sidx[r];
            const int zs = pk & 127, zd = (pk >> 7) & 127;
            const int st = (pk >> 14) & 31, eq = (pk >> 19) & 1;
            uint2 u0 = g_Th[zs * 32 + lane];
            uint2 u1 = g_Th[(96 + zd) * 32 + lane];
            uint2 u2 = g_Th[(192 + st) * 32 + lane];
            uint2 u3 = eq ? te1u : te0u;
            *(float4*)&Sum[r * SS + lane * 4] = tsum4(u0, u1, u2, u3);
        }

        // ---- P3: GEMM 32x32 per warp, single-pass fp16, swizzled A reads ----
        float d[2][4][4];
        #pragma unroll
        for (int mt = 0; mt < 2; mt++)
            #pragma unroll
            for (int jj = 0; jj < 4; jj++)
                d[mt][jj][0] = d[mt][jj][1] = d[mt][jj][2] = d[mt][jj][3] = 0.0f;

        {
            const uint32_t Bu = B_u + wn * 64 + lmoff;
            #pragma unroll
            for (int ks = 0; ks < 8; ks++) {
                const uint32_t aoff = ((uint32_t)(ks * 32)) ^ r6x;
                uint32_t a[8];
                ldsm4(a + 0, AuBase + aoff);
                ldsm4(a + 4, AuBase + 4096 + aoff);
                uint32_t b[8];
                ldsm4t(b + 0, Bu + ks * 16 * SA);
                ldsm4t(b + 4, Bu + ks * 16 * SA + 32);
                #pragma unroll
                for (int mt = 0; mt < 2; mt++)
                    #pragma unroll
                    for (int jj = 0; jj < 4; jj++)
                        mma_f16(d[mt][jj], a + mt * 4, b + 2 * jj);
            }
        }
        __syncthreads();

        // ---- P4: epilogue in-place into Sum ----
        #pragma unroll
        for (int mt = 0; mt < 2; mt++) {
            const int r1 = m0 + mt * 16 + (lane >> 2);
            float* S1 = &Sum[r1 * SS];
            float* S2 = &Sum[(r1 + 8) * SS];
            #pragma unroll
            for (int jj = 0; jj < 4; jj++) {
                const int c = wn * 32 + jj * 8 + (lane & 3) * 2;
                const float* dd = d[mt][jj];
                float2 s1 = *(float2*)&S1[c];
                s1.x = silu_f(dd[0] + s1.x);
                s1.y = silu_f(dd[1] + s1.y);
                *(float2*)&S1[c] = s1;
                float2 s2 = *(float2*)&S2[c];
                s2.x = silu_f(dd[2] + s2.x);
                s2.y = silu_f(dd[3] + s2.y);
                *(float2*)&S2[c] = s2;
            }
        }
        __syncthreads();

        // ---- P5: coalesced copy-out (8 rows/warp, 512B rows) ----
        #pragma unroll
        for (int i = 0; i < 8; i++) {
            const int r = wid * 8 + i;
            const int ge = ebase + r;
            if (ge < E) {
                float4 v = *(float4*)&Sum[r * SS + lane * 4];
                *(float4*)&out[(size_t)ge * EMB + lane * 4] = v;
            }
        }
        __syncthreads();
    }
}

// ---------------------------------------------------------------------------
extern "C" void kernel_launch(void* const* d_in, const int* in_sizes, int n_in,
                              void* d_out, int out_size)
{
    const int*   Z          = (const int*)d_in[0];
    const int*   stepA      = (const int*)d_in[1];
    const int*   src        = (const int*)d_in[2];
    const int*   dst        = (const int*)d_in[3];
    const int*   equiv      = (const int*)d_in[4];
    const float* rbf        = (const float*)d_in[5];
    const float* dvec       = (const float*)d_in[6];
    const float* emb_table  = (const float*)d_in[7];
    const float* step_table = (const float*)d_in[8];
    const float* equiv_tab  = (const float*)d_in[9];
    const float* W_rbf      = (const float*)d_in[10];
    const float* b_rbf      = (const float*)d_in[11];
    const float* W          = (const float*)d_in[12];
    const float* b          = (const float*)d_in[13];
    float* out = (float*)d_out;

    const int E = in_sizes[2];
    const int tiles = (E + TILE - 1) / TILE;

    static int sms = 0;
    if (sms == 0) {
        if (cudaDeviceGetAttribute(&sms, cudaDevAttrMultiProcessorCount, 0) != cudaSuccess || sms <= 0)
            sms = 148;
    }
    int grid = 2 * sms;
    if (grid > tiles) grid = tiles;

    cudaFuncSetAttribute(edge_kernel, cudaFuncAttributeMaxDynamicSharedMemorySize, SMEM_TOT);

    precompute_kernel<<<107, 256>>>(emb_table, step_table, equiv_tab, W, b);
    edge_kernel<<<grid, THREADS, SMEM_TOT>>>(Z, stepA, src, dst, equiv,
                                             rbf, dvec, W_rbf, b_rbf,
                                             W + 2 * EMB * EMB, out, E, tiles);
}

// round 13
// speedup vs baseline: 3.4286x; 1.1127x over previous
#include <cuda_runtime.h>
#include <cuda_fp16.h>
#include <cstdint>

#define EMB 128
#define NR 6
#define SA 272          // B smem row stride in bytes (136 fp16)
#define SH 136          // Sum_h row stride in halves (272B, conflict-free)
#define RS 9            // rbf stage row stride in floats
#define TILE 96         // edges per tile
#define THREADS 384     // 12 warps, monolithic phases, 2 CTAs/SM

// smem offsets (bytes)
#define OFF_A    0        // 96*256 swizzled   = 24576
#define OFF_B    24576    // 128*272           = 34816 -> 59392
#define OFF_SUM  59392    // 96*272 (fp16)     = 26112 -> 85504
#define OFF_RBFS OFF_SUM  // overlay: 96*9*4   = 3456 (dead before Sum written)
#define OFF_WR   85504    // 4*264*4           = 4224  -> 89728
#define OFF_IDX  89728    // 96*4              = 384   -> 90112
#define SMEM_TOT 90112    // (90112+1024r)*2 = 182272 <= 233472; ~45KB L1D left

// Precomputed table @ W_block projections in fp16: rows 0-95 Tsrc, 96-191 Tdst,
// 192-211 Tstep, 212-213 Teq (+bias folded into Teq rows). uint2 for 8B loads.
__device__ uint2 g_Th[214 * 32];

__device__ __forceinline__ uint32_t smem_u32(const void* p) {
    uint32_t a;
    asm("{ .reg .u64 t; cvta.to.shared.u64 t, %1; cvt.u32.u64 %0, t; }" : "=r"(a) : "l"(p));
    return a;
}
// silu(x) = 0.5x * (1 + tanh(x/2))
__device__ __forceinline__ float silu_f(float x) {
    float h = 0.5f * x, t;
    asm("tanh.approx.f32 %0, %1;" : "=f"(t) : "f"(h));
    return fmaf(h, t, h);
}
__device__ __forceinline__ void ldsm4(uint32_t* r, uint32_t addr) {
    asm volatile("ldmatrix.sync.aligned.m8n8.x4.shared.b16 {%0,%1,%2,%3}, [%4];"
                 : "=r"(r[0]), "=r"(r[1]), "=r"(r[2]), "=r"(r[3]) : "r"(addr));
}
__device__ __forceinline__ void ldsm4t(uint32_t* r, uint32_t addr) {
    asm volatile("ldmatrix.sync.aligned.m8n8.x4.trans.shared.b16 {%0,%1,%2,%3}, [%4];"
                 : "=r"(r[0]), "=r"(r[1]), "=r"(r[2]), "=r"(r[3]) : "r"(addr));
}
__device__ __forceinline__ void mma_f16(float* d, const uint32_t* a, const uint32_t* b) {
    asm volatile("mma.sync.aligned.m16n8k16.row.col.f32.f16.f16.f32 "
                 "{%0,%1,%2,%3}, {%4,%5,%6,%7}, {%8,%9}, {%0,%1,%2,%3};"
                 : "+f"(d[0]), "+f"(d[1]), "+f"(d[2]), "+f"(d[3])
                 : "r"(a[0]), "r"(a[1]), "r"(a[2]), "r"(a[3]), "r"(b[0]), "r"(b[1]));
}
// sum 4 fp16 table fragments (uint2 each = 4 halves) into float4
__device__ __forceinline__ float4 tsum4(uint2 u0, uint2 u1, uint2 u2, uint2 u3) {
    float2 a0 = __half22float2(*(__half2*)&u0.x), a1 = __half22float2(*(__half2*)&u0.y);
    float2 b0 = __half22float2(*(__half2*)&u1.x), b1 = __half22float2(*(__half2*)&u1.y);
    float2 c0 = __half22float2(*(__half2*)&u2.x), c1 = __half22float2(*(__half2*)&u2.y);
    float2 d0 = __half22float2(*(__half2*)&u3.x), d1 = __half22float2(*(__half2*)&u3.y);
    float4 s;
    s.x = (a0.x + b0.x) + (c0.x + d0.x);
    s.y = (a0.y + b0.y) + (c0.y + d0.y);
    s.z = (a1.x + b1.x) + (c1.x + d1.x);
    s.w = (a1.y + b1.y) + (c1.y + d1.y);
    return s;
}

// ---------------------------------------------------------------------------
// Kernel 1: g_Th = fp16(tables @ W_blocks) (bias folded into Teq rows).
// ---------------------------------------------------------------------------
__global__ void precompute_kernel(const float* __restrict__ emb_table,
                                  const float* __restrict__ step_table,
                                  const float* __restrict__ equiv_table,
                                  const float* __restrict__ W,
                                  const float* __restrict__ b)
{
    __shared__ float in[2][EMB];
    int r = blockIdx.x * 2 + (threadIdx.x >> 7);
    int c = threadIdx.x & 127;
    if (r >= 214) return;
    const float* srow; const float* Wb; bool addb = false;
    if (r < 96)       { srow = emb_table + r * EMB;           Wb = W; }
    else if (r < 192) { srow = emb_table + (r - 96) * EMB;    Wb = W + EMB * EMB; }
    else if (r < 212) { srow = step_table + (r - 192) * EMB;  Wb = W + 3 * EMB * EMB; }
    else              { srow = equiv_table + (r - 212) * EMB; Wb = W + 4 * EMB * EMB; addb = true; }
    in[threadIdx.x >> 7][c] = srow[c];
    __syncthreads();
    const float* inr = in[threadIdx.x >> 7];
    float a0 = 0, a1 = 0, a2 = 0, a3 = 0;
    #pragma unroll
    for (int k = 0; k < EMB; k += 4) {
        a0 = fmaf(inr[k + 0], Wb[(k + 0) * EMB + c], a0);
        a1 = fmaf(inr[k + 1], Wb[(k + 1) * EMB + c], a1);
        a2 = fmaf(inr[k + 2], Wb[(k + 2) * EMB + c], a2);
        a3 = fmaf(inr[k + 3], Wb[(k + 3) * EMB + c], a3);
    }
    float v = (a0 + a1) + (a2 + a3) + (addb ? b[c] : 0.0f);
    ((__half*)g_Th)[r * EMB + c] = __float2half(v);
}

// ---------------------------------------------------------------------------
// Kernel 2: persistent monolithic edge kernel, 2 CTAs/SM x 384 threads.
// 12 warps in a 3(m) x 4(n) grid, 32x32 output tile per warp, fp16 mma.sync.
// A tile: compact 256B stride, XOR-swizzled. Sum staged in fp16 (half2).
// ---------------------------------------------------------------------------
__global__ __launch_bounds__(THREADS, 2)
void edge_kernel(const int* __restrict__ Z, const int* __restrict__ stepA,
                 const int* __restrict__ src, const int* __restrict__ dst,
                 const int* __restrict__ equiv,
                 const float* __restrict__ rbf, const float* __restrict__ dvec,
                 const float* __restrict__ W_rbf, const float* __restrict__ b_rbf,
                 const float* __restrict__ W2,
                 float* __restrict__ out, int E, int tiles)
{
    extern __shared__ char sm[];
    char*   const Asm  = sm + OFF_A;
    char*   const Bsm  = sm + OFF_B;
    __half* const Sumh = (__half*)(sm + OFF_SUM);
    float*  const rbfs = (float*)(sm + OFF_RBFS);   // overlay, dead before Sum written
    float*  const Wr   = (float*)(sm + OFF_WR);     // [4][264] (32k x 8 + pad per q)
    int*    const sidx = (int*)(sm + OFF_IDX);      // [96] packed

    const int tid  = threadIdx.x;
    const int wid  = tid >> 5;
    const int lane = tid & 31;

    // ---- one-time: W2^T -> fp16 smem; W_rbf -> banked smem blocks ----
    for (int idx = tid; idx < EMB * EMB; idx += THREADS) {
        int k = idx >> 7, n = idx & 127;
        *(__half*)(Bsm + k * SA + n * 2) = __float2half(W2[idx]);
    }
    for (int i = tid; i < 4 * 32 * 8; i += THREADS) {
        int q = i >> 8, kk = (i >> 3) & 31, j = i & 7;
        int k = 32 * q + kk;
        Wr[q * 264 + kk * 8 + j] = (j < 6) ? W_rbf[j * EMB + k] : (j == 6 ? b_rbf[k] : 0.0f);
    }
    __syncthreads();

    const int wm = wid >> 2;      // 0..2  (m-group of 32 edges)
    const int wn = wid & 3;       // 0..3  (n-group of 32 cols)
    const int m0 = wm * 32;
    const uint32_t lmoff = (uint32_t)((lane & 15) * SA + (lane >> 4) * 16);
    const uint32_t A_u = smem_u32(Asm);
    const uint32_t B_u = smem_u32(Bsm);
    // A swizzled read addressing: row = m0 + (lane&15); r3 = row&7 = lane&7
    const uint32_t r3   = (uint32_t)(lane & 7);
    const uint32_t hxa  = (uint32_t)(((lane >> 4) ^ (lane & 1)) * 16);
    const uint32_t r6x  = (r3 & 6) * 16;
    const uint32_t AuBase = A_u + (uint32_t)(m0 + (lane & 15)) * 256 + hxa;
    // A-production mapping: e = tid % 96 (lanes contiguous), q = tid / 96
    const int pe = tid % TILE;
    const int pq = tid / TILE;    // 0..3, k-range [32q, 32q+32)
    // preload Teq rows (fp16)
    const uint2 te0u = g_Th[212 * 32 + lane];
    const uint2 te1u = g_Th[213 * 32 + lane];
    float* const envo = out + (size_t)E * EMB;

    for (int t = blockIdx.x; t < tiles; t += gridDim.x) {
        const int ebase = t * TILE;

        // ---- P1: indices (tid<96) + rbf stage (96..191) + rbf_env (192..287) ----
        if (tid < TILE) {
            const int ge = ebase + tid;
            int pk = 0;
            if (ge < E) {
                int s = src[ge], dd = dst[ge];
                pk = Z[s] | (Z[dd] << 7) | (stepA[s] << 14) | (equiv[ge] << 19);
            }
            sidx[tid] = pk;
        } else if (tid < 2 * TILE) {
            const int e = tid - TILE;
            const int ge = ebase + e;
            if (ge < E) {
                const float* rp = rbf + (size_t)ge * NR;
                float2 a = *(const float2*)(rp);
                float2 b = *(const float2*)(rp + 2);
                float2 c = *(const float2*)(rp + 4);
                float* rr = rbfs + e * RS;
                rr[0] = a.x; rr[1] = a.y; rr[2] = b.x;
                rr[3] = b.y; rr[4] = c.x; rr[5] = c.y;
            }
        } else if (tid < 3 * TILE) {
            const int e = tid - 2 * TILE;
            const int ge = ebase + e;
            if (ge < E) {
                float x = dvec[ge] * 0.2f;
                float inv = 1.0f / x;
                float x2 = x * x;
                float x5 = x2 * x2 * x;
                float env = inv + x5 * (-28.0f + x * (48.0f + x * (-21.0f)));
                float coef = env * inv;
                const float PI = 3.14159265358979323846f;
                float th = PI * x;
                float s1 = __sinf(th), c1 = __cosf(th);
                float twoc = 2.0f * c1;
                float sp = 0.0f, s = s1;
                float o[NR];
                #pragma unroll
                for (int j = 0; j < NR; j++) {
                    o[j] = coef * s;
                    float sn = twoc * s - sp;
                    sp = s; s = sn;
                }
                float* op = envo + (size_t)ge * NR;
                *(float2*)(op + 0) = make_float2(o[0], o[1]);
                *(float2*)(op + 2) = make_float2(o[2], o[3]);
                *(float2*)(op + 4) = make_float2(o[4], o[5]);
            }
        }
        __syncthreads();

        // ---- P2a: A = silu(rbf @ W_rbf + b) fp16, swizzled store ----
        {
            const float* rr = rbfs + pe * RS;
            float r0 = rr[0], r1 = rr[1], r2 = rr[2], r3v = rr[3], r4 = rr[4], r5 = rr[5];
            const float* wq = Wr + pq * 264;
            char* ah = Asm + pe * 256;
            const int sw = pe & 7;
            #pragma unroll
            for (int g = 0; g < 4; g++) {
                uint32_t hb[4];
                #pragma unroll
                for (int pp = 0; pp < 4; pp++) {
                    const int kk = g * 8 + pp * 2;
                    float4 wa = *(const float4*)&wq[kk * 8];
                    float4 wb = *(const float4*)&wq[kk * 8 + 4];
                    float4 wc = *(const float4*)&wq[kk * 8 + 8];
                    float4 wd = *(const float4*)&wq[kk * 8 + 12];
                    float z0 = wb.z + r0 * wa.x + r1 * wa.y + r2 * wa.z + r3v * wa.w + r4 * wb.x + r5 * wb.y;
                    float z1 = wd.z + r0 * wc.x + r1 * wc.y + r2 * wc.z + r3v * wc.w + r4 * wd.x + r5 * wd.y;
                    float a0 = silu_f(z0);
                    float a1 = silu_f(z1);
                    asm("cvt.rn.f16x2.f32 %0, %1, %2;" : "=r"(hb[pp]) : "f"(a1), "f"(a0));
                }
                const uint32_t off = (uint32_t)(((pq * 4 + g) ^ sw) * 16);
                *(uint4*)(ah + off) = make_uint4(hb[0], hb[1], hb[2], hb[3]);
            }
        }
        __syncthreads();

        // ---- P2b: fp16 table gathers -> fp16 Sum (8 rows/warp) ----
        #pragma unroll
        for (int i = 0; i < 8; i++) {
            const int r = wid * 8 + i;
            const uint32_t pk = (uint32_t)sidx[r];
            const int zs = pk & 127, zd = (pk >> 7) & 127;
            const int st = (pk >> 14) & 31, eq = (pk >> 19) & 1;
            uint2 u0 = g_Th[zs * 32 + lane];
            uint2 u1 = g_Th[(96 + zd) * 32 + lane];
            uint2 u2 = g_Th[(192 + st) * 32 + lane];
            uint2 u3 = eq ? te1u : te0u;
            float4 s = tsum4(u0, u1, u2, u3);
            uint2 o;
            asm("cvt.rn.f16x2.f32 %0, %1, %2;" : "=r"(o.x) : "f"(s.y), "f"(s.x));
            asm("cvt.rn.f16x2.f32 %0, %1, %2;" : "=r"(o.y) : "f"(s.w), "f"(s.z));
            *(uint2*)&Sumh[r * SH + lane * 4] = o;
        }

        // ---- P3: GEMM 32x32 per warp, single-pass fp16, swizzled A reads ----
        float d[2][4][4];
        #pragma unroll
        for (int mt = 0; mt < 2; mt++)
            #pragma unroll
            for (int jj = 0; jj < 4; jj++)
                d[mt][jj][0] = d[mt][jj][1] = d[mt][jj][2] = d[mt][jj][3] = 0.0f;

        {
            const uint32_t Bu = B_u + wn * 64 + lmoff;
            #pragma unroll
            for (int ks = 0; ks < 8; ks++) {
                const uint32_t aoff = ((uint32_t)(ks * 32)) ^ r6x;
                uint32_t a[8];
                ldsm4(a + 0, AuBase + aoff);
                ldsm4(a + 4, AuBase + 4096 + aoff);
                uint32_t b[8];
                ldsm4t(b + 0, Bu + ks * 16 * SA);
                ldsm4t(b + 4, Bu + ks * 16 * SA + 32);
                #pragma unroll
                for (int mt = 0; mt < 2; mt++)
                    #pragma unroll
                    for (int jj = 0; jj < 4; jj++)
                        mma_f16(d[mt][jj], a + mt * 4, b + 2 * jj);
            }
        }
        __syncthreads();

        // ---- P4: epilogue in-place into fp16 Sum ----
        #pragma unroll
        for (int mt = 0; mt < 2; mt++) {
            const int r1 = m0 + mt * 16 + (lane >> 2);
            __half* S1 = Sumh + r1 * SH;
            __half* S2 = Sumh + (r1 + 8) * SH;
            #pragma unroll
            for (int jj = 0; jj < 4; jj++) {
                const int c = wn * 32 + jj * 8 + (lane & 3) * 2;
                const float* dd = d[mt][jj];
                float2 f1 = __half22float2(*(__half2*)&S1[c]);
                f1.x = silu_f(dd[0] + f1.x);
                f1.y = silu_f(dd[1] + f1.y);
                *(__half2*)&S1[c] = __float22half2_rn(f1);
                float2 f2 = __half22float2(*(__half2*)&S2[c]);
                f2.x = silu_f(dd[2] + f2.x);
                f2.y = silu_f(dd[3] + f2.y);
                *(__half2*)&S2[c] = __float22half2_rn(f2);
            }
        }
        __syncthreads();

        // ---- P5: convert + coalesced copy-out (8 rows/warp) ----
        #pragma unroll
        for (int i = 0; i < 8; i++) {
            const int r = wid * 8 + i;
            const int ge = ebase + r;
            if (ge < E) {
                uint2 u = *(uint2*)&Sumh[r * SH + lane * 4];
                float2 a = __half22float2(*(__half2*)&u.x);
                float2 b = __half22float2(*(__half2*)&u.y);
                *(float4*)&out[(size_t)ge * EMB + lane * 4] = make_float4(a.x, a.y, b.x, b.y);
            }
        }
        __syncthreads();
    }
}

// ---------------------------------------------------------------------------
extern "C" void kernel_launch(void* const* d_in, const int* in_sizes, int n_in,
                              void* d_out, int out_size)
{
    const int*   Z          = (const int*)d_in[0];
    const int*   stepA      = (const int*)d_in[1];
    const int*   src        = (const int*)d_in[2];
    const int*   dst        = (const int*)d_in[3];
    const int*   equiv      = (const int*)d_in[4];
    const float* rbf        = (const float*)d_in[5];
    const float* dvec       = (const float*)d_in[6];
    const float* emb_table  = (const float*)d_in[7];
    const float* step_table = (const float*)d_in[8];
    const float* equiv_tab  = (const float*)d_in[9];
    const float* W_rbf      = (const float*)d_in[10];
    const float* b_rbf      = (const float*)d_in[11];
    const float* W          = (const float*)d_in[12];
    const float* b          = (const float*)d_in[13];
    float* out = (float*)d_out;

    const int E = in_sizes[2];
    const int tiles = (E + TILE - 1) / TILE;

    static int sms = 0;
    if (sms == 0) {
        if (cudaDeviceGetAttribute(&sms, cudaDevAttrMultiProcessorCount, 0) != cudaSuccess || sms <= 0)
            sms = 148;
    }
    int grid = 2 * sms;
    if (grid > tiles) grid = tiles;

    cudaFuncSetAttribute(edge_kernel, cudaFuncAttributeMaxDynamicSharedMemorySize, SMEM_TOT);

    precompute_kernel<<<107, 256>>>(emb_table, step_table, equiv_tab, W, b);
    edge_kernel<<<grid, THREADS, SMEM_TOT>>>(Z, stepA, src, dst, equiv,
                                             rbf, dvec, W_rbf, b_rbf,
                                             W + 2 * EMB * EMB, out, E, tiles);
}

// round 14
// speedup vs baseline: 3.5428x; 1.0333x over previous
#include <cuda_runtime.h>
#include <cuda_fp16.h>
#include <cstdint>

#define EMB 128
#define NR 6
#define SA 272          // B smem row stride in bytes (136 fp16)
#define SH 136          // Sum_h row stride in halves (272B, conflict-free)
#define RS 9            // rbf stage row stride in floats
#define TILE 96         // edges per tile
#define THREADS 384     // 12 warps, monolithic phases, 2 CTAs/SM

// smem offsets (bytes)
#define OFF_A    0        // 96*256 swizzled   = 24576
#define OFF_B    24576    // 128*272           = 34816 -> 59392
#define OFF_SUM  59392    // 96*272 (fp16)     = 26112 -> 85504
#define OFF_RBFS OFF_SUM  // overlay: 96*9*4   = 3456 (dead before Sum written)
#define OFF_WR   85504    // 4*264*4           = 4224  -> 89728
#define OFF_IDX  89728    // 2 x 96*4          = 768   -> 90496
#define SMEM_TOT 90496    // (90496+1024r)*2 = 183040 <= 233472; ~45KB L1D left

// Precomputed table @ W_block projections in fp16: rows 0-95 Tsrc, 96-191 Tdst,
// 192-211 Tstep, 212-213 Teq (+bias folded into Teq rows). uint2 for 8B loads.
__device__ uint2 g_Th[214 * 32];

__device__ __forceinline__ uint32_t smem_u32(const void* p) {
    uint32_t a;
    asm("{ .reg .u64 t; cvta.to.shared.u64 t, %1; cvt.u32.u64 %0, t; }" : "=r"(a) : "l"(p));
    return a;
}
// silu(x) = 0.5x * (1 + tanh(x/2))  (fp32, for A production)
__device__ __forceinline__ float silu_f(float x) {
    float h = 0.5f * x, t;
    asm("tanh.approx.f32 %0, %1;" : "=f"(t) : "f"(h));
    return fmaf(h, t, h);
}
__device__ __forceinline__ uint32_t hadd2(uint32_t a, uint32_t b) {
    uint32_t r;
    asm("add.f16x2 %0, %1, %2;" : "=r"(r) : "r"(a), "r"(b));
    return r;
}
// packed fp16x2 silu: h = 0.5x; t = tanh(h); r = h*t + h
__device__ __forceinline__ uint32_t silu_h2(uint32_t x) {
    uint32_t h, t, r;
    asm("mul.f16x2 %0, %1, %2;" : "=r"(h) : "r"(x), "r"(0x38003800u));
    asm("tanh.approx.f16x2 %0, %1;" : "=r"(t) : "r"(h));
    asm("fma.rn.f16x2 %0, %1, %2, %1;" : "=r"(r) : "r"(h), "r"(t));
    return r;
}
__device__ __forceinline__ void ldsm4(uint32_t* r, uint32_t addr) {
    asm volatile("ldmatrix.sync.aligned.m8n8.x4.shared.b16 {%0,%1,%2,%3}, [%4];"
                 : "=r"(r[0]), "=r"(r[1]), "=r"(r[2]), "=r"(r[3]) : "r"(addr));
}
__device__ __forceinline__ void ldsm4t(uint32_t* r, uint32_t addr) {
    asm volatile("ldmatrix.sync.aligned.m8n8.x4.trans.shared.b16 {%0,%1,%2,%3}, [%4];"
                 : "=r"(r[0]), "=r"(r[1]), "=r"(r[2]), "=r"(r[3]) : "r"(addr));
}
__device__ __forceinline__ void mma_f16(float* d, const uint32_t* a, const uint32_t* b) {
    asm volatile("mma.sync.aligned.m16n8k16.row.col.f32.f16.f16.f32 "
                 "{%0,%1,%2,%3}, {%4,%5,%6,%7}, {%8,%9}, {%0,%1,%2,%3};"
                 : "+f"(d[0]), "+f"(d[1]), "+f"(d[2]), "+f"(d[3])
                 : "r"(a[0]), "r"(a[1]), "r"(a[2]), "r"(a[3]), "r"(b[0]), "r"(b[1]));
}

// ---------------------------------------------------------------------------
// Kernel 1: g_Th = fp16(tables @ W_blocks) (bias folded into Teq rows).
// ---------------------------------------------------------------------------
__global__ void precompute_kernel(const float* __restrict__ emb_table,
                                  const float* __restrict__ step_table,
                                  const float* __restrict__ equiv_table,
                                  const float* __restrict__ W,
                                  const float* __restrict__ b)
{
    __shared__ float in[2][EMB];
    int r = blockIdx.x * 2 + (threadIdx.x >> 7);
    int c = threadIdx.x & 127;
    if (r >= 214) return;
    const float* srow; const float* Wb; bool addb = false;
    if (r < 96)       { srow = emb_table + r * EMB;           Wb = W; }
    else if (r < 192) { srow = emb_table + (r - 96) * EMB;    Wb = W + EMB * EMB; }
    else if (r < 212) { srow = step_table + (r - 192) * EMB;  Wb = W + 3 * EMB * EMB; }
    else              { srow = equiv_table + (r - 212) * EMB; Wb = W + 4 * EMB * EMB; addb = true; }
    in[threadIdx.x >> 7][c] = srow[c];
    __syncthreads();
    const float* inr = in[threadIdx.x >> 7];
    float a0 = 0, a1 = 0, a2 = 0, a3 = 0;
    #pragma unroll
    for (int k = 0; k < EMB; k += 4) {
        a0 = fmaf(inr[k + 0], Wb[(k + 0) * EMB + c], a0);
        a1 = fmaf(inr[k + 1], Wb[(k + 1) * EMB + c], a1);
        a2 = fmaf(inr[k + 2], Wb[(k + 2) * EMB + c], a2);
        a3 = fmaf(inr[k + 3], Wb[(k + 3) * EMB + c], a3);
    }
    float v = (a0 + a1) + (a2 + a3) + (addb ? b[c] : 0.0f);
    ((__half*)g_Th)[r * EMB + c] = __float2half(v);
}

// ---------------------------------------------------------------------------
// Kernel 2: persistent monolithic edge kernel, 2 CTAs/SM x 384 threads.
// 12 warps in a 3(m) x 4(n) grid, 32x32 output tile per warp, fp16 mma.sync.
// A tile: compact 256B stride, XOR-swizzled. Sum staged in fp16 (half2).
// P1 split 4 ways (src-chain / dst-chain / rbf / env); fp16x2 epilogue.
// ---------------------------------------------------------------------------
__global__ __launch_bounds__(THREADS, 2)
void edge_kernel(const int* __restrict__ Z, const int* __restrict__ stepA,
                 const int* __restrict__ src, const int* __restrict__ dst,
                 const int* __restrict__ equiv,
                 const float* __restrict__ rbf, const float* __restrict__ dvec,
                 const float* __restrict__ W_rbf, const float* __restrict__ b_rbf,
                 const float* __restrict__ W2,
                 float* __restrict__ out, int E, int tiles)
{
    extern __shared__ char sm[];
    char*   const Asm  = sm + OFF_A;
    char*   const Bsm  = sm + OFF_B;
    __half* const Sumh = (__half*)(sm + OFF_SUM);
    float*  const rbfs = (float*)(sm + OFF_RBFS);   // overlay, dead before Sum written
    float*  const Wr   = (float*)(sm + OFF_WR);     // [4][264] (32k x 8 + pad per q)
    int*    const sidxA = (int*)(sm + OFF_IDX);     // [96]: Z[src] | step<<7
    int*    const sidxB = sidxA + TILE;             // [96]: Z[dst] | equiv<<7

    const int tid  = threadIdx.x;
    const int wid  = tid >> 5;
    const int lane = tid & 31;

    // ---- one-time: W2^T -> fp16 smem; W_rbf -> banked smem blocks ----
    for (int idx = tid; idx < EMB * EMB; idx += THREADS) {
        int k = idx >> 7, n = idx & 127;
        *(__half*)(Bsm + k * SA + n * 2) = __float2half(W2[idx]);
    }
    for (int i = tid; i < 4 * 32 * 8; i += THREADS) {
        int q = i >> 8, kk = (i >> 3) & 31, j = i & 7;
        int k = 32 * q + kk;
        Wr[q * 264 + kk * 8 + j] = (j < 6) ? W_rbf[j * EMB + k] : (j == 6 ? b_rbf[k] : 0.0f);
    }
    __syncthreads();

    const int wm = wid >> 2;      // 0..2  (m-group of 32 edges)
    const int wn = wid & 3;       // 0..3  (n-group of 32 cols)
    const int m0 = wm * 32;
    const uint32_t lmoff = (uint32_t)((lane & 15) * SA + (lane >> 4) * 16);
    const uint32_t A_u = smem_u32(Asm);
    const uint32_t B_u = smem_u32(Bsm);
    // A swizzled read addressing: row = m0 + (lane&15); r3 = row&7 = lane&7
    const uint32_t r3   = (uint32_t)(lane & 7);
    const uint32_t hxa  = (uint32_t)(((lane >> 4) ^ (lane & 1)) * 16);
    const uint32_t r6x  = (r3 & 6) * 16;
    const uint32_t AuBase = A_u + (uint32_t)(m0 + (lane & 15)) * 256 + hxa;
    // role mapping: pe = edge within tile, pq = role / k-quarter
    const int pe = tid % TILE;
    const int pq = tid / TILE;    // 0..3
    // preload Teq rows (fp16)
    const uint2 te0u = g_Th[212 * 32 + lane];
    const uint2 te1u = g_Th[213 * 32 + lane];
    float* const envo = out + (size_t)E * EMB;

    for (int t = blockIdx.x; t < tiles; t += gridDim.x) {
        const int ebase = t * TILE;
        const int ge1 = ebase + pe;
        const bool v1 = (ge1 < E);

        // ---- P1: 4-role split over all 384 threads ----
        if (pq == 0) {
            int pk = 0;
            if (v1) { int s = src[ge1]; pk = Z[s] | (stepA[s] << 7); }
            sidxA[pe] = pk;
        } else if (pq == 1) {
            int pk = 0;
            if (v1) { int dd = dst[ge1]; pk = Z[dd] | (equiv[ge1] << 7); }
            sidxB[pe] = pk;
        } else if (pq == 2) {
            if (v1) {
                const float* rp = rbf + (size_t)ge1 * NR;
                float2 a = *(const float2*)(rp);
                float2 b = *(const float2*)(rp + 2);
                float2 c = *(const float2*)(rp + 4);
                float* rr = rbfs + pe * RS;
                rr[0] = a.x; rr[1] = a.y; rr[2] = b.x;
                rr[3] = b.y; rr[4] = c.x; rr[5] = c.y;
            }
        } else {
            if (v1) {
                float x = dvec[ge1] * 0.2f;
                float inv = 1.0f / x;
                float x2 = x * x;
                float x5 = x2 * x2 * x;
                float env = inv + x5 * (-28.0f + x * (48.0f + x * (-21.0f)));
                float coef = env * inv;
                const float PI = 3.14159265358979323846f;
                float th = PI * x;
                float s1 = __sinf(th), c1 = __cosf(th);
                float twoc = 2.0f * c1;
                float sp = 0.0f, s = s1;
                float o[NR];
                #pragma unroll
                for (int j = 0; j < NR; j++) {
                    o[j] = coef * s;
                    float sn = twoc * s - sp;
                    sp = s; s = sn;
                }
                float* op = envo + (size_t)ge1 * NR;
                *(float2*)(op + 0) = make_float2(o[0], o[1]);
                *(float2*)(op + 2) = make_float2(o[2], o[3]);
                *(float2*)(op + 4) = make_float2(o[4], o[5]);
            }
        }
        __syncthreads();

        // ---- P2a: A = silu(rbf @ W_rbf + b) fp16, swizzled store ----
        {
            const float* rr = rbfs + pe * RS;
            float r0 = rr[0], r1 = rr[1], r2 = rr[2], r3v = rr[3], r4 = rr[4], r5 = rr[5];
            const float* wq = Wr + pq * 264;
            char* ah = Asm + pe * 256;
            const int sw = pe & 7;
            #pragma unroll
            for (int g = 0; g < 4; g++) {
                uint32_t hb[4];
                #pragma unroll
                for (int pp = 0; pp < 4; pp++) {
                    const int kk = g * 8 + pp * 2;
                    float4 wa = *(const float4*)&wq[kk * 8];
                    float4 wb = *(const float4*)&wq[kk * 8 + 4];
                    float4 wc = *(const float4*)&wq[kk * 8 + 8];
                    float4 wd = *(const float4*)&wq[kk * 8 + 12];
                    float z0 = wb.z + r0 * wa.x + r1 * wa.y + r2 * wa.z + r3v * wa.w + r4 * wb.x + r5 * wb.y;
                    float z1 = wd.z + r0 * wc.x + r1 * wc.y + r2 * wc.z + r3v * wc.w + r4 * wd.x + r5 * wd.y;
                    float a0 = silu_f(z0);
                    float a1 = silu_f(z1);
                    asm("cvt.rn.f16x2.f32 %0, %1, %2;" : "=r"(hb[pp]) : "f"(a1), "f"(a0));
                }
                const uint32_t off = (uint32_t)(((pq * 4 + g) ^ sw) * 16);
                *(uint4*)(ah + off) = make_uint4(hb[0], hb[1], hb[2], hb[3]);
            }
        }
        __syncthreads();

        // ---- P2b: fp16 table gathers -> fp16 Sum via add.f16x2 (8 rows/warp) ----
        #pragma unroll
        for (int i = 0; i < 8; i++) {
            const int r = wid * 8 + i;
            const uint32_t pkA = (uint32_t)sidxA[r];
            const uint32_t pkB = (uint32_t)sidxB[r];
            const int zs = pkA & 127, st = pkA >> 7;
            const int zd = pkB & 127, eq = pkB >> 7;
            uint2 u0 = g_Th[zs * 32 + lane];
            uint2 u1 = g_Th[(96 + zd) * 32 + lane];
            uint2 u2 = g_Th[(192 + st) * 32 + lane];
            uint2 u3 = eq ? te1u : te0u;
            uint2 o;
            o.x = hadd2(hadd2(u0.x, u1.x), hadd2(u2.x, u3.x));
            o.y = hadd2(hadd2(u0.y, u1.y), hadd2(u2.y, u3.y));
            *(uint2*)&Sumh[r * SH + lane * 4] = o;
        }

        // ---- P3: GEMM 32x32 per warp, single-pass fp16, swizzled A reads ----
        float d[2][4][4];
        #pragma unroll
        for (int mt = 0; mt < 2; mt++)
            #pragma unroll
            for (int jj = 0; jj < 4; jj++)
                d[mt][jj][0] = d[mt][jj][1] = d[mt][jj][2] = d[mt][jj][3] = 0.0f;

        {
            const uint32_t Bu = B_u + wn * 64 + lmoff;
            #pragma unroll
            for (int ks = 0; ks < 8; ks++) {
                const uint32_t aoff = ((uint32_t)(ks * 32)) ^ r6x;
                uint32_t a[8];
                ldsm4(a + 0, AuBase + aoff);
                ldsm4(a + 4, AuBase + 4096 + aoff);
                uint32_t b[8];
                ldsm4t(b + 0, Bu + ks * 16 * SA);
                ldsm4t(b + 4, Bu + ks * 16 * SA + 32);
                #pragma unroll
                for (int mt = 0; mt < 2; mt++)
                    #pragma unroll
                    for (int jj = 0; jj < 4; jj++)
                        mma_f16(d[mt][jj], a + mt * 4, b + 2 * jj);
            }
        }
        __syncthreads();

        // ---- P4: epilogue in fp16x2 (cvt, add.f16x2, tanh.approx.f16x2) ----
        #pragma unroll
        for (int mt = 0; mt < 2; mt++) {
            const int r1 = m0 + mt * 16 + (lane >> 2);
            __half* S1 = Sumh + r1 * SH;
            __half* S2 = Sumh + (r1 + 8) * SH;
            #pragma unroll
            for (int jj = 0; jj < 4; jj++) {
                const int c = wn * 32 + jj * 8 + (lane & 3) * 2;
                const float* dd = d[mt][jj];
                uint32_t dh0, dh1;
                asm("cvt.rn.f16x2.f32 %0, %1, %2;" : "=r"(dh0) : "f"(dd[1]), "f"(dd[0]));
                asm("cvt.rn.f16x2.f32 %0, %1, %2;" : "=r"(dh1) : "f"(dd[3]), "f"(dd[2]));
                uint32_t* p1 = (uint32_t*)&S1[c];
                uint32_t* p2 = (uint32_t*)&S2[c];
                *p1 = silu_h2(hadd2(*p1, dh0));
                *p2 = silu_h2(hadd2(*p2, dh1));
            }
        }
        __syncthreads();

        // ---- P5: convert + coalesced copy-out (8 rows/warp) ----
        #pragma unroll
        for (int i = 0; i < 8; i++) {
            const int r = wid * 8 + i;
            const int ge = ebase + r;
            if (ge < E) {
                uint2 u = *(uint2*)&Sumh[r * SH + lane * 4];
                float2 a = __half22float2(*(__half2*)&u.x);
                float2 b = __half22float2(*(__half2*)&u.y);
                *(float4*)&out[(size_t)ge * EMB + lane * 4] = make_float4(a.x, a.y, b.x, b.y);
            }
        }
        __syncthreads();
    }
}

// ---------------------------------------------------------------------------
extern "C" void kernel_launch(void* const* d_in, const int* in_sizes, int n_in,
                              void* d_out, int out_size)
{
    const int*   Z          = (const int*)d_in[0];
    const int*   stepA      = (const int*)d_in[1];
    const int*   src        = (const int*)d_in[2];
    const int*   dst        = (const int*)d_in[3];
    const int*   equiv      = (const int*)d_in[4];
    const float* rbf        = (const float*)d_in[5];
    const float* dvec       = (const float*)d_in[6];
    const float* emb_table  = (const float*)d_in[7];
    const float* step_table = (const float*)d_in[8];
    const float* equiv_tab  = (const float*)d_in[9];
    const float* W_rbf      = (const float*)d_in[10];
    const float* b_rbf      = (const float*)d_in[11];
    const float* W          = (const float*)d_in[12];
    const float* b          = (const float*)d_in[13];
    float* out = (float*)d_out;

    const int E = in_sizes[2];
    const int tiles = (E + TILE - 1) / TILE;

    static int sms = 0;
    if (sms == 0) {
        if (cudaDeviceGetAttribute(&sms, cudaDevAttrMultiProcessorCount, 0) != cudaSuccess || sms <= 0)
            sms = 148;
    }
    int grid = 2 * sms;
    if (grid > tiles) grid = tiles;

    cudaFuncSetAttribute(edge_kernel, cudaFuncAttributeMaxDynamicSharedMemorySize, SMEM_TOT);

    precompute_kernel<<<107, 256>>>(emb_table, step_table, equiv_tab, W, b);
    edge_kernel<<<grid, THREADS, SMEM_TOT>>>(Z, stepA, src, dst, equiv,
                                             rbf, dvec, W_rbf, b_rbf,
                                             W + 2 * EMB * EMB, out, E, tiles);
}

// round 15
// speedup vs baseline: 3.5924x; 1.0140x over previous
#include <cuda_runtime.h>
#include <cuda_fp16.h>
#include <cstdint>

#define EMB 128
#define NR 6
#define SA 272          // B smem row stride in bytes (136 fp16)
#define SH 136          // Sum_h row stride in halves (272B, conflict-free)
#define RS 9            // rbf stage row stride in floats
#define TILE 96         // edges per tile
#define THREADS 384     // 12 warps, monolithic phases, 2 CTAs/SM

// smem offsets (bytes)
#define OFF_A    0        // 96*256 swizzled   = 24576
#define OFF_B    24576    // 128*272           = 34816 -> 59392
#define OFF_SUM  59392    // 96*272 (fp16)     = 26112 -> 85504
#define OFF_RBFS 85504    // 96*9*4            = 3456  -> 88960 (no overlay now)
#define OFF_WR   88960    // 4*264*4           = 4224  -> 93184
#define OFF_IDX  93184    // 2 x 96*4          = 768   -> 93952
#define SMEM_TOT 93952    // (93952+1024r)*2 = 189952 <= 233472; ~40KB L1D left

// Precomputed table @ W_block projections in fp16: rows 0-95 Tsrc, 96-191 Tdst,
// 192-211 Tstep, 212-213 Teq (+bias folded into Teq rows). uint2 for 8B loads.
__device__ uint2 g_Th[214 * 32];

__device__ __forceinline__ uint32_t smem_u32(const void* p) {
    uint32_t a;
    asm("{ .reg .u64 t; cvta.to.shared.u64 t, %1; cvt.u32.u64 %0, t; }" : "=r"(a) : "l"(p));
    return a;
}
// silu(x) = 0.5x * (1 + tanh(x/2))  (fp32, for A production)
__device__ __forceinline__ float silu_f(float x) {
    float h = 0.5f * x, t;
    asm("tanh.approx.f32 %0, %1;" : "=f"(t) : "f"(h));
    return fmaf(h, t, h);
}
__device__ __forceinline__ uint32_t hadd2(uint32_t a, uint32_t b) {
    uint32_t r;
    asm("add.f16x2 %0, %1, %2;" : "=r"(r) : "r"(a), "r"(b));
    return r;
}
// packed fp16x2 silu: h = 0.5x; t = tanh(h); r = h*t + h
__device__ __forceinline__ uint32_t silu_h2(uint32_t x) {
    uint32_t h, t, r;
    asm("mul.f16x2 %0, %1, %2;" : "=r"(h) : "r"(x), "r"(0x38003800u));
    asm("tanh.approx.f16x2 %0, %1;" : "=r"(t) : "r"(h));
    asm("fma.rn.f16x2 %0, %1, %2, %1;" : "=r"(r) : "r"(h), "r"(t));
    return r;
}
__device__ __forceinline__ void ldsm4(uint32_t* r, uint32_t addr) {
    asm volatile("ldmatrix.sync.aligned.m8n8.x4.shared.b16 {%0,%1,%2,%3}, [%4];"
                 : "=r"(r[0]), "=r"(r[1]), "=r"(r[2]), "=r"(r[3]) : "r"(addr));
}
__device__ __forceinline__ void ldsm4t(uint32_t* r, uint32_t addr) {
    asm volatile("ldmatrix.sync.aligned.m8n8.x4.trans.shared.b16 {%0,%1,%2,%3}, [%4];"
                 : "=r"(r[0]), "=r"(r[1]), "=r"(r[2]), "=r"(r[3]) : "r"(addr));
}
__device__ __forceinline__ void mma_f16(float* d, const uint32_t* a, const uint32_t* b) {
    asm volatile("mma.sync.aligned.m16n8k16.row.col.f32.f16.f16.f32 "
                 "{%0,%1,%2,%3}, {%4,%5,%6,%7}, {%8,%9}, {%0,%1,%2,%3};"
                 : "+f"(d[0]), "+f"(d[1]), "+f"(d[2]), "+f"(d[3])
                 : "r"(a[0]), "r"(a[1]), "r"(a[2]), "r"(a[3]), "r"(b[0]), "r"(b[1]));
}

// ---------------------------------------------------------------------------
// Kernel 1: g_Th = fp16(tables @ W_blocks) (bias folded into Teq rows).
// ---------------------------------------------------------------------------
__global__ void precompute_kernel(const float* __restrict__ emb_table,
                                  const float* __restrict__ step_table,
                                  const float* __restrict__ equiv_table,
                                  const float* __restrict__ W,
                                  const float* __restrict__ b)
{
    __shared__ float in[2][EMB];
    int r = blockIdx.x * 2 + (threadIdx.x >> 7);
    int c = threadIdx.x & 127;
    if (r >= 214) return;
    const float* srow; const float* Wb; bool addb = false;
    if (r < 96)       { srow = emb_table + r * EMB;           Wb = W; }
    else if (r < 192) { srow = emb_table + (r - 96) * EMB;    Wb = W + EMB * EMB; }
    else if (r < 212) { srow = step_table + (r - 192) * EMB;  Wb = W + 3 * EMB * EMB; }
    else              { srow = equiv_table + (r - 212) * EMB; Wb = W + 4 * EMB * EMB; addb = true; }
    in[threadIdx.x >> 7][c] = srow[c];
    __syncthreads();
    const float* inr = in[threadIdx.x >> 7];
    float a0 = 0, a1 = 0, a2 = 0, a3 = 0;
    #pragma unroll
    for (int k = 0; k < EMB; k += 4) {
        a0 = fmaf(inr[k + 0], Wb[(k + 0) * EMB + c], a0);
        a1 = fmaf(inr[k + 1], Wb[(k + 1) * EMB + c], a1);
        a2 = fmaf(inr[k + 2], Wb[(k + 2) * EMB + c], a2);
        a3 = fmaf(inr[k + 3], Wb[(k + 3) * EMB + c], a3);
    }
    float v = (a0 + a1) + (a2 + a3) + (addb ? b[c] : 0.0f);
    ((__half*)g_Th)[r * EMB + c] = __float2half(v);
}

// ---------------------------------------------------------------------------
// Kernel 2: persistent monolithic edge kernel, 2 CTAs/SM x 384 threads.
// 12 warps in a 3(m) x 4(n) grid, 32x32 output tile per warp, fp16 mma.sync.
// Software-pipelined: independent global loads prefetched one tile ahead;
// copy-out of tile t-1 merged into P1 of tile t (4 syncs/tile).
// ---------------------------------------------------------------------------
__global__ __launch_bounds__(THREADS, 2)
void edge_kernel(const int* __restrict__ Z, const int* __restrict__ stepA,
                 const int* __restrict__ src, const int* __restrict__ dst,
                 const int* __restrict__ equiv,
                 const float* __restrict__ rbf, const float* __restrict__ dvec,
                 const float* __restrict__ W_rbf, const float* __restrict__ b_rbf,
                 const float* __restrict__ W2,
                 float* __restrict__ out, int E, int tiles)
{
    extern __shared__ char sm[];
    char*   const Asm  = sm + OFF_A;
    char*   const Bsm  = sm + OFF_B;
    __half* const Sumh = (__half*)(sm + OFF_SUM);
    float*  const rbfs = (float*)(sm + OFF_RBFS);
    float*  const Wr   = (float*)(sm + OFF_WR);     // [4][264] (32k x 8 + pad per q)
    int*    const sidxA = (int*)(sm + OFF_IDX);     // [96]: Z[src] | step<<7
    int*    const sidxB = sidxA + TILE;             // [96]: Z[dst] | equiv<<7

    const int tid  = threadIdx.x;
    const int wid  = tid >> 5;
    const int lane = tid & 31;
    // role mapping: pe = edge within tile, pq = role / k-quarter
    const int pe = tid % TILE;
    const int pq = tid / TILE;    // 0..3
    const int stride = gridDim.x;

    // ---- initial prefetch for first tile (latency hidden behind setup) ----
    int   pfi = 0, pfi2 = 0;
    float pf0 = 1.0f, pf1 = 0, pf2 = 0, pf3 = 0, pf4 = 0, pf5 = 0;
    {
        const int t0 = blockIdx.x;
        const int gn = t0 * TILE + pe;
        const bool vn = (t0 < tiles) && (gn < E);
        if (pq == 0)      { if (vn) pfi = src[gn]; }
        else if (pq == 1) { if (vn) { pfi = dst[gn]; pfi2 = equiv[gn]; } }
        else if (pq == 2) {
            if (vn) {
                const float* rp = rbf + (size_t)gn * NR;
                float2 a = *(const float2*)(rp);
                float2 b = *(const float2*)(rp + 2);
                float2 c = *(const float2*)(rp + 4);
                pf0 = a.x; pf1 = a.y; pf2 = b.x; pf3 = b.y; pf4 = c.x; pf5 = c.y;
            }
        } else            { if (vn) pf0 = dvec[gn]; }
    }

    // ---- one-time: W2^T -> fp16 smem; W_rbf -> banked smem blocks ----
    for (int idx = tid; idx < EMB * EMB; idx += THREADS) {
        int k = idx >> 7, n = idx & 127;
        *(__half*)(Bsm + k * SA + n * 2) = __float2half(W2[idx]);
    }
    for (int i = tid; i < 4 * 32 * 8; i += THREADS) {
        int q = i >> 8, kk = (i >> 3) & 31, j = i & 7;
        int k = 32 * q + kk;
        Wr[q * 264 + kk * 8 + j] = (j < 6) ? W_rbf[j * EMB + k] : (j == 6 ? b_rbf[k] : 0.0f);
    }
    __syncthreads();

    const int wm = wid >> 2;      // 0..2  (m-group of 32 edges)
    const int wn = wid & 3;       // 0..3  (n-group of 32 cols)
    const int m0 = wm * 32;
    const uint32_t lmoff = (uint32_t)((lane & 15) * SA + (lane >> 4) * 16);
    const uint32_t A_u = smem_u32(Asm);
    const uint32_t B_u = smem_u32(Bsm);
    // A swizzled read addressing: row = m0 + (lane&15); r3 = row&7 = lane&7
    const uint32_t r3   = (uint32_t)(lane & 7);
    const uint32_t hxa  = (uint32_t)(((lane >> 4) ^ (lane & 1)) * 16);
    const uint32_t r6x  = (r3 & 6) * 16;
    const uint32_t AuBase = A_u + (uint32_t)(m0 + (lane & 15)) * 256 + hxa;
    // preload Teq rows (fp16)
    const uint2 te0u = g_Th[212 * 32 + lane];
    const uint2 te1u = g_Th[213 * 32 + lane];
    float* const envo = out + (size_t)E * EMB;

    int prev_ebase = -1;

    for (int t = blockIdx.x; t < tiles; t += stride) {
        const int ebase = t * TILE;
        const int ge1 = ebase + pe;
        const bool v1 = (ge1 < E);

        // ---- P0: copy-out of tile t-1  +  P1(t) consume  +  prefetch(t+stride) ----
        if (prev_ebase >= 0) {
            #pragma unroll
            for (int i = 0; i < 8; i++) {
                const int r = wid * 8 + i;
                const int ge = prev_ebase + r;
                if (ge < E) {
                    uint2 u = *(uint2*)&Sumh[r * SH + lane * 4];
                    float2 a = __half22float2(*(__half2*)&u.x);
                    float2 b = __half22float2(*(__half2*)&u.y);
                    *(float4*)&out[(size_t)ge * EMB + lane * 4] = make_float4(a.x, a.y, b.x, b.y);
                }
            }
        }
        if (pq == 0) {
            int pk = 0;
            if (v1) { int s = pfi; pk = Z[s] | (stepA[s] << 7); }
            sidxA[pe] = pk;
        } else if (pq == 1) {
            int pk = 0;
            if (v1) { int dd = pfi; pk = Z[dd] | (pfi2 << 7); }
            sidxB[pe] = pk;
        } else if (pq == 2) {
            float* rr = rbfs + pe * RS;
            rr[0] = pf0; rr[1] = pf1; rr[2] = pf2;
            rr[3] = pf3; rr[4] = pf4; rr[5] = pf5;
        } else {
            if (v1) {
                float x = pf0 * 0.2f;
                float inv = 1.0f / x;
                float x2 = x * x;
                float x5 = x2 * x2 * x;
                float env = inv + x5 * (-28.0f + x * (48.0f + x * (-21.0f)));
                float coef = env * inv;
                const float PI = 3.14159265358979323846f;
                float th = PI * x;
                float s1 = __sinf(th), c1 = __cosf(th);
                float twoc = 2.0f * c1;
                float sp = 0.0f, s = s1;
                float o[NR];
                #pragma unroll
                for (int j = 0; j < NR; j++) {
                    o[j] = coef * s;
                    float sn = twoc * s - sp;
                    sp = s; s = sn;
                }
                float* op = envo + (size_t)ge1 * NR;
                *(float2*)(op + 0) = make_float2(o[0], o[1]);
                *(float2*)(op + 2) = make_float2(o[2], o[3]);
                *(float2*)(op + 4) = make_float2(o[4], o[5]);
            }
        }
        // issue prefetch for tile t+stride (consumed next iteration)
        {
            const int tn = t + stride;
            const int gn = tn * TILE + pe;
            const bool vn = (tn < tiles) && (gn < E);
            if (pq == 0)      { pfi = vn ? src[gn] : 0; }
            else if (pq == 1) { pfi = vn ? dst[gn] : 0; pfi2 = vn ? equiv[gn] : 0; }
            else if (pq == 2) {
                if (vn) {
                    const float* rp = rbf + (size_t)gn * NR;
                    float2 a = *(const float2*)(rp);
                    float2 b = *(const float2*)(rp + 2);
                    float2 c = *(const float2*)(rp + 4);
                    pf0 = a.x; pf1 = a.y; pf2 = b.x; pf3 = b.y; pf4 = c.x; pf5 = c.y;
                }
            } else            { pf0 = vn ? dvec[gn] : 1.0f; }
        }
        __syncthreads();

        // ---- P2a: A = silu(rbf @ W_rbf + b) fp16, swizzled store ----
        {
            const float* rr = rbfs + pe * RS;
            float r0 = rr[0], r1 = rr[1], r2 = rr[2], r3v = rr[3], r4 = rr[4], r5 = rr[5];
            const float* wq = Wr + pq * 264;
            char* ah = Asm + pe * 256;
            const int sw = pe & 7;
            #pragma unroll
            for (int g = 0; g < 4; g++) {
                uint32_t hb[4];
                #pragma unroll
                for (int pp = 0; pp < 4; pp++) {
                    const int kk = g * 8 + pp * 2;
                    float4 wa = *(const float4*)&wq[kk * 8];
                    float4 wb = *(const float4*)&wq[kk * 8 + 4];
                    float4 wc = *(const float4*)&wq[kk * 8 + 8];
                    float4 wd = *(const float4*)&wq[kk * 8 + 12];
                    float z0 = wb.z + r0 * wa.x + r1 * wa.y + r2 * wa.z + r3v * wa.w + r4 * wb.x + r5 * wb.y;
                    float z1 = wd.z + r0 * wc.x + r1 * wc.y + r2 * wc.z + r3v * wc.w + r4 * wd.x + r5 * wd.y;
                    float a0 = silu_f(z0);
                    float a1 = silu_f(z1);
                    asm("cvt.rn.f16x2.f32 %0, %1, %2;" : "=r"(hb[pp]) : "f"(a1), "f"(a0));
                }
                const uint32_t off = (uint32_t)(((pq * 4 + g) ^ sw) * 16);
                *(uint4*)(ah + off) = make_uint4(hb[0], hb[1], hb[2], hb[3]);
            }
        }
        __syncthreads();

        // ---- P2b: fp16 table gathers -> fp16 Sum via add.f16x2 (8 rows/warp) ----
        #pragma unroll
        for (int i = 0; i < 8; i++) {
            const int r = wid * 8 + i;
            const uint32_t pkA = (uint32_t)sidxA[r];
            const uint32_t pkB = (uint32_t)sidxB[r];
            const int zs = pkA & 127, st = pkA >> 7;
            const int zd = pkB & 127, eq = pkB >> 7;
            uint2 u0 = g_Th[zs * 32 + lane];
            uint2 u1 = g_Th[(96 + zd) * 32 + lane];
            uint2 u2 = g_Th[(192 + st) * 32 + lane];
            uint2 u3 = eq ? te1u : te0u;
            uint2 o;
            o.x = hadd2(hadd2(u0.x, u1.x), hadd2(u2.x, u3.x));
            o.y = hadd2(hadd2(u0.y, u1.y), hadd2(u2.y, u3.y));
            *(uint2*)&Sumh[r * SH + lane * 4] = o;
        }

        // ---- P3: GEMM 32x32 per warp, single-pass fp16, swizzled A reads ----
        float d[2][4][4];
        #pragma unroll
        for (int mt = 0; mt < 2; mt++)
            #pragma unroll
            for (int jj = 0; jj < 4; jj++)
                d[mt][jj][0] = d[mt][jj][1] = d[mt][jj][2] = d[mt][jj][3] = 0.0f;

        {
            const uint32_t Bu = B_u + wn * 64 + lmoff;
            #pragma unroll
            for (int ks = 0; ks < 8; ks++) {
                const uint32_t aoff = ((uint32_t)(ks * 32)) ^ r6x;
                uint32_t a[8];
                ldsm4(a + 0, AuBase + aoff);
                ldsm4(a + 4, AuBase + 4096 + aoff);
                uint32_t b[8];
                ldsm4t(b + 0, Bu + ks * 16 * SA);
                ldsm4t(b + 4, Bu + ks * 16 * SA + 32);
                #pragma unroll
                for (int mt = 0; mt < 2; mt++)
                    #pragma unroll
                    for (int jj = 0; jj < 4; jj++)
                        mma_f16(d[mt][jj], a + mt * 4, b + 2 * jj);
            }
        }
        __syncthreads();

        // ---- P4: epilogue in fp16x2 (cvt, add.f16x2, tanh.approx.f16x2) ----
        #pragma unroll
        for (int mt = 0; mt < 2; mt++) {
            const int r1 = m0 + mt * 16 + (lane >> 2);
            __half* S1 = Sumh + r1 * SH;
            __half* S2 = Sumh + (r1 + 8) * SH;
            #pragma unroll
            for (int jj = 0; jj < 4; jj++) {
                const int c = wn * 32 + jj * 8 + (lane & 3) * 2;
                const float* dd = d[mt][jj];
                uint32_t dh0, dh1;
                asm("cvt.rn.f16x2.f32 %0, %1, %2;" : "=r"(dh0) : "f"(dd[1]), "f"(dd[0]));
                asm("cvt.rn.f16x2.f32 %0, %1, %2;" : "=r"(dh1) : "f"(dd[3]), "f"(dd[2]));
                uint32_t* p1 = (uint32_t*)&S1[c];
                uint32_t* p2 = (uint32_t*)&S2[c];
                *p1 = silu_h2(hadd2(*p1, dh0));
                *p2 = silu_h2(hadd2(*p2, dh1));
            }
        }
        __syncthreads();

        prev_ebase = ebase;
    }

    // ---- final copy-out for the last processed tile ----
    if (prev_ebase >= 0) {
        #pragma unroll
        for (int i = 0; i < 8; i++) {
            const int r = wid * 8 + i;
            const int ge = prev_ebase + r;
            if (ge < E) {
                uint2 u = *(uint2*)&Sumh[r * SH + lane * 4];
                float2 a = __half22float2(*(__half2*)&u.x);
                float2 b = __half22float2(*(__half2*)&u.y);
                *(float4*)&out[(size_t)ge * EMB + lane * 4] = make_float4(a.x, a.y, b.x, b.y);
            }
        }
    }
}

// ---------------------------------------------------------------------------
extern "C" void kernel_launch(void* const* d_in, const int* in_sizes, int n_in,
                              void* d_out, int out_size)
{
    const int*   Z          = (const int*)d_in[0];
    const int*   stepA      = (const int*)d_in[1];
    const int*   src        = (const int*)d_in[2];
    const int*   dst        = (const int*)d_in[3];
    const int*   equiv      = (const int*)d_in[4];
    const float* rbf        = (const float*)d_in[5];
    const float* dvec       = (const float*)d_in[6];
    const float* emb_table  = (const float*)d_in[7];
    const float* step_table = (const float*)d_in[8];
    const float* equiv_tab  = (const float*)d_in[9];
    const float* W_rbf      = (const float*)d_in[10];
    const float* b_rbf      = (const float*)d_in[11];
    const float* W          = (const float*)d_in[12];
    const float* b          = (const float*)d_in[13];
    float* out = (float*)d_out;

    const int E = in_sizes[2];
    const int tiles = (E + TILE - 1) / TILE;

    static int sms = 0;
    if (sms == 0) {
        if (cudaDeviceGetAttribute(&sms, cudaDevAttrMultiProcessorCount, 0) != cudaSuccess || sms <= 0)
            sms = 148;
    }
    int grid = 2 * sms;
    if (grid > tiles) grid = tiles;

    cudaFuncSetAttribute(edge_kernel, cudaFuncAttributeMaxDynamicSharedMemorySize, SMEM_TOT);

    precompute_kernel<<<107, 256>>>(emb_table, step_table, equiv_tab, W, b);
    edge_kernel<<<grid, THREADS, SMEM_TOT>>>(Z, stepA, src, dst, equiv,
                                             rbf, dvec, W_rbf, b_rbf,
                                             W + 2 * EMB * EMB, out, E, tiles);
}

// round 16
// speedup vs baseline: 4.2887x; 1.1938x over previous
#include <cuda_runtime.h>
#include <cuda_fp16.h>
#include <cstdint>

#define EMB 128
#define NR 6
#define SA 272          // B smem row stride in bytes (136 fp16)
#define SH 136          // Sum_h row stride in halves (272B, conflict-free)
#define TILE 96         // edges per tile
#define THREADS 384     // 12 warps, monolithic phases, 2 CTAs/SM

// smem offsets (bytes)
#define OFF_A    0        // 96*256 swizzled   = 24576
#define OFF_B    24576    // 128*272           = 34816 -> 59392
#define OFF_SUM  59392    // 96*272 (fp16)     = 26112 -> 85504
#define OFF_RBFH 85504    // 96*48 (fp16 k16)  = 4608  -> 90112
#define OFF_WRH  90112    // 16*272 (fp16)     = 4352  -> 94464
#define OFF_IDX  94464    // 2 x 96*4          = 768   -> 95232
#define SMEM_TOT 95232    // (95232+1024r)*2 = 192512 <= 233472; ~40KB L1D left

// Precomputed table @ W_block projections in fp16: rows 0-95 Tsrc, 96-191 Tdst,
// 192-211 Tstep, 212-213 Teq (+bias folded into Teq rows). uint2 for 8B loads.
__device__ uint2 g_Th[214 * 32];

__device__ __forceinline__ uint32_t smem_u32(const void* p) {
    uint32_t a;
    asm("{ .reg .u64 t; cvta.to.shared.u64 t, %1; cvt.u32.u64 %0, t; }" : "=r"(a) : "l"(p));
    return a;
}
// silu(x) = 0.5x * (1 + tanh(x/2))  (fp32)
__device__ __forceinline__ float silu_f(float x) {
    float h = 0.5f * x, t;
    asm("tanh.approx.f32 %0, %1;" : "=f"(t) : "f"(h));
    return fmaf(h, t, h);
}
__device__ __forceinline__ uint32_t hadd2(uint32_t a, uint32_t b) {
    uint32_t r;
    asm("add.f16x2 %0, %1, %2;" : "=r"(r) : "r"(a), "r"(b));
    return r;
}
// packed fp16x2 silu: h = 0.5x; t = tanh(h); r = h*t + h
__device__ __forceinline__ uint32_t silu_h2(uint32_t x) {
    uint32_t h, t, r;
    asm("mul.f16x2 %0, %1, %2;" : "=r"(h) : "r"(x), "r"(0x38003800u));
    asm("tanh.approx.f16x2 %0, %1;" : "=r"(t) : "r"(h));
    asm("fma.rn.f16x2 %0, %1, %2, %1;" : "=r"(r) : "r"(h), "r"(t));
    return r;
}
__device__ __forceinline__ void ldsm4(uint32_t* r, uint32_t addr) {
    asm volatile("ldmatrix.sync.aligned.m8n8.x4.shared.b16 {%0,%1,%2,%3}, [%4];"
                 : "=r"(r[0]), "=r"(r[1]), "=r"(r[2]), "=r"(r[3]) : "r"(addr));
}
__device__ __forceinline__ void ldsm4t(uint32_t* r, uint32_t addr) {
    asm volatile("ldmatrix.sync.aligned.m8n8.x4.trans.shared.b16 {%0,%1,%2,%3}, [%4];"
                 : "=r"(r[0]), "=r"(r[1]), "=r"(r[2]), "=r"(r[3]) : "r"(addr));
}
__device__ __forceinline__ void mma_f16(float* d, const uint32_t* a, const uint32_t* b) {
    asm volatile("mma.sync.aligned.m16n8k16.row.col.f32.f16.f16.f32 "
                 "{%0,%1,%2,%3}, {%4,%5,%6,%7}, {%8,%9}, {%0,%1,%2,%3};"
                 : "+f"(d[0]), "+f"(d[1]), "+f"(d[2]), "+f"(d[3])
                 : "r"(a[0]), "r"(a[1]), "r"(a[2]), "r"(a[3]), "r"(b[0]), "r"(b[1]));
}

// ---------------------------------------------------------------------------
// Kernel 1: g_Th = fp16(tables @ W_blocks) (bias folded into Teq rows).
// ---------------------------------------------------------------------------
__global__ void precompute_kernel(const float* __restrict__ emb_table,
                                  const float* __restrict__ step_table,
                                  const float* __restrict__ equiv_table,
                                  const float* __restrict__ W,
                                  const float* __restrict__ b)
{
    __shared__ float in[2][EMB];
    int r = blockIdx.x * 2 + (threadIdx.x >> 7);
    int c = threadIdx.x & 127;
    if (r >= 214) return;
    const float* srow; const float* Wb; bool addb = false;
    if (r < 96)       { srow = emb_table + r * EMB;           Wb = W; }
    else if (r < 192) { srow = emb_table + (r - 96) * EMB;    Wb = W + EMB * EMB; }
    else if (r < 212) { srow = step_table + (r - 192) * EMB;  Wb = W + 3 * EMB * EMB; }
    else              { srow = equiv_table + (r - 212) * EMB; Wb = W + 4 * EMB * EMB; addb = true; }
    in[threadIdx.x >> 7][c] = srow[c];
    __syncthreads();
    const float* inr = in[threadIdx.x >> 7];
    float a0 = 0, a1 = 0, a2 = 0, a3 = 0;
    #pragma unroll
    for (int k = 0; k < EMB; k += 4) {
        a0 = fmaf(inr[k + 0], Wb[(k + 0) * EMB + c], a0);
        a1 = fmaf(inr[k + 1], Wb[(k + 1) * EMB + c], a1);
        a2 = fmaf(inr[k + 2], Wb[(k + 2) * EMB + c], a2);
        a3 = fmaf(inr[k + 3], Wb[(k + 3) * EMB + c], a3);
    }
    float v = (a0 + a1) + (a2 + a3) + (addb ? b[c] : 0.0f);
    ((__half*)g_Th)[r * EMB + c] = __float2half(v);
}

// ---------------------------------------------------------------------------
// Kernel 2: persistent monolithic edge kernel, 2 CTAs/SM x 384 threads.
// Main GEMM: 12 warps 3(m)x4(n), 32x32 tiles, fp16 mma.sync.
// A-production: tensor core too — Z = rbf16[96x16] @ Wrbf16[16x128] (bias in k=6),
// silu + store into swizzled A. Software-pipelined global loads, merged copy-out.
// ---------------------------------------------------------------------------
__global__ __launch_bounds__(THREADS, 2)
void edge_kernel(const int* __restrict__ Z, const int* __restrict__ stepA,
                 const int* __restrict__ src, const int* __restrict__ dst,
                 const int* __restrict__ equiv,
                 const float* __restrict__ rbf, const float* __restrict__ dvec,
                 const float* __restrict__ W_rbf, const float* __restrict__ b_rbf,
                 const float* __restrict__ W2,
                 float* __restrict__ out, int E, int tiles)
{
    extern __shared__ char sm[];
    char*   const Asm  = sm + OFF_A;
    char*   const Bsm  = sm + OFF_B;
    __half* const Sumh = (__half*)(sm + OFF_SUM);
    char*   const RBFh = sm + OFF_RBFH;             // [96][48B] (k0..15 fp16 + pad)
    char*   const WRh  = sm + OFF_WRH;              // [16][272B]
    int*    const sidxA = (int*)(sm + OFF_IDX);     // [96]: Z[src] | step<<7
    int*    const sidxB = sidxA + TILE;             // [96]: Z[dst] | equiv<<7

    const int tid  = threadIdx.x;
    const int wid  = tid >> 5;
    const int lane = tid & 31;
    const int pe = tid % TILE;
    const int pq = tid / TILE;    // 0..3 role
    const int stride = gridDim.x;

    // ---- initial prefetch for first tile ----
    int   pfi = 0, pfi2 = 0;
    float pf0 = 1.0f, pf1 = 0, pf2 = 0, pf3 = 0, pf4 = 0, pf5 = 0;
    {
        const int t0 = blockIdx.x;
        const int gn = t0 * TILE + pe;
        const bool vn = (t0 < tiles) && (gn < E);
        if (pq == 0)      { if (vn) pfi = src[gn]; }
        else if (pq == 1) { if (vn) { pfi = dst[gn]; pfi2 = equiv[gn]; } }
        else if (pq == 2) {
            if (vn) {
                const float* rp = rbf + (size_t)gn * NR;
                float2 a = *(const float2*)(rp);
                float2 b = *(const float2*)(rp + 2);
                float2 c = *(const float2*)(rp + 4);
                pf0 = a.x; pf1 = a.y; pf2 = b.x; pf3 = b.y; pf4 = c.x; pf5 = c.y;
            }
        } else            { if (vn) pf0 = dvec[gn]; }
    }

    // ---- one-time: W2^T -> fp16 smem; W_rbf/bias -> fp16 smem [16][272B] ----
    for (int idx = tid; idx < EMB * EMB; idx += THREADS) {
        int k = idx >> 7, n = idx & 127;
        *(__half*)(Bsm + k * SA + n * 2) = __float2half(W2[idx]);
    }
    for (int i = tid; i < 16 * EMB; i += THREADS) {
        int k = i >> 7, n = i & 127;
        float v = (k < 6) ? W_rbf[k * EMB + n] : (k == 6 ? b_rbf[n] : 0.0f);
        *(__half*)(WRh + k * 272 + n * 2) = __float2half(v);
    }
    __syncthreads();

    const int wm = wid >> 2;      // 0..2  (m-group of 32 edges)  [main GEMM]
    const int wn = wid & 3;       // 0..3  (n-group of 32 cols)
    const int m0 = wm * 32;
    const uint32_t lmoff = (uint32_t)((lane & 15) * SA + (lane >> 4) * 16);
    const uint32_t A_u  = smem_u32(Asm);
    const uint32_t B_u  = smem_u32(Bsm);
    const uint32_t RH_u = smem_u32(RBFh);
    const uint32_t WR_u = smem_u32(WRh);
    // A swizzled read addressing (main GEMM): row = m0 + (lane&15)
    const uint32_t r3   = (uint32_t)(lane & 7);
    const uint32_t hxa  = (uint32_t)(((lane >> 4) ^ (lane & 1)) * 16);
    const uint32_t r6x  = (r3 & 6) * 16;
    const uint32_t AuBase = A_u + (uint32_t)(m0 + (lane & 15)) * 256 + hxa;
    // A-production GEMM: warp covers rows m0a..m0a+15, cols wn2*64..+63
    const int m0a = (wid >> 1) * 16;
    const int wn2 = wid & 1;
    const uint32_t RHfrag = RH_u + (uint32_t)((m0a + (lane & 15)) * 48 + (lane >> 4) * 16);
    const uint32_t WRfrag = WR_u + (uint32_t)((lane & 15) * 272 + (lane >> 4) * 16 + wn2 * 128);
    const int rowA = m0a + (lane >> 2);
    const int cbA  = wn2 * 128 + (lane & 3) * 4;   // byte col base in A row
    // preload Teq rows (fp16)
    const uint2 te0u = g_Th[212 * 32 + lane];
    const uint2 te1u = g_Th[213 * 32 + lane];
    float* const envo = out + (size_t)E * EMB;

    int prev_ebase = -1;

    for (int t = blockIdx.x; t < tiles; t += stride) {
        const int ebase = t * TILE;
        const int ge1 = ebase + pe;
        const bool v1 = (ge1 < E);

        // ---- P0/P1: copy-out(t-1) + stage(t) + prefetch(t+stride) ----
        if (prev_ebase >= 0) {
            #pragma unroll
            for (int i = 0; i < 8; i++) {
                const int r = wid * 8 + i;
                const int ge = prev_ebase + r;
                if (ge < E) {
                    uint2 u = *(uint2*)&Sumh[r * SH + lane * 4];
                    float2 a = __half22float2(*(__half2*)&u.x);
                    float2 b = __half22float2(*(__half2*)&u.y);
                    *(float4*)&out[(size_t)ge * EMB + lane * 4] = make_float4(a.x, a.y, b.x, b.y);
                }
            }
        }
        if (pq == 0) {
            int pk = 0;
            if (v1) { int s = pfi; pk = Z[s] | (stepA[s] << 7); }
            sidxA[pe] = pk;
        } else if (pq == 1) {
            int pk = 0;
            if (v1) { int dd = pfi; pk = Z[dd] | (pfi2 << 7); }
            sidxB[pe] = pk;
        } else if (pq == 2) {
            // stage rbf row as fp16 k0..5, k6=1.0 (bias slot), k7..15=0
            uint32_t p01, p23, p45;
            asm("cvt.rn.f16x2.f32 %0, %1, %2;" : "=r"(p01) : "f"(pf1), "f"(pf0));
            asm("cvt.rn.f16x2.f32 %0, %1, %2;" : "=r"(p23) : "f"(pf3), "f"(pf2));
            asm("cvt.rn.f16x2.f32 %0, %1, %2;" : "=r"(p45) : "f"(pf5), "f"(pf4));
            *(uint4*)(RBFh + pe * 48)      = make_uint4(p01, p23, p45, 0x00003C00u);
            *(uint4*)(RBFh + pe * 48 + 16) = make_uint4(0, 0, 0, 0);
        } else {
            if (v1) {
                float x = pf0 * 0.2f;
                float inv = 1.0f / x;
                float x2 = x * x;
                float x5 = x2 * x2 * x;
                float env = inv + x5 * (-28.0f + x * (48.0f + x * (-21.0f)));
                float coef = env * inv;
                const float PI = 3.14159265358979323846f;
                float th = PI * x;
                float s1 = __sinf(th), c1 = __cosf(th);
                float twoc = 2.0f * c1;
                float sp = 0.0f, s = s1;
                float o[NR];
                #pragma unroll
                for (int j = 0; j < NR; j++) {
                    o[j] = coef * s;
                    float sn = twoc * s - sp;
                    sp = s; s = sn;
                }
                float* op = envo + (size_t)ge1 * NR;
                *(float2*)(op + 0) = make_float2(o[0], o[1]);
                *(float2*)(op + 2) = make_float2(o[2], o[3]);
                *(float2*)(op + 4) = make_float2(o[4], o[5]);
            }
        }
        // prefetch tile t+stride
        {
            const int tn = t + stride;
            const int gn = tn * TILE + pe;
            const bool vn = (tn < tiles) && (gn < E);
            if (pq == 0)      { pfi = vn ? src[gn] : 0; }
            else if (pq == 1) { pfi = vn ? dst[gn] : 0; pfi2 = vn ? equiv[gn] : 0; }
            else if (pq == 2) {
                if (vn) {
                    const float* rp = rbf + (size_t)gn * NR;
                    float2 a = *(const float2*)(rp);
                    float2 b = *(const float2*)(rp + 2);
                    float2 c = *(const float2*)(rp + 4);
                    pf0 = a.x; pf1 = a.y; pf2 = b.x; pf3 = b.y; pf4 = c.x; pf5 = c.y;
                } else { pf0 = pf1 = pf2 = pf3 = pf4 = pf5 = 0.0f; }
            } else            { pf0 = vn ? dvec[gn] : 1.0f; }
        }
        __syncthreads();

        // ---- P2a: A = silu(rbf16 @ Wrbf16) via tensor core, store swizzled ----
        {
            uint32_t a[4];
            ldsm4(a, RHfrag);
            uint32_t b[16];
            ldsm4t(b + 0,  WRfrag);
            ldsm4t(b + 4,  WRfrag + 32);
            ldsm4t(b + 8,  WRfrag + 64);
            ldsm4t(b + 12, WRfrag + 96);
            float z[8][4];
            #pragma unroll
            for (int j = 0; j < 8; j++)
                z[j][0] = z[j][1] = z[j][2] = z[j][3] = 0.0f;
            #pragma unroll
            for (int j = 0; j < 8; j++)
                mma_f16(z[j], a, b + 2 * j);
            char* const ar1 = Asm + rowA * 256;
            char* const ar2 = ar1 + 8 * 256;
            const uint32_t x1 = (uint32_t)(rowA & 7) << 4;
            const uint32_t x2 = (uint32_t)((rowA + 8) & 7) << 4;
            #pragma unroll
            for (int j = 0; j < 8; j++) {
                const uint32_t byte = (uint32_t)(cbA + j * 16);
                const uint32_t ch = byte & 0xFFFFFFF0u, wi = byte & 15u;
                uint32_t u0, u1;
                float s0 = silu_f(z[j][0]), s1v = silu_f(z[j][1]);
                float s2 = silu_f(z[j][2]), s3 = silu_f(z[j][3]);
                asm("cvt.rn.f16x2.f32 %0, %1, %2;" : "=r"(u0) : "f"(s1v), "f"(s0));
                asm("cvt.rn.f16x2.f32 %0, %1, %2;" : "=r"(u1) : "f"(s3), "f"(s2));
                *(uint32_t*)(ar1 + ((ch ^ x1) | wi)) = u0;
                *(uint32_t*)(ar2 + ((ch ^ x2) | wi)) = u1;
            }
        }
        __syncthreads();

        // ---- P2b: fp16 table gathers -> fp16 Sum via add.f16x2 (8 rows/warp) ----
        #pragma unroll
        for (int i = 0; i < 8; i++) {
            const int r = wid * 8 + i;
            const uint32_t pkA = (uint32_t)sidxA[r];
            const uint32_t pkB = (uint32_t)sidxB[r];
            const int zs = pkA & 127, st = pkA >> 7;
            const int zd = pkB & 127, eq = pkB >> 7;
            uint2 u0 = g_Th[zs * 32 + lane];
            uint2 u1 = g_Th[(96 + zd) * 32 + lane];
            uint2 u2 = g_Th[(192 + st) * 32 + lane];
            uint2 u3 = eq ? te1u : te0u;
            uint2 o;
            o.x = hadd2(hadd2(u0.x, u1.x), hadd2(u2.x, u3.x));
            o.y = hadd2(hadd2(u0.y, u1.y), hadd2(u2.y, u3.y));
            *(uint2*)&Sumh[r * SH + lane * 4] = o;
        }

        // ---- P3: main GEMM 32x32 per warp, single-pass fp16, swizzled A ----
        float d[2][4][4];
        #pragma unroll
        for (int mt = 0; mt < 2; mt++)
            #pragma unroll
            for (int jj = 0; jj < 4; jj++)
                d[mt][jj][0] = d[mt][jj][1] = d[mt][jj][2] = d[mt][jj][3] = 0.0f;

        {
            const uint32_t Bu = B_u + wn * 64 + lmoff;
            #pragma unroll
            for (int ks = 0; ks < 8; ks++) {
                const uint32_t aoff = ((uint32_t)(ks * 32)) ^ r6x;
                uint32_t a[8];
                ldsm4(a + 0, AuBase + aoff);
                ldsm4(a + 4, AuBase + 4096 + aoff);
                uint32_t b[8];
                ldsm4t(b + 0, Bu + ks * 16 * SA);
                ldsm4t(b + 4, Bu + ks * 16 * SA + 32);
                #pragma unroll
                for (int mt = 0; mt < 2; mt++)
                    #pragma unroll
                    for (int jj = 0; jj < 4; jj++)
                        mma_f16(d[mt][jj], a + mt * 4, b + 2 * jj);
            }
        }
        __syncthreads();

        // ---- P4: epilogue in fp16x2 ----
        #pragma unroll
        for (int mt = 0; mt < 2; mt++) {
            const int r1 = m0 + mt * 16 + (lane >> 2);
            __half* S1 = Sumh + r1 * SH;
            __half* S2 = Sumh + (r1 + 8) * SH;
            #pragma unroll
            for (int jj = 0; jj < 4; jj++) {
                const int c = wn * 32 + jj * 8 + (lane & 3) * 2;
                const float* dd = d[mt][jj];
                uint32_t dh0, dh1;
                asm("cvt.rn.f16x2.f32 %0, %1, %2;" : "=r"(dh0) : "f"(dd[1]), "f"(dd[0]));
                asm("cvt.rn.f16x2.f32 %0, %1, %2;" : "=r"(dh1) : "f"(dd[3]), "f"(dd[2]));
                uint32_t* p1 = (uint32_t*)&S1[c];
                uint32_t* p2 = (uint32_t*)&S2[c];
                *p1 = silu_h2(hadd2(*p1, dh0));
                *p2 = silu_h2(hadd2(*p2, dh1));
            }
        }
        __syncthreads();

        prev_ebase = ebase;
    }

    // ---- final copy-out ----
    if (prev_ebase >= 0) {
        #pragma unroll
        for (int i = 0; i < 8; i++) {
            const int r = wid * 8 + i;
            const int ge = prev_ebase + r;
            if (ge < E) {
                uint2 u = *(uint2*)&Sumh[r * SH + lane * 4];
                float2 a = __half22float2(*(__half2*)&u.x);
                float2 b = __half22float2(*(__half2*)&u.y);
                *(float4*)&out[(size_t)ge * EMB + lane * 4] = make_float4(a.x, a.y, b.x, b.y);
            }
        }
    }
}

// ---------------------------------------------------------------------------
extern "C" void kernel_launch(void* const* d_in, const int* in_sizes, int n_in,
                              void* d_out, int out_size)
{
    const int*   Z          = (const int*)d_in[0];
    const int*   stepA      = (const int*)d_in[1];
    const int*   src        = (const int*)d_in[2];
    const int*   dst        = (const int*)d_in[3];
    const int*   equiv      = (const int*)d_in[4];
    const float* rbf        = (const float*)d_in[5];
    const float* dvec       = (const float*)d_in[6];
    const float* emb_table  = (const float*)d_in[7];
    const float* step_table = (const float*)d_in[8];
    const float* equiv_tab  = (const float*)d_in[9];
    const float* W_rbf      = (const float*)d_in[10];
    const float* b_rbf      = (const float*)d_in[11];
    const float* W          = (const float*)d_in[12];
    const float* b          = (const float*)d_in[13];
    float* out = (float*)d_out;

    const int E = in_sizes[2];
    const int tiles = (E + TILE - 1) / TILE;

    static int sms = 0;
    if (sms == 0) {
        if (cudaDeviceGetAttribute(&sms, cudaDevAttrMultiProcessorCount, 0) != cudaSuccess || sms <= 0)
            sms = 148;
    }
    int grid = 2 * sms;
    if (grid > tiles) grid = tiles;

    cudaFuncSetAttribute(edge_kernel, cudaFuncAttributeMaxDynamicSharedMemorySize, SMEM_TOT);

    precompute_kernel<<<107, 256>>>(emb_table, step_table, equiv_tab, W, b);
    edge_kernel<<<grid, THREADS, SMEM_TOT>>>(Z, stepA, src, dst, equiv,
                                             rbf, dvec, W_rbf, b_rbf,
                                             W + 2 * EMB * EMB, out, E, tiles);
}